// round 8
// baseline (speedup 1.0000x reference)
#include <cuda_runtime.h>
#include <math.h>

// Problem constants
#define B_  32
#define T_  32
#define I_  256
#define H_  512
#define NH_ 4
#define HS_ 64
#define MS_ 2048
#define O_  256
// derived
#define KG_ 1024        // ctrl_in (512) + H (512)
#define NG_ 2048        // 4*H, gate col index n = g*512 + j
#define NHP_ 516        // 4 heads * 129 used head outputs
#define HPROW_ 2115     // HS + MS + 3
#define NBLK 128
#define NTHR 512
#define NBAR (4*T_)

typedef unsigned long long u64;

__device__ __forceinline__ u64 ffma2(u64 a, u64 b, u64 c) {
    u64 d; asm("fma.rn.f32x2 %0, %1, %2, %3;" : "=l"(d) : "l"(a), "l"(b), "l"(c)); return d;
}
__device__ __forceinline__ u64 fadd2(u64 a, u64 b) {
    u64 d; asm("add.rn.f32x2 %0, %1, %2;" : "=l"(d) : "l"(a), "l"(b)); return d;
}
__device__ __forceinline__ u64 pack2(float lo, float hi) {
    u64 d; asm("mov.b64 %0, {%1, %2};" : "=l"(d) : "f"(lo), "f"(hi)); return d;
}
__device__ __forceinline__ float2 unpack2(u64 v) {
    float2 r; asm("mov.b64 {%0, %1}, %2;" : "=f"(r.x), "=f"(r.y) : "l"(v)); return r;
}

// ---------------- scratch (device globals; no allocation allowed) ----------------
__device__ float g_WgT[KG_*NG_];              // [k][n]  8MB   (n = g*512+j)
__device__ float g_WhT[H_*NHP_];              // [k][n*129+p]  1MB
__device__ float g_WoT[(H_+NH_*HS_)*O_];      // [k][o]
__device__ float g_h[B_*H_];
__device__ float g_c[B_*H_];
__device__ float g_gates_part[8][B_][NG_];    // k-split (8) partial gates
__device__ float g_hp_part[16][B_][NHP_];     // k-split (16) partial head outputs
__device__ float2 g_stats[B_][8][4];          // [b][key][mq] = {chunk max, chunk sumexp}
__device__ float g_read_part[T_][4][B_][NH_*HS_]; // per-mq read partials
__device__ float g_hist_h[T_][B_][H_];
__device__ float g_mem[B_][MS_][HS_];         // 16.7MB
__device__ int   g_bar[NBAR];

__device__ __forceinline__ float sigm_acc(float v) { return 1.f / (1.f + expf(-v)); }

// ---------------- grid barrier: release-add + acquire-poll, no L1 flush ----------------
__device__ __forceinline__ void gridbar(int idx) {
    __syncthreads();
    if (threadIdx.x == 0) {
        int* p = &g_bar[idx];
        asm volatile("red.release.gpu.global.add.s32 [%0], 1;" :: "l"(p) : "memory");
        int v;
        do {
            asm volatile("ld.acquire.gpu.global.s32 %0, [%1];" : "=r"(v) : "l"(p) : "memory");
        } while (v < NBLK);
    }
    __syncthreads();
}

// ---------------- fused prep: transposes + zeroing in ONE launch ----------------
__global__ void k_prep(const float* __restrict__ W_ih, const float* __restrict__ W_hh,
                       const float* __restrict__ W_head, const float* __restrict__ W_out) {
    const int b = blockIdx.x;
    const int tid = threadIdx.x;                // 256
    const int tx = tid & 31, ty = tid >> 5;     // (32, 8)
    __shared__ float tile[32][33];
    if (b < 2048) {                             // WgT[k][n] = [W_ih|W_hh][n][k]
        int bx = (b & 31) * 32, by = (b >> 5) * 32;
        #pragma unroll
        for (int i = 0; i < 32; i += 8) {
            int row = by + ty + i, k = bx + tx;
            tile[ty + i][tx] = (k < 512) ? W_ih[row*512 + k] : W_hh[row*512 + (k - 512)];
        }
        __syncthreads();
        #pragma unroll
        for (int i = 0; i < 32; i += 8) {
            int k = bx + ty + i, row = by + tx;
            g_WgT[(size_t)k * NG_ + row] = tile[tx][ty + i];
        }
    } else if (b < 2048 + 272) {                // WhT[k][r], r = n*129+p
        int bb = b - 2048;
        int bx = (bb & 15) * 32, by = (bb >> 4) * 32;
        #pragma unroll
        for (int i = 0; i < 32; i += 8) {
            int r = by + ty + i, k = bx + tx;
            float v = 0.f;
            if (r < NHP_) {
                int n = r / 129, p = r % 129;
                v = W_head[(size_t)(n * HPROW_ + p) * 512 + k];
            }
            tile[ty + i][tx] = v;
        }
        __syncthreads();
        #pragma unroll
        for (int i = 0; i < 32; i += 8) {
            int k = bx + ty + i, r = by + tx;
            if (r < NHP_) g_WhT[(size_t)k * NHP_ + r] = tile[tx][ty + i];
        }
    } else if (b < 2048 + 272 + 192) {          // WoT[k][o] = W_out[o][k]
        int bb = b - 2320;
        int bx = (bb % 24) * 32, by = (bb / 24) * 32;
        #pragma unroll
        for (int i = 0; i < 32; i += 8) {
            int o = by + ty + i, k = bx + tx;
            tile[ty + i][tx] = W_out[o * (H_ + NH_*HS_) + k];
        }
        __syncthreads();
        #pragma unroll
        for (int i = 0; i < 32; i += 8) {
            int k = bx + ty + i, o = by + tx;
            g_WoT[(size_t)k * O_ + o] = tile[tx][ty + i];
        }
    } else {                                    // zero mem, h, c, barriers
        int bb = b - 2512;                      // 0..511
        int gtid = bb * 256 + tid;              // 0..131071
        float4 z4 = make_float4(0.f, 0.f, 0.f, 0.f);
        #pragma unroll
        for (int i = 0; i < 8; ++i)
            ((float4*)g_mem)[gtid + i * 131072] = z4;
        if (gtid < 4096)            ((float4*)g_h)[gtid] = z4;
        else if (gtid < 8192)       ((float4*)g_c)[gtid - 4096] = z4;
        else if (gtid < 8192+NBAR)  g_bar[gtid - 8192] = 0;
    }
}

__global__ void k_nop() {}

// ---------------- the persistent recurrence kernel (512 threads) ----------------
struct SmGates {
    u64   vdup[128][32];      // {v,v} per [k][b]  32KB
    float w[2][32][128];      // double-buffered weight tile 32KB
};
struct SmP2    { float h[4][32]; };
struct SmAttn  {
    float key[8][64];
    float stat[8][512];
    float gm[8], inv[8], ws[4];
    float sk[4][64];
    u64   wsm[8][512];        // softmax weights pre-duplicated {w,w}
    float racc[16][4][64];
};
union __align__(16) SmU { SmGates g; SmP2 p2; SmAttn a; };

extern __shared__ unsigned char sm_raw[];

__global__ __launch_bounds__(NTHR, 1)
void k_steps(const float* __restrict__ x, const float* __restrict__ b_ih,
             const float* __restrict__ b_hh, const float* __restrict__ b_head) {
    SmU& sm = *reinterpret_cast<SmU*>(sm_raw);
    const int bid = blockIdx.x, tid = threadIdx.x;

    // P1 partition: (16 n-chunks of 128) x (8 k-slices of 128)
    const int nc = bid >> 3, ksg = bid & 7;
    const int n0 = nc * 128, k0g = ksg * 128;
    const int n4 = tid & 31;          // 4 n-cols: col0 = n0 + n4*4
    const int bq = tid >> 5;          // 0..15 -> 2 batches each
    const int b0v = bq * 2;
    // P2 partition
    const int bq2 = bid >> 4, ks2 = bid & 15;
    const int b02 = bq2 * 4, j0 = ks2 * 32;
    // P3/P4 partition
    const int ab = bid >> 2, mq = bid & 3;
    const int m0 = mq * 512;

    for (int t = 0; t < T_; ++t) {
        // ================= P1: gates GEMM (k-split partials) =================
        {
            // v tile [128k][32b], stored duplicated {v,v}
            #pragma unroll
            for (int e = 0; e < 8; ++e) {
                int idx = e * 512 + tid;
                int kk = idx >> 5, bb = idx & 31;
                int gk = k0g + kk;
                float vv;
                if (gk < 256) {
                    vv = __ldg(&x[(bb * T_ + t) * I_ + gk]);
                } else if (gk < 512) {
                    if (t == 0) vv = 0.f;
                    else {
                        int r = gk - 256;
                        vv = __ldcg(&g_read_part[t-1][0][bb][r]) + __ldcg(&g_read_part[t-1][1][bb][r])
                           + __ldcg(&g_read_part[t-1][2][bb][r]) + __ldcg(&g_read_part[t-1][3][bb][r]);
                    }
                } else {
                    vv = __ldcg(&g_h[bb * H_ + (gk - 512)]);
                }
                sm.g.vdup[kk][bb] = pack2(vv, vv);
            }
            // preload w tile 0 (32k x 128n)
            {
                #pragma unroll
                for (int e = 0; e < 2; ++e) {
                    int lin = e * 2048 + tid * 4;
                    int row = lin >> 7, col = lin & 127;
                    *(float4*)&sm.g.w[0][row][col] =
                        __ldcg((const float4*)&g_WgT[(size_t)(k0g + row) * NG_ + n0 + col]);
                }
            }
            u64 acc2[2][2] = {{0ull,0ull},{0ull,0ull}};
            int buf = 0;
            for (int c = 0; c < 4; ++c) {
                __syncthreads();
                float4 nxt[2];
                if (c < 3) {
                    #pragma unroll
                    for (int e = 0; e < 2; ++e) {
                        int lin = e * 2048 + tid * 4;
                        int row = lin >> 7, col = lin & 127;
                        nxt[e] = __ldcg((const float4*)&g_WgT[(size_t)(k0g + (c+1)*32 + row) * NG_ + n0 + col]);
                    }
                }
                #pragma unroll
                for (int kk = 0; kk < 32; ++kk) {
                    ulonglong2 w2 = *(const ulonglong2*)&sm.g.w[buf][kk][n4 * 4];
                    u64 v0 = sm.g.vdup[c*32 + kk][b0v];
                    u64 v1 = sm.g.vdup[c*32 + kk][b0v + 1];
                    acc2[0][0] = ffma2(v0, w2.x, acc2[0][0]);
                    acc2[0][1] = ffma2(v0, w2.y, acc2[0][1]);
                    acc2[1][0] = ffma2(v1, w2.x, acc2[1][0]);
                    acc2[1][1] = ffma2(v1, w2.y, acc2[1][1]);
                }
                if (c < 3) {
                    #pragma unroll
                    for (int e = 0; e < 2; ++e) {
                        int lin = e * 2048 + tid * 4;
                        int row = lin >> 7, col = lin & 127;
                        *(float4*)&sm.g.w[buf ^ 1][row][col] = nxt[e];
                    }
                    buf ^= 1;
                }
            }
            const int col0 = n0 + n4 * 4;
            float4 bi4 = make_float4(0.f,0.f,0.f,0.f);
            if (ksg == 0) {
                bi4 = make_float4(b_ih[col0] + b_hh[col0],
                                  b_ih[col0+1] + b_hh[col0+1],
                                  b_ih[col0+2] + b_hh[col0+2],
                                  b_ih[col0+3] + b_hh[col0+3]);
            }
            #pragma unroll
            for (int bi = 0; bi < 2; ++bi) {
                float2 p0 = unpack2(acc2[bi][0]);
                float2 p1 = unpack2(acc2[bi][1]);
                float4 o4 = make_float4(p0.x + bi4.x, p0.y + bi4.y, p1.x + bi4.z, p1.y + bi4.w);
                *(float4*)&g_gates_part[ksg][b0v + bi][col0] = o4;
            }
        }
        gridbar(4*t + 0);

        // ================= P2: LSTM elementwise + partial head GEMM =================
        {
            if (tid < 128) {
                int bi = tid >> 5, jj = tid & 31;
                int b = b02 + bi, j = j0 + jj;
                float gi = 0.f, gf = 0.f, gg = 0.f, go = 0.f;
                #pragma unroll
                for (int p = 0; p < 8; ++p) {
                    gi += __ldcg(&g_gates_part[p][b][j]);
                    gf += __ldcg(&g_gates_part[p][b][512 + j]);
                    gg += __ldcg(&g_gates_part[p][b][1024 + j]);
                    go += __ldcg(&g_gates_part[p][b][1536 + j]);
                }
                float cold = g_c[b * H_ + j];
                float iv = sigm_acc(gi), fv = sigm_acc(gf);
                float gv = tanhf(gg),   ov = sigm_acc(go);
                float cn = fv * cold + iv * gv;
                float hn = ov * tanhf(cn);
                g_c[b * H_ + j] = cn;
                g_h[b * H_ + j] = hn;
                g_hist_h[t][b][j] = hn;
                sm.p2.h[bi][jj] = hn;
            }
            __syncthreads();
            #pragma unroll
            for (int e = 0; e < 2; ++e) {
                int nn = tid + e * 512;
                if (nn < NHP_) {
                    float a0 = 0.f, a1 = 0.f, a2 = 0.f, a3 = 0.f;
                    #pragma unroll
                    for (int k = 0; k < 32; ++k) {
                        float w = __ldcg(&g_WhT[(size_t)(j0 + k) * NHP_ + nn]);
                        a0 += sm.p2.h[0][k] * w;
                        a1 += sm.p2.h[1][k] * w;
                        a2 += sm.p2.h[2][k] * w;
                        a3 += sm.p2.h[3][k] * w;
                    }
                    g_hp_part[ks2][b02 + 0][nn] = a0;
                    g_hp_part[ks2][b02 + 1][nn] = a1;
                    g_hp_part[ks2][b02 + 2][nn] = a2;
                    g_hp_part[ks2][b02 + 3][nn] = a3;
                }
            }
        }
        // hoist the block-private mem-row load ABOVE the barrier (overlaps barrier wait)
        ulonglong2 r[16];
        {
            const ulonglong2* mp = (const ulonglong2*)&g_mem[ab][m0 + tid][0];
            #pragma unroll
            for (int i = 0; i < 16; ++i) r[i] = mp[i];
        }
        gridbar(4*t + 1);

        // ================= P3: keys + scores (1 row/thread) + chunk stats =================
        float s[8];
        {
            {   // key build: 512 entries, 1 per thread
                int key = tid >> 6, h = tid & 63;
                int n = key & 3;
                int p = (key < 4) ? h : 64 + h;
                float v = __ldg(&b_head[n * HPROW_ + p]);
                #pragma unroll
                for (int ps = 0; ps < 16; ++ps) v += __ldcg(&g_hp_part[ps][ab][n * 129 + p]);
                sm.a.key[key][h] = v * 0.125f;   // fold 1/sqrt(HS)
            }
            __syncthreads();
            u64 s2[8];
            #pragma unroll
            for (int key = 0; key < 8; ++key) s2[key] = 0ull;
            #pragma unroll
            for (int hc = 0; hc < 16; ++hc) {
                u64 m01 = r[hc].x, m23 = r[hc].y;
                #pragma unroll
                for (int key = 0; key < 8; ++key) {
                    ulonglong2 k2 = *(const ulonglong2*)&sm.a.key[key][hc * 4];
                    s2[key] = ffma2(k2.x, m01, s2[key]);
                    s2[key] = ffma2(k2.y, m23, s2[key]);
                }
            }
            #pragma unroll
            for (int key = 0; key < 8; ++key) {
                float2 p = unpack2(s2[key]);
                s[key] = p.x + p.y;
                sm.a.stat[key][tid] = s[key];
            }
            __syncthreads();
            const int w = tid >> 5, l = tid & 31;
            if (w < 8) {
                float mx = -1e30f;
                for (int i = l; i < 512; i += 32) mx = fmaxf(mx, sm.a.stat[w][i]);
                #pragma unroll
                for (int sh = 16; sh; sh >>= 1) mx = fmaxf(mx, __shfl_xor_sync(0xffffffffu, mx, sh));
                if (l == 0) sm.a.gm[w] = mx;
            }
            __syncthreads();
            #pragma unroll
            for (int key = 0; key < 8; ++key)
                sm.a.stat[key][tid] = __expf(s[key] - sm.a.gm[key]);
            __syncthreads();
            if (w < 8) {
                float se = 0.f;
                for (int i = l; i < 512; i += 32) se += sm.a.stat[w][i];
                #pragma unroll
                for (int sh = 16; sh; sh >>= 1) se += __shfl_xor_sync(0xffffffffu, se, sh);
                if (l == 0) g_stats[ab][w][mq] = make_float2(sm.a.gm[w], se);
            }
        }
        gridbar(4*t + 2);

        // ================= P4: softmax apply, read accumulate, memory update =================
        {
            if (tid < 8) {
                float2 st0 = __ldcg(&g_stats[ab][tid][0]);
                float2 st1 = __ldcg(&g_stats[ab][tid][1]);
                float2 st2 = __ldcg(&g_stats[ab][tid][2]);
                float2 st3 = __ldcg(&g_stats[ab][tid][3]);
                float gm = fmaxf(fmaxf(st0.x, st1.x), fmaxf(st2.x, st3.x));
                float ssum = st0.y * __expf(st0.x - gm) + st1.y * __expf(st1.x - gm)
                           + st2.y * __expf(st2.x - gm) + st3.y * __expf(st3.x - gm);
                sm.a.gm[tid] = gm; sm.a.inv[tid] = 1.f / ssum;
            } else if (tid < 12) {
                int n = tid - 8;
                float v = __ldg(&b_head[n * HPROW_ + 128]);
                #pragma unroll
                for (int ps = 0; ps < 16; ++ps) v += __ldcg(&g_hp_part[ps][ab][n * 129 + 128]);
                sm.a.ws[n] = sigm_acc(v);
            }
            __syncthreads();
            if (tid < 256) {
                int n = tid >> 6, h = tid & 63;
                float v = __ldg(&b_head[n * HPROW_ + 64 + h]);
                #pragma unroll
                for (int ps = 0; ps < 16; ++ps) v += __ldcg(&g_hp_part[ps][ab][n * 129 + 64 + h]);
                sm.a.sk[n][h] = v * sm.a.ws[n];
            }
            #pragma unroll
            for (int key = 0; key < 8; ++key) {
                float wv = __expf(s[key] - sm.a.gm[key]) * sm.a.inv[key];
                sm.a.wsm[key][tid] = pack2(wv, wv);
            }
            __syncthreads();

            const int w = tid >> 5, l = tid & 31;
            const int msub = l >> 3, hb = (l & 7) * 8;
            u64 skreg2[4][4];
            #pragma unroll
            for (int n = 0; n < 4; ++n)
                #pragma unroll
                for (int q2 = 0; q2 < 4; ++q2)
                    skreg2[n][q2] = *(const u64*)&sm.a.sk[n][hb + q2 * 2];
            u64 racc2[4][4];
            #pragma unroll
            for (int n = 0; n < 4; ++n)
                #pragma unroll
                for (int q2 = 0; q2 < 4; ++q2) racc2[n][q2] = 0ull;
            #pragma unroll
            for (int it = 0; it < 8; ++it) {
                int ml = it * 64 + w * 4 + msub;
                ulonglong2* mp2 = (ulonglong2*)&g_mem[ab][m0 + ml][hb];
                ulonglong2 a2 = mp2[0], c2 = mp2[1];
                u64 rw2[4], ww2[4];
                #pragma unroll
                for (int n = 0; n < 4; ++n) { rw2[n] = sm.a.wsm[n][ml]; ww2[n] = sm.a.wsm[4 + n][ml]; }
                #pragma unroll
                for (int n = 0; n < 4; ++n) {
                    racc2[n][0] = ffma2(rw2[n], a2.x, racc2[n][0]);
                    racc2[n][1] = ffma2(rw2[n], a2.y, racc2[n][1]);
                    racc2[n][2] = ffma2(rw2[n], c2.x, racc2[n][2]);
                    racc2[n][3] = ffma2(rw2[n], c2.y, racc2[n][3]);
                }
                #pragma unroll
                for (int n = 0; n < 4; ++n) {
                    a2.x = ffma2(ww2[n], skreg2[n][0], a2.x);
                    a2.y = ffma2(ww2[n], skreg2[n][1], a2.y);
                    c2.x = ffma2(ww2[n], skreg2[n][2], c2.x);
                    c2.y = ffma2(ww2[n], skreg2[n][3], c2.y);
                }
                mp2[0] = a2; mp2[1] = c2;
            }
            #pragma unroll
            for (int n = 0; n < 4; ++n)
                #pragma unroll
                for (int q2 = 0; q2 < 4; ++q2) {
                    racc2[n][q2] = fadd2(racc2[n][q2], __shfl_xor_sync(0xffffffffu, racc2[n][q2], 8));
                    racc2[n][q2] = fadd2(racc2[n][q2], __shfl_xor_sync(0xffffffffu, racc2[n][q2], 16));
                }
            if (l < 8) {
                #pragma unroll
                for (int n = 0; n < 4; ++n)
                    #pragma unroll
                    for (int q2 = 0; q2 < 4; ++q2) {
                        float2 p = unpack2(racc2[n][q2]);
                        sm.a.racc[w][n][hb + q2*2]     = p.x;
                        sm.a.racc[w][n][hb + q2*2 + 1] = p.y;
                    }
            }
            __syncthreads();
            if (tid < 256) {
                int n = tid >> 6, h = tid & 63;
                float ssum = 0.f;
                #pragma unroll
                for (int wr = 0; wr < 16; ++wr) ssum += sm.a.racc[wr][n][h];
                g_read_part[t][mq][ab][n * 64 + h] = ssum;
            }
        }
        gridbar(4*t + 3);
    }
}

// ---------------- final output GEMM: outputs[b][t][o] (512 threads) ----------------
__global__ __launch_bounds__(512)
void k_out(const float* __restrict__ b_out, float* __restrict__ out) {
    const int m0 = blockIdx.x * 32, ncb = blockIdx.y;
    const int tid = threadIdx.x;
    __shared__ float a_sh[32][64];
    const int n_l = tid & 63, mg = tid >> 6;     // mg 0..7, 4 rows each
    const int n = ncb * 64 + n_l;
    float acc[4];
    #pragma unroll
    for (int rr = 0; rr < 4; ++rr) acc[rr] = 0.f;
    for (int kt = 0; kt < 12; ++kt) {
        __syncthreads();
        #pragma unroll
        for (int e = 0; e < 4; ++e) {
            int lidx = e * 512 + tid;
            int mrow = lidx >> 6, kk = lidx & 63;
            int m = m0 + mrow;
            int ts = m >> 5, bb = m & 31;
            int gk = kt * 64 + kk;
            float v;
            if (gk < 512) v = g_hist_h[ts][bb][gk];
            else {
                int rp = gk - 512;
                v = g_read_part[ts][0][bb][rp] + g_read_part[ts][1][bb][rp]
                  + g_read_part[ts][2][bb][rp] + g_read_part[ts][3][bb][rp];
            }
            a_sh[mrow][kk] = v;
        }
        __syncthreads();
        #pragma unroll 4
        for (int kk = 0; kk < 64; ++kk) {
            float wv = g_WoT[(kt * 64 + kk) * O_ + n];
            #pragma unroll
            for (int rr = 0; rr < 4; ++rr) acc[rr] += a_sh[mg * 4 + rr][kk] * wv;
        }
    }
    float bo = b_out[n];
    #pragma unroll
    for (int rr = 0; rr < 4; ++rr) {
        int m = m0 + mg * 4 + rr;
        int ts = m >> 5, bb = m & 31;
        out[(bb * T_ + ts) * O_ + n] = acc[rr] + bo;
    }
}

// ---------------- final state copy: mem, h, c into d_out ----------------
__global__ void k_final(float* __restrict__ out) {
    const int OUT_N = B_ * T_ * O_;            // 262144
    const int NMEM  = B_ * MS_ * HS_;          // 4194304
    const int total = NMEM + 2 * B_ * H_;
    for (int i = blockIdx.x * blockDim.x + threadIdx.x; i < total; i += gridDim.x * blockDim.x) {
        if (i < NMEM)                 out[OUT_N + i] = (&g_mem[0][0][0])[i];
        else if (i < NMEM + B_ * H_)  out[OUT_N + i] = g_h[i - NMEM];
        else                          out[OUT_N + i] = g_c[i - NMEM - B_ * H_];
    }
}

extern "C" void kernel_launch(void* const* d_in, const int* in_sizes, int n_in,
                              void* d_out, int out_size) {
    const float* x      = (const float*)d_in[0];
    const float* W_ih   = (const float*)d_in[1];
    const float* W_hh   = (const float*)d_in[2];
    const float* b_ih   = (const float*)d_in[3];
    const float* b_hh   = (const float*)d_in[4];
    const float* W_head = (const float*)d_in[5];
    const float* b_head = (const float*)d_in[6];
    const float* W_out  = (const float*)d_in[7];
    const float* b_out  = (const float*)d_in[8];
    float* out = (float*)d_out;

    static int smem_set = 0;
    if (!smem_set) {
        cudaFuncSetAttribute(k_steps, cudaFuncAttributeMaxDynamicSharedMemorySize,
                             (int)sizeof(SmU));
        smem_set = 1;
    }

    k_prep<<<3024, 256>>>(W_ih, W_hh, W_head, W_out);
    k_nop<<<1, 32>>>();
    k_nop<<<1, 32>>>();
    k_steps<<<NBLK, NTHR, sizeof(SmU)>>>(x, b_ih, b_hh, b_head);
    k_out<<<dim3(32, 4), 512>>>(b_out, out);
    k_final<<<2048, 256>>>(out);
}

// round 9
// speedup vs baseline: 1.1187x; 1.1187x over previous
#include <cuda_runtime.h>
#include <math.h>

// Problem constants
#define B_  32
#define T_  32
#define I_  256
#define H_  512
#define NH_ 4
#define HS_ 64
#define MS_ 2048
#define O_  256
// derived
#define KG_ 1024        // ctrl_in (512) + H (512)
#define NG_ 2048        // 4*H, gate col index n = g*512 + j
#define NHP_ 516        // 4 heads * 129 used head outputs
#define HPROW_ 2115     // HS + MS + 3
#define NBLK 128
#define NBAR (4*T_)

typedef unsigned long long u64;

__device__ __forceinline__ u64 ffma2(u64 a, u64 b, u64 c) {
    u64 d; asm("fma.rn.f32x2 %0, %1, %2, %3;" : "=l"(d) : "l"(a), "l"(b), "l"(c)); return d;
}
__device__ __forceinline__ u64 pack2(float lo, float hi) {
    u64 d; asm("mov.b64 %0, {%1, %2};" : "=l"(d) : "f"(lo), "f"(hi)); return d;
}
__device__ __forceinline__ float2 unpack2(u64 v) {
    float2 r; asm("mov.b64 {%0, %1}, %2;" : "=f"(r.x), "=f"(r.y) : "l"(v)); return r;
}

// ---------------- scratch (device globals; no allocation allowed) ----------------
__device__ float g_WgT[KG_*NG_];              // [k][n]  8MB   (n = g*512+j)
__device__ float g_WhT[H_*NHP_];              // [k][n*129+p]  1MB
__device__ float g_WoT[(H_+NH_*HS_)*O_];      // [k][o]
__device__ float g_h[B_*H_];
__device__ float g_c[B_*H_];
__device__ float g_gates_part[8][B_][NG_];    // k-split (8) partial gates
__device__ float g_hp_part[16][B_][NHP_];     // k-split (16) partial head outputs
__device__ float2 g_stats[B_][8][4];          // [b][key][mq] = {chunk max, chunk sumexp}
__device__ float g_read_part[T_][4][B_][NH_*HS_]; // per-mq read partials
__device__ float g_hist_h[T_][B_][H_];
__device__ float g_mem[B_][MS_][HS_];         // 16.7MB
__device__ int   g_bar[NBAR];

__device__ __forceinline__ float sigm_acc(float v) { return 1.f / (1.f + expf(-v)); }

// ---------------- grid barrier: release-add + acquire-poll, no L1 flush ----------------
__device__ __forceinline__ void gridbar(int idx) {
    __syncthreads();
    if (threadIdx.x == 0) {
        int* p = &g_bar[idx];
        asm volatile("red.release.gpu.global.add.s32 [%0], 1;" :: "l"(p) : "memory");
        int v;
        do {
            asm volatile("ld.acquire.gpu.global.s32 %0, [%1];" : "=r"(v) : "l"(p) : "memory");
        } while (v < NBLK);
    }
    __syncthreads();
}

// ---------------- fused prep: transposes + zeroing in ONE launch ----------------
__global__ void k_prep(const float* __restrict__ W_ih, const float* __restrict__ W_hh,
                       const float* __restrict__ W_head, const float* __restrict__ W_out) {
    const int b = blockIdx.x;
    const int tid = threadIdx.x;                // 256
    const int tx = tid & 31, ty = tid >> 5;     // (32, 8)
    __shared__ float tile[32][33];
    if (b < 2048) {                             // WgT[k][n] = [W_ih|W_hh][n][k]
        int bx = (b & 31) * 32, by = (b >> 5) * 32;
        #pragma unroll
        for (int i = 0; i < 32; i += 8) {
            int row = by + ty + i, k = bx + tx;
            tile[ty + i][tx] = (k < 512) ? W_ih[row*512 + k] : W_hh[row*512 + (k - 512)];
        }
        __syncthreads();
        #pragma unroll
        for (int i = 0; i < 32; i += 8) {
            int k = bx + ty + i, row = by + tx;
            g_WgT[(size_t)k * NG_ + row] = tile[tx][ty + i];
        }
    } else if (b < 2048 + 272) {                // WhT[k][r], r = n*129+p
        int bb = b - 2048;
        int bx = (bb & 15) * 32, by = (bb >> 4) * 32;
        #pragma unroll
        for (int i = 0; i < 32; i += 8) {
            int r = by + ty + i, k = bx + tx;
            float v = 0.f;
            if (r < NHP_) {
                int n = r / 129, p = r % 129;
                v = W_head[(size_t)(n * HPROW_ + p) * 512 + k];
            }
            tile[ty + i][tx] = v;
        }
        __syncthreads();
        #pragma unroll
        for (int i = 0; i < 32; i += 8) {
            int k = bx + ty + i, r = by + tx;
            if (r < NHP_) g_WhT[(size_t)k * NHP_ + r] = tile[tx][ty + i];
        }
    } else if (b < 2048 + 272 + 192) {          // WoT[k][o] = W_out[o][k]
        int bb = b - 2320;
        int bx = (bb % 24) * 32, by = (bb / 24) * 32;
        #pragma unroll
        for (int i = 0; i < 32; i += 8) {
            int o = by + ty + i, k = bx + tx;
            tile[ty + i][tx] = W_out[o * (H_ + NH_*HS_) + k];
        }
        __syncthreads();
        #pragma unroll
        for (int i = 0; i < 32; i += 8) {
            int k = bx + ty + i, o = by + tx;
            g_WoT[(size_t)k * O_ + o] = tile[tx][ty + i];
        }
    } else {                                    // zero mem, h, c, barriers
        int bb = b - 2512;                      // 0..511
        int gtid = bb * 256 + tid;              // 0..131071
        float4 z4 = make_float4(0.f, 0.f, 0.f, 0.f);
        #pragma unroll
        for (int i = 0; i < 8; ++i)
            ((float4*)g_mem)[gtid + i * 131072] = z4;
        if (gtid < 4096)            ((float4*)g_h)[gtid] = z4;
        else if (gtid < 8192)       ((float4*)g_c)[gtid - 4096] = z4;
        else if (gtid < 8192+NBAR)  g_bar[gtid - 8192] = 0;
    }
}

__global__ void k_nop() {}

// ---------------- the persistent recurrence kernel (256 threads) ----------------
struct SmGates { u64 vp[128][16]; };   // v as {b even, b odd} pairs; warp-broadcast reads
struct SmP2    { float h[4][32]; };
struct SmAttn  {
    float key[8][64];
    float stat[8][256];
    float gm[8], inv[8], ws[4];
    float sk[4][64];
    float wsm[8][512];
    float racc[8][4][64];
};
union SmU { SmGates g; SmP2 p2; SmAttn a; };

__global__ __launch_bounds__(256, 1)
void k_steps(const float* __restrict__ x, const float* __restrict__ b_ih,
             const float* __restrict__ b_hh, const float* __restrict__ b_head) {
    __shared__ SmU sm;
    const int bid = blockIdx.x, tid = threadIdx.x;

    // P1 partition: (16 n-chunks of 128) x (8 k-slices of 128)
    const int nc = bid >> 3, ksg = bid & 7;
    const int n0 = nc * 128, k0g = ksg * 128;
    const int n_l = tid & 127;        // this thread's n-column within the chunk
    const int bh  = tid >> 7;         // 0: batches 0..15, 1: batches 16..31
    // P2 partition
    const int bq2 = bid >> 4, ks2 = bid & 15;
    const int b02 = bq2 * 4, j0 = ks2 * 32;
    // P3/P4 partition
    const int ab = bid >> 2, mq = bid & 3;
    const int m0 = mq * 512;

    for (int t = 0; t < T_; ++t) {
        // ================= P1: gates GEMM (k-split partials) =================
        // LDS: warp-broadcast v pairs only. w: L1-resident global slice (same 64KB every t).
        {
            // build v pair tile [128k][16 pairs]
            #pragma unroll
            for (int e = 0; e < 8; ++e) {
                int idx = e * 256 + tid;
                int kk = idx >> 4, p = idx & 15;
                int gk = k0g + kk;
                int bb = p * 2;
                float v0, v1;
                if (gk < 256) {
                    v0 = __ldg(&x[(bb * T_ + t) * I_ + gk]);
                    v1 = __ldg(&x[((bb+1) * T_ + t) * I_ + gk]);
                } else if (gk < 512) {
                    if (t == 0) { v0 = 0.f; v1 = 0.f; }
                    else {
                        int r = gk - 256;
                        v0 = __ldcg(&g_read_part[t-1][0][bb][r]) + __ldcg(&g_read_part[t-1][1][bb][r])
                           + __ldcg(&g_read_part[t-1][2][bb][r]) + __ldcg(&g_read_part[t-1][3][bb][r]);
                        v1 = __ldcg(&g_read_part[t-1][0][bb+1][r]) + __ldcg(&g_read_part[t-1][1][bb+1][r])
                           + __ldcg(&g_read_part[t-1][2][bb+1][r]) + __ldcg(&g_read_part[t-1][3][bb+1][r]);
                    }
                } else {
                    v0 = __ldcg(&g_h[bb * H_ + (gk - 512)]);
                    v1 = __ldcg(&g_h[(bb+1) * H_ + (gk - 512)]);
                }
                sm.g.vp[kk][p] = pack2(v0, v1);
            }
            __syncthreads();
            const float* wp = &g_WgT[(size_t)k0g * NG_ + n0 + n_l];
            u64 acc[8];
            #pragma unroll
            for (int i = 0; i < 8; ++i) acc[i] = 0ull;
            #pragma unroll 4
            for (int k = 0; k < 128; ++k) {
                float w = __ldg(wp + (size_t)k * NG_);      // L1 hit (warm after step 0)
                u64 w2 = pack2(w, w);
                const u64* vrow = &sm.g.vp[k][bh * 8];      // broadcast within warp
                #pragma unroll
                for (int i = 0; i < 8; ++i)
                    acc[i] = ffma2(vrow[i], w2, acc[i]);
            }
            const int n_g = n0 + n_l;
            float bi = 0.f;
            if (ksg == 0) bi = __ldg(&b_ih[n_g]) + __ldg(&b_hh[n_g]);
            #pragma unroll
            for (int i = 0; i < 8; ++i) {
                float2 pp = unpack2(acc[i]);
                int b = bh * 16 + i * 2;
                g_gates_part[ksg][b][n_g]     = pp.x + bi;
                g_gates_part[ksg][b + 1][n_g] = pp.y + bi;
            }
            __syncthreads();
        }
        gridbar(4*t + 0);

        // ================= P2: LSTM elementwise + partial head GEMM =================
        {
            if (tid < 128) {
                int bi = tid >> 5, jj = tid & 31;
                int b = b02 + bi, j = j0 + jj;
                float gi = 0.f, gf = 0.f, gg = 0.f, go = 0.f;
                #pragma unroll
                for (int p = 0; p < 8; ++p) {
                    gi += __ldcg(&g_gates_part[p][b][j]);
                    gf += __ldcg(&g_gates_part[p][b][512 + j]);
                    gg += __ldcg(&g_gates_part[p][b][1024 + j]);
                    go += __ldcg(&g_gates_part[p][b][1536 + j]);
                }
                float cold = g_c[b * H_ + j];
                float iv = sigm_acc(gi), fv = sigm_acc(gf);
                float gv = tanhf(gg),   ov = sigm_acc(go);
                float cn = fv * cold + iv * gv;
                float hn = ov * tanhf(cn);
                g_c[b * H_ + j] = cn;
                g_h[b * H_ + j] = hn;
                g_hist_h[t][b][j] = hn;
                sm.p2.h[bi][jj] = hn;
            }
            __syncthreads();
            #pragma unroll
            for (int e = 0; e < 3; ++e) {
                int nn = tid + e * 256;
                if (nn < NHP_) {
                    float a0 = 0.f, a1 = 0.f, a2 = 0.f, a3 = 0.f;
                    #pragma unroll
                    for (int k = 0; k < 32; ++k) {
                        float w = __ldcg(&g_WhT[(size_t)(j0 + k) * NHP_ + nn]);
                        a0 += sm.p2.h[0][k] * w;
                        a1 += sm.p2.h[1][k] * w;
                        a2 += sm.p2.h[2][k] * w;
                        a3 += sm.p2.h[3][k] * w;
                    }
                    g_hp_part[ks2][b02 + 0][nn] = a0;
                    g_hp_part[ks2][b02 + 1][nn] = a1;
                    g_hp_part[ks2][b02 + 2][nn] = a2;
                    g_hp_part[ks2][b02 + 3][nn] = a3;
                }
            }
        }
        gridbar(4*t + 1);

        // ================= P3: attention scores (kept in registers) =================
        float s[2][8];
        {
            #pragma unroll
            for (int e = 0; e < 2; ++e) {
                int idx = e * 256 + tid;
                int key = idx >> 6, h = idx & 63;
                int n = key & 3;
                int p = (key < 4) ? h : 64 + h;
                float v = __ldg(&b_head[n * HPROW_ + p]);
                #pragma unroll
                for (int ps = 0; ps < 16; ++ps) v += __ldcg(&g_hp_part[ps][ab][n * 129 + p]);
                sm.a.key[key][h] = v * 0.125f;   // fold 1/sqrt(HS)
            }
            __syncthreads();
            #pragma unroll
            for (int ms = 0; ms < 2; ++ms)
                #pragma unroll
                for (int key = 0; key < 8; ++key) s[ms][key] = 0.f;
            #pragma unroll
            for (int ms = 0; ms < 2; ++ms) {
                const int m = m0 + tid * 2 + ms;
                const float4* mp = (const float4*)&g_mem[ab][m][0];   // block-private: L1-warm
                float4 r[16];
                #pragma unroll
                for (int i = 0; i < 16; ++i) r[i] = mp[i];
                #pragma unroll
                for (int hc = 0; hc < 16; ++hc) {
                    float4 mv = r[hc];
                    #pragma unroll
                    for (int key = 0; key < 8; ++key) {
                        float4 kq = *(const float4*)&sm.a.key[key][hc * 4];
                        s[ms][key] += kq.x*mv.x + kq.y*mv.y + kq.z*mv.z + kq.w*mv.w;
                    }
                }
            }
            // chunk stats: max
            #pragma unroll
            for (int key = 0; key < 8; ++key)
                sm.a.stat[key][tid] = fmaxf(s[0][key], s[1][key]);
            __syncthreads();
            {
                const int w = tid >> 5, l = tid & 31;
                float mx = -1e30f;
                for (int i = l; i < 256; i += 32) mx = fmaxf(mx, sm.a.stat[w][i]);
                #pragma unroll
                for (int sh = 16; sh; sh >>= 1) mx = fmaxf(mx, __shfl_xor_sync(0xffffffffu, mx, sh));
                if (l == 0) sm.a.gm[w] = mx;
            }
            __syncthreads();
            #pragma unroll
            for (int key = 0; key < 8; ++key)
                sm.a.stat[key][tid] = __expf(s[0][key] - sm.a.gm[key]) + __expf(s[1][key] - sm.a.gm[key]);
            __syncthreads();
            {
                const int w = tid >> 5, l = tid & 31;
                float se = 0.f;
                for (int i = l; i < 256; i += 32) se += sm.a.stat[w][i];
                #pragma unroll
                for (int sh = 16; sh; sh >>= 1) se += __shfl_xor_sync(0xffffffffu, se, sh);
                if (l == 0) g_stats[ab][w][mq] = make_float2(sm.a.gm[w], se);
            }
        }
        gridbar(4*t + 2);

        // ================= P4: softmax apply, read accumulate, memory update =================
        {
            if (tid < 8) {
                float2 st0 = __ldcg(&g_stats[ab][tid][0]);
                float2 st1 = __ldcg(&g_stats[ab][tid][1]);
                float2 st2 = __ldcg(&g_stats[ab][tid][2]);
                float2 st3 = __ldcg(&g_stats[ab][tid][3]);
                float gm = fmaxf(fmaxf(st0.x, st1.x), fmaxf(st2.x, st3.x));
                float ssum = st0.y * __expf(st0.x - gm) + st1.y * __expf(st1.x - gm)
                           + st2.y * __expf(st2.x - gm) + st3.y * __expf(st3.x - gm);
                sm.a.gm[tid] = gm; sm.a.inv[tid] = 1.f / ssum;
            } else if (tid < 12) {
                int n = tid - 8;
                float v = __ldg(&b_head[n * HPROW_ + 128]);
                #pragma unroll
                for (int ps = 0; ps < 16; ++ps) v += __ldcg(&g_hp_part[ps][ab][n * 129 + 128]);
                sm.a.ws[n] = sigm_acc(v);
            }
            __syncthreads();
            {
                int n = tid >> 6, h = tid & 63;
                float v = __ldg(&b_head[n * HPROW_ + 64 + h]);
                #pragma unroll
                for (int ps = 0; ps < 16; ++ps) v += __ldcg(&g_hp_part[ps][ab][n * 129 + 64 + h]);
                sm.a.sk[n][h] = v * sm.a.ws[n];
            }
            #pragma unroll
            for (int ms = 0; ms < 2; ++ms)
                #pragma unroll
                for (int key = 0; key < 8; ++key)
                    sm.a.wsm[key][tid * 2 + ms] = __expf(s[ms][key] - sm.a.gm[key]) * sm.a.inv[key];
            __syncthreads();

            const int w = tid >> 5, l = tid & 31;
            const int msub = l >> 3, hb = (l & 7) * 8;
            float skreg[4][8];
            #pragma unroll
            for (int n = 0; n < 4; ++n) {
                float4 a4 = *(const float4*)&sm.a.sk[n][hb];
                float4 c4 = *(const float4*)&sm.a.sk[n][hb + 4];
                skreg[n][0]=a4.x; skreg[n][1]=a4.y; skreg[n][2]=a4.z; skreg[n][3]=a4.w;
                skreg[n][4]=c4.x; skreg[n][5]=c4.y; skreg[n][6]=c4.z; skreg[n][7]=c4.w;
            }
            float racc[4][8];
            #pragma unroll
            for (int n = 0; n < 4; ++n)
                #pragma unroll
                for (int q = 0; q < 8; ++q) racc[n][q] = 0.f;
            #pragma unroll
            for (int it = 0; it < 16; ++it) {
                int ml = it * 32 + w * 4 + msub;
                int m = m0 + ml;
                float* mp = &g_mem[ab][m][hb];                        // block-private: L1-warm
                float4 a4 = *(const float4*)mp;
                float4 c4 = *(const float4*)(mp + 4);
                float mv[8] = {a4.x, a4.y, a4.z, a4.w, c4.x, c4.y, c4.z, c4.w};
                float rw[4], ww[4];
                #pragma unroll
                for (int n = 0; n < 4; ++n) { rw[n] = sm.a.wsm[n][ml]; ww[n] = sm.a.wsm[4 + n][ml]; }
                #pragma unroll
                for (int n = 0; n < 4; ++n)
                    #pragma unroll
                    for (int q = 0; q < 8; ++q) racc[n][q] += rw[n] * mv[q];
                #pragma unroll
                for (int q = 0; q < 8; ++q)
                    mv[q] += ww[0]*skreg[0][q] + ww[1]*skreg[1][q] + ww[2]*skreg[2][q] + ww[3]*skreg[3][q];
                a4.x=mv[0]; a4.y=mv[1]; a4.z=mv[2]; a4.w=mv[3];
                c4.x=mv[4]; c4.y=mv[5]; c4.z=mv[6]; c4.w=mv[7];
                *(float4*)mp = a4;
                *(float4*)(mp + 4) = c4;
            }
            #pragma unroll
            for (int n = 0; n < 4; ++n)
                #pragma unroll
                for (int q = 0; q < 8; ++q) {
                    racc[n][q] += __shfl_xor_sync(0xffffffffu, racc[n][q], 8);
                    racc[n][q] += __shfl_xor_sync(0xffffffffu, racc[n][q], 16);
                }
            if (l < 8) {
                #pragma unroll
                for (int n = 0; n < 4; ++n)
                    #pragma unroll
                    for (int q = 0; q < 8; ++q) sm.a.racc[w][n][hb + q] = racc[n][q];
            }
            __syncthreads();
            {
                int n = tid >> 6, h = tid & 63;
                float ssum = 0.f;
                #pragma unroll
                for (int wr = 0; wr < 8; ++wr) ssum += sm.a.racc[wr][n][h];
                g_read_part[t][mq][ab][n * 64 + h] = ssum;
            }
        }
        gridbar(4*t + 3);
    }
}

// ---------------- final output GEMM: outputs[b][t][o] ----------------
__global__ void k_out(const float* __restrict__ b_out, float* __restrict__ out) {
    const int m0 = blockIdx.x * 32, nc = blockIdx.y;
    const int tid = threadIdx.x;
    __shared__ float a_sh[32][64];
    const int n_l = tid & 63, mg = tid >> 6;
    const int n = nc * 64 + n_l;
    float acc[8];
    #pragma unroll
    for (int r = 0; r < 8; ++r) acc[r] = 0.f;
    for (int kt = 0; kt < 12; ++kt) {
        __syncthreads();
        #pragma unroll
        for (int e = 0; e < 8; ++e) {
            int lidx = e * 256 + tid;
            int mrow = lidx >> 6, kk = lidx & 63;
            int m = m0 + mrow;
            int ts = m >> 5, bb = m & 31;
            int gk = kt * 64 + kk;
            float v;
            if (gk < 512) v = g_hist_h[ts][bb][gk];
            else {
                int r = gk - 512;
                v = g_read_part[ts][0][bb][r] + g_read_part[ts][1][bb][r]
                  + g_read_part[ts][2][bb][r] + g_read_part[ts][3][bb][r];
            }
            a_sh[mrow][kk] = v;
        }
        __syncthreads();
        #pragma unroll 4
        for (int kk = 0; kk < 64; ++kk) {
            float wv = g_WoT[(kt * 64 + kk) * O_ + n];
            #pragma unroll
            for (int r = 0; r < 8; ++r) acc[r] += a_sh[mg * 8 + r][kk] * wv;
        }
    }
    float bo = b_out[n];
    #pragma unroll
    for (int r = 0; r < 8; ++r) {
        int m = m0 + mg * 8 + r;
        int ts = m >> 5, bb = m & 31;
        out[(bb * T_ + ts) * O_ + n] = acc[r] + bo;
    }
}

// ---------------- final state copy: mem, h, c into d_out ----------------
__global__ void k_final(float* __restrict__ out) {
    const int OUT_N = B_ * T_ * O_;            // 262144
    const int NMEM  = B_ * MS_ * HS_;          // 4194304
    const int total = NMEM + 2 * B_ * H_;
    for (int i = blockIdx.x * blockDim.x + threadIdx.x; i < total; i += gridDim.x * blockDim.x) {
        if (i < NMEM)                 out[OUT_N + i] = (&g_mem[0][0][0])[i];
        else if (i < NMEM + B_ * H_)  out[OUT_N + i] = g_h[i - NMEM];
        else                          out[OUT_N + i] = g_c[i - NMEM - B_ * H_];
    }
}

extern "C" void kernel_launch(void* const* d_in, const int* in_sizes, int n_in,
                              void* d_out, int out_size) {
    const float* x      = (const float*)d_in[0];
    const float* W_ih   = (const float*)d_in[1];
    const float* W_hh   = (const float*)d_in[2];
    const float* b_ih   = (const float*)d_in[3];
    const float* b_hh   = (const float*)d_in[4];
    const float* W_head = (const float*)d_in[5];
    const float* b_head = (const float*)d_in[6];
    const float* W_out  = (const float*)d_in[7];
    const float* b_out  = (const float*)d_in[8];
    float* out = (float*)d_out;

    k_prep<<<3024, 256>>>(W_ih, W_hh, W_head, W_out);
    k_nop<<<1, 32>>>();
    k_nop<<<1, 32>>>();
    k_steps<<<NBLK, 256>>>(x, b_ih, b_hh, b_head);
    k_out<<<dim3(32, 4), 256>>>(b_out, out);
    k_final<<<2048, 256>>>(out);
}

// round 10
// speedup vs baseline: 1.1662x; 1.0424x over previous
#include <cuda_runtime.h>
#include <math.h>

// Problem constants
#define B_  32
#define T_  32
#define I_  256
#define H_  512
#define NH_ 4
#define HS_ 64
#define MS_ 2048
#define O_  256
// derived
#define KG_ 1024        // ctrl_in (512) + H (512)
#define NG_ 2048        // 4*H, gate col index n = g*512 + j
#define NHP_ 516        // 4 heads * 129 used head outputs
#define HPROW_ 2115     // HS + MS + 3
#define NBLK 128
#define NTHR 512
#define NBAR (4*T_)

typedef unsigned long long u64;

__device__ __forceinline__ u64 ffma2(u64 a, u64 b, u64 c) {
    u64 d; asm("fma.rn.f32x2 %0, %1, %2, %3;" : "=l"(d) : "l"(a), "l"(b), "l"(c)); return d;
}
__device__ __forceinline__ u64 fadd2(u64 a, u64 b) {
    u64 d; asm("add.rn.f32x2 %0, %1, %2;" : "=l"(d) : "l"(a), "l"(b)); return d;
}
__device__ __forceinline__ u64 pack2(float lo, float hi) {
    u64 d; asm("mov.b64 %0, {%1, %2};" : "=l"(d) : "f"(lo), "f"(hi)); return d;
}
__device__ __forceinline__ float2 unpack2(u64 v) {
    float2 r; asm("mov.b64 {%0, %1}, %2;" : "=f"(r.x), "=f"(r.y) : "l"(v)); return r;
}

// ---------------- scratch (device globals; no allocation allowed) ----------------
__device__ float g_WgT[KG_*NG_];              // [k][n]  8MB   (n = g*512+j)
__device__ float g_WhT[H_*NHP_];              // [k][n*129+p]  1MB
__device__ float g_WoT[(H_+NH_*HS_)*O_];      // [k][o]
__device__ float g_h[B_*H_];
__device__ float g_c[B_*H_];
__device__ float g_gates_part[8][B_][NG_];    // k-split (8) partial gates
__device__ float g_hp_part[16][B_][NHP_];     // k-split (16) partial head outputs
__device__ float2 g_stats[B_][8][4];          // [b][key][mq] = {chunk max, chunk sumexp}
__device__ float g_read_part[T_][4][B_][NH_*HS_]; // per-mq read partials
__device__ float g_hist_h[T_][B_][H_];
__device__ float g_mem[B_][MS_][HS_];         // 16.7MB
__device__ int   g_bar[NBAR];

__device__ __forceinline__ float sigm_acc(float v) { return 1.f / (1.f + expf(-v)); }

// ---------------- grid barrier: release-add + acquire-poll, no L1 flush ----------------
__device__ __forceinline__ void gridbar(int idx) {
    __syncthreads();
    if (threadIdx.x == 0) {
        int* p = &g_bar[idx];
        asm volatile("red.release.gpu.global.add.s32 [%0], 1;" :: "l"(p) : "memory");
        int v;
        do {
            asm volatile("ld.acquire.gpu.global.s32 %0, [%1];" : "=r"(v) : "l"(p) : "memory");
        } while (v < NBLK);
    }
    __syncthreads();
}

// ---------------- fused prep: transposes + zeroing in ONE launch ----------------
__global__ void k_prep(const float* __restrict__ W_ih, const float* __restrict__ W_hh,
                       const float* __restrict__ W_head, const float* __restrict__ W_out) {
    const int b = blockIdx.x;
    const int tid = threadIdx.x;                // 256
    const int tx = tid & 31, ty = tid >> 5;     // (32, 8)
    __shared__ float tile[32][33];
    if (b < 2048) {                             // WgT[k][n] = [W_ih|W_hh][n][k]
        int bx = (b & 31) * 32, by = (b >> 5) * 32;
        #pragma unroll
        for (int i = 0; i < 32; i += 8) {
            int row = by + ty + i, k = bx + tx;
            tile[ty + i][tx] = (k < 512) ? W_ih[row*512 + k] : W_hh[row*512 + (k - 512)];
        }
        __syncthreads();
        #pragma unroll
        for (int i = 0; i < 32; i += 8) {
            int k = bx + ty + i, row = by + tx;
            g_WgT[(size_t)k * NG_ + row] = tile[tx][ty + i];
        }
    } else if (b < 2048 + 272) {                // WhT[k][r], r = n*129+p
        int bb = b - 2048;
        int bx = (bb & 15) * 32, by = (bb >> 4) * 32;
        #pragma unroll
        for (int i = 0; i < 32; i += 8) {
            int r = by + ty + i, k = bx + tx;
            float v = 0.f;
            if (r < NHP_) {
                int n = r / 129, p = r % 129;
                v = W_head[(size_t)(n * HPROW_ + p) * 512 + k];
            }
            tile[ty + i][tx] = v;
        }
        __syncthreads();
        #pragma unroll
        for (int i = 0; i < 32; i += 8) {
            int k = bx + ty + i, r = by + tx;
            if (r < NHP_) g_WhT[(size_t)k * NHP_ + r] = tile[tx][ty + i];
        }
    } else if (b < 2048 + 272 + 192) {          // WoT[k][o] = W_out[o][k]
        int bb = b - 2320;
        int bx = (bb % 24) * 32, by = (bb / 24) * 32;
        #pragma unroll
        for (int i = 0; i < 32; i += 8) {
            int o = by + ty + i, k = bx + tx;
            tile[ty + i][tx] = W_out[o * (H_ + NH_*HS_) + k];
        }
        __syncthreads();
        #pragma unroll
        for (int i = 0; i < 32; i += 8) {
            int k = bx + ty + i, o = by + tx;
            g_WoT[(size_t)k * O_ + o] = tile[tx][ty + i];
        }
    } else {                                    // zero mem, h, c, barriers
        int bb = b - 2512;                      // 0..511
        int gtid = bb * 256 + tid;              // 0..131071
        float4 z4 = make_float4(0.f, 0.f, 0.f, 0.f);
        #pragma unroll
        for (int i = 0; i < 8; ++i)
            ((float4*)g_mem)[gtid + i * 131072] = z4;
        if (gtid < 4096)            ((float4*)g_h)[gtid] = z4;
        else if (gtid < 8192)       ((float4*)g_c)[gtid - 4096] = z4;
        else if (gtid < 8192+NBAR)  g_bar[gtid - 8192] = 0;
    }
}

__global__ void k_nop() {}

// ---------------- the persistent recurrence kernel (512 threads) ----------------
struct SmGates { u64 vdup[128][36]; };   // {v,v} per [k][b]; padded to kill STS conflicts
struct SmP2    { float h[4][32]; };
struct SmAttn  {
    float key[8][64];
    float stat[8][512];
    float gm[8], inv[8], ws[4];
    float sk[4][64];
    u64   wsm[8][512];                   // softmax weights pre-duplicated {w,w}
    float racc[16][4][64];
};
union __align__(16) SmU { SmGates g; SmP2 p2; SmAttn a; };

extern __shared__ unsigned char sm_raw[];

__global__ __launch_bounds__(NTHR, 1)
void k_steps(const float* __restrict__ x, const float* __restrict__ b_ih,
             const float* __restrict__ b_hh, const float* __restrict__ b_head) {
    SmU& sm = *reinterpret_cast<SmU*>(sm_raw);
    const int bid = blockIdx.x, tid = threadIdx.x;

    // P1 partition: (16 n-chunks of 128) x (8 k-slices of 128)
    const int nc = bid >> 3, ksg = bid & 7;
    const int n0 = nc * 128, k0g = ksg * 128;
    const int cg = tid & 31;          // col group: 4 cols each -> 128 cols
    const int bg = tid >> 5;          // batch pair 0..15 -> batches 2bg, 2bg+1
    // P2 partition
    const int bq2 = bid >> 4, ks2 = bid & 15;
    const int b02 = bq2 * 4, j0 = ks2 * 32;
    // P3/P4 partition
    const int ab = bid >> 2, mq = bid & 3;
    const int m0 = mq * 512;

    for (int t = 0; t < T_; ++t) {
        // ================= P1: gates GEMM (k-split partials) =================
        {
            // build vdup[128][32 used]: lanes cover 8 consecutive k x 4 batches
            #pragma unroll
            for (int e = 0; e < 8; ++e) {
                int idx = e * 512 + tid;
                int kk8 = idx & 7, bb = (idx >> 3) & 31, khi = idx >> 8;
                int kk = khi * 8 + kk8;
                int gk = k0g + kk;
                float v;
                if (gk < 256) {
                    v = __ldg(&x[(bb * T_ + t) * I_ + gk]);
                } else if (gk < 512) {
                    if (t == 0) v = 0.f;
                    else {
                        int r = gk - 256;
                        v = __ldcg(&g_read_part[t-1][0][bb][r]) + __ldcg(&g_read_part[t-1][1][bb][r])
                          + __ldcg(&g_read_part[t-1][2][bb][r]) + __ldcg(&g_read_part[t-1][3][bb][r]);
                    }
                } else {
                    v = __ldcg(&g_h[bb * H_ + (gk - 512)]);
                }
                sm.g.vdup[kk][bb] = pack2(v, v);
            }
            __syncthreads();
            const int n_g = n0 + cg * 4;
            const float* wbase = &g_WgT[(size_t)k0g * NG_ + n_g];
            u64 acc00, acc01, acc10, acc11;     // [batch][col-pair]
            {
                u64 b01 = 0ull, b23 = 0ull;
                if (ksg == 0) {
                    b01 = pack2(__ldg(&b_ih[n_g])   + __ldg(&b_hh[n_g]),
                                __ldg(&b_ih[n_g+1]) + __ldg(&b_hh[n_g+1]));
                    b23 = pack2(__ldg(&b_ih[n_g+2]) + __ldg(&b_hh[n_g+2]),
                                __ldg(&b_ih[n_g+3]) + __ldg(&b_hh[n_g+3]));
                }
                acc00 = b01; acc01 = b23; acc10 = b01; acc11 = b23;
            }
            const int b0 = bg * 2;
            #pragma unroll 4
            for (int k = 0; k < 128; ++k) {
                ulonglong2 wl = *(const ulonglong2*)(wbase + (size_t)k * NG_);  // {w0,w1},{w2,w3}
                u64 v0 = sm.g.vdup[k][b0];        // broadcast within warp
                u64 v1 = sm.g.vdup[k][b0 + 1];
                acc00 = ffma2(wl.x, v0, acc00);
                acc01 = ffma2(wl.y, v0, acc01);
                acc10 = ffma2(wl.x, v1, acc10);
                acc11 = ffma2(wl.y, v1, acc11);
            }
            ulonglong2 st0; st0.x = acc00; st0.y = acc01;
            ulonglong2 st1; st1.x = acc10; st1.y = acc11;
            *(ulonglong2*)&g_gates_part[ksg][b0][n_g]     = st0;
            *(ulonglong2*)&g_gates_part[ksg][b0 + 1][n_g] = st1;
            __syncthreads();
        }
        gridbar(4*t + 0);

        // ================= P2: LSTM elementwise + partial head GEMM =================
        {
            if (tid < 128) {
                int bi = tid >> 5, jj = tid & 31;
                int b = b02 + bi, j = j0 + jj;
                float gi = 0.f, gf = 0.f, gg = 0.f, go = 0.f;
                #pragma unroll
                for (int p = 0; p < 8; ++p) {
                    gi += __ldcg(&g_gates_part[p][b][j]);
                    gf += __ldcg(&g_gates_part[p][b][512 + j]);
                    gg += __ldcg(&g_gates_part[p][b][1024 + j]);
                    go += __ldcg(&g_gates_part[p][b][1536 + j]);
                }
                float cold = g_c[b * H_ + j];
                float iv = sigm_acc(gi), fv = sigm_acc(gf);
                float gv = tanhf(gg),   ov = sigm_acc(go);
                float cn = fv * cold + iv * gv;
                float hn = ov * tanhf(cn);
                g_c[b * H_ + j] = cn;
                g_h[b * H_ + j] = hn;
                g_hist_h[t][b][j] = hn;
                sm.p2.h[bi][jj] = hn;
            }
            __syncthreads();
            #pragma unroll
            for (int e = 0; e < 2; ++e) {
                int nn = tid + e * 512;
                if (nn < NHP_) {
                    float a0 = 0.f, a1 = 0.f, a2 = 0.f, a3 = 0.f;
                    #pragma unroll
                    for (int k = 0; k < 32; ++k) {
                        float w = __ldcg(&g_WhT[(size_t)(j0 + k) * NHP_ + nn]);
                        a0 += sm.p2.h[0][k] * w;
                        a1 += sm.p2.h[1][k] * w;
                        a2 += sm.p2.h[2][k] * w;
                        a3 += sm.p2.h[3][k] * w;
                    }
                    g_hp_part[ks2][b02 + 0][nn] = a0;
                    g_hp_part[ks2][b02 + 1][nn] = a1;
                    g_hp_part[ks2][b02 + 2][nn] = a2;
                    g_hp_part[ks2][b02 + 3][nn] = a3;
                }
            }
        }
        // hoist the block-private mem-row load ABOVE the barrier (overlaps barrier wait)
        ulonglong2 r[16];
        {
            const ulonglong2* mp = (const ulonglong2*)&g_mem[ab][m0 + tid][0];
            #pragma unroll
            for (int i = 0; i < 16; ++i) r[i] = mp[i];
        }
        gridbar(4*t + 1);

        // ================= P3: keys + scores (1 row/thread) + chunk stats =================
        float s[8];
        {
            {   // key build: 512 entries, 1 per thread
                int key = tid >> 6, h = tid & 63;
                int n = key & 3;
                int p = (key < 4) ? h : 64 + h;
                float v = __ldg(&b_head[n * HPROW_ + p]);
                #pragma unroll
                for (int ps = 0; ps < 16; ++ps) v += __ldcg(&g_hp_part[ps][ab][n * 129 + p]);
                sm.a.key[key][h] = v * 0.125f;   // fold 1/sqrt(HS)
            }
            __syncthreads();
            u64 s2[8];
            #pragma unroll
            for (int key = 0; key < 8; ++key) s2[key] = 0ull;
            #pragma unroll
            for (int hc = 0; hc < 16; ++hc) {
                u64 m01 = r[hc].x, m23 = r[hc].y;
                #pragma unroll
                for (int key = 0; key < 8; ++key) {
                    ulonglong2 k2 = *(const ulonglong2*)&sm.a.key[key][hc * 4];
                    s2[key] = ffma2(k2.x, m01, s2[key]);
                    s2[key] = ffma2(k2.y, m23, s2[key]);
                }
            }
            #pragma unroll
            for (int key = 0; key < 8; ++key) {
                float2 p = unpack2(s2[key]);
                s[key] = p.x + p.y;
                sm.a.stat[key][tid] = s[key];
            }
            __syncthreads();
            const int w = tid >> 5, l = tid & 31;
            if (w < 8) {
                float mx = -1e30f;
                for (int i = l; i < 512; i += 32) mx = fmaxf(mx, sm.a.stat[w][i]);
                #pragma unroll
                for (int sh = 16; sh; sh >>= 1) mx = fmaxf(mx, __shfl_xor_sync(0xffffffffu, mx, sh));
                if (l == 0) sm.a.gm[w] = mx;
            }
            __syncthreads();
            #pragma unroll
            for (int key = 0; key < 8; ++key)
                sm.a.stat[key][tid] = __expf(s[key] - sm.a.gm[key]);
            __syncthreads();
            if (w < 8) {
                float se = 0.f;
                for (int i = l; i < 512; i += 32) se += sm.a.stat[w][i];
                #pragma unroll
                for (int sh = 16; sh; sh >>= 1) se += __shfl_xor_sync(0xffffffffu, se, sh);
                if (l == 0) g_stats[ab][w][mq] = make_float2(sm.a.gm[w], se);
            }
        }
        gridbar(4*t + 2);

        // ================= P4: softmax apply, read accumulate, memory update =================
        {
            if (tid < 8) {
                float2 st0 = __ldcg(&g_stats[ab][tid][0]);
                float2 st1 = __ldcg(&g_stats[ab][tid][1]);
                float2 st2 = __ldcg(&g_stats[ab][tid][2]);
                float2 st3 = __ldcg(&g_stats[ab][tid][3]);
                float gm = fmaxf(fmaxf(st0.x, st1.x), fmaxf(st2.x, st3.x));
                float ssum = st0.y * __expf(st0.x - gm) + st1.y * __expf(st1.x - gm)
                           + st2.y * __expf(st2.x - gm) + st3.y * __expf(st3.x - gm);
                sm.a.gm[tid] = gm; sm.a.inv[tid] = 1.f / ssum;
            } else if (tid < 12) {
                int n = tid - 8;
                float v = __ldg(&b_head[n * HPROW_ + 128]);
                #pragma unroll
                for (int ps = 0; ps < 16; ++ps) v += __ldcg(&g_hp_part[ps][ab][n * 129 + 128]);
                sm.a.ws[n] = sigm_acc(v);
            }
            __syncthreads();
            if (tid < 256) {
                int n = tid >> 6, h = tid & 63;
                float v = __ldg(&b_head[n * HPROW_ + 64 + h]);
                #pragma unroll
                for (int ps = 0; ps < 16; ++ps) v += __ldcg(&g_hp_part[ps][ab][n * 129 + 64 + h]);
                sm.a.sk[n][h] = v * sm.a.ws[n];
            }
            #pragma unroll
            for (int key = 0; key < 8; ++key) {
                float wv = __expf(s[key] - sm.a.gm[key]) * sm.a.inv[key];
                sm.a.wsm[key][tid] = pack2(wv, wv);
            }
            __syncthreads();

            const int w = tid >> 5, l = tid & 31;
            const int msub = l >> 3, hb = (l & 7) * 8;
            u64 skreg2[4][4];
            #pragma unroll
            for (int n = 0; n < 4; ++n)
                #pragma unroll
                for (int q2 = 0; q2 < 4; ++q2)
                    skreg2[n][q2] = *(const u64*)&sm.a.sk[n][hb + q2 * 2];
            u64 racc2[4][4];
            #pragma unroll
            for (int n = 0; n < 4; ++n)
                #pragma unroll
                for (int q2 = 0; q2 < 4; ++q2) racc2[n][q2] = 0ull;
            #pragma unroll
            for (int it = 0; it < 8; ++it) {
                int ml = it * 64 + w * 4 + msub;
                ulonglong2* mp2 = (ulonglong2*)&g_mem[ab][m0 + ml][hb];
                ulonglong2 a2 = mp2[0], c2 = mp2[1];
                u64 rw2[4], ww2[4];
                #pragma unroll
                for (int n = 0; n < 4; ++n) { rw2[n] = sm.a.wsm[n][ml]; ww2[n] = sm.a.wsm[4 + n][ml]; }
                #pragma unroll
                for (int n = 0; n < 4; ++n) {
                    racc2[n][0] = ffma2(rw2[n], a2.x, racc2[n][0]);
                    racc2[n][1] = ffma2(rw2[n], a2.y, racc2[n][1]);
                    racc2[n][2] = ffma2(rw2[n], c2.x, racc2[n][2]);
                    racc2[n][3] = ffma2(rw2[n], c2.y, racc2[n][3]);
                }
                #pragma unroll
                for (int n = 0; n < 4; ++n) {
                    a2.x = ffma2(ww2[n], skreg2[n][0], a2.x);
                    a2.y = ffma2(ww2[n], skreg2[n][1], a2.y);
                    c2.x = ffma2(ww2[n], skreg2[n][2], c2.x);
                    c2.y = ffma2(ww2[n], skreg2[n][3], c2.y);
                }
                mp2[0] = a2; mp2[1] = c2;
            }
            #pragma unroll
            for (int n = 0; n < 4; ++n)
                #pragma unroll
                for (int q2 = 0; q2 < 4; ++q2) {
                    racc2[n][q2] = fadd2(racc2[n][q2], __shfl_xor_sync(0xffffffffu, racc2[n][q2], 8));
                    racc2[n][q2] = fadd2(racc2[n][q2], __shfl_xor_sync(0xffffffffu, racc2[n][q2], 16));
                }
            if (l < 8) {
                #pragma unroll
                for (int n = 0; n < 4; ++n)
                    #pragma unroll
                    for (int q2 = 0; q2 < 4; ++q2) {
                        float2 p = unpack2(racc2[n][q2]);
                        sm.a.racc[w][n][hb + q2*2]     = p.x;
                        sm.a.racc[w][n][hb + q2*2 + 1] = p.y;
                    }
            }
            __syncthreads();
            if (tid < 256) {
                int n = tid >> 6, h = tid & 63;
                float ssum = 0.f;
                #pragma unroll
                for (int wr = 0; wr < 16; ++wr) ssum += sm.a.racc[wr][n][h];
                g_read_part[t][mq][ab][n * 64 + h] = ssum;
            }
        }
        gridbar(4*t + 3);
    }
}

// ---------------- final output GEMM: outputs[b][t][o] ----------------
__global__ void k_out(const float* __restrict__ b_out, float* __restrict__ out) {
    const int m0 = blockIdx.x * 32, nc = blockIdx.y;
    const int tid = threadIdx.x;
    __shared__ float a_sh[32][64];
    const int n_l = tid & 63, mg = tid >> 6;
    const int n = nc * 64 + n_l;
    float acc[8];
    #pragma unroll
    for (int r = 0; r < 8; ++r) acc[r] = 0.f;
    for (int kt = 0; kt < 12; ++kt) {
        __syncthreads();
        #pragma unroll
        for (int e = 0; e < 8; ++e) {
            int lidx = e * 256 + tid;
            int mrow = lidx >> 6, kk = lidx & 63;
            int m = m0 + mrow;
            int ts = m >> 5, bb = m & 31;
            int gk = kt * 64 + kk;
            float v;
            if (gk < 512) v = g_hist_h[ts][bb][gk];
            else {
                int r = gk - 512;
                v = g_read_part[ts][0][bb][r] + g_read_part[ts][1][bb][r]
                  + g_read_part[ts][2][bb][r] + g_read_part[ts][3][bb][r];
            }
            a_sh[mrow][kk] = v;
        }
        __syncthreads();
        #pragma unroll 4
        for (int kk = 0; kk < 64; ++kk) {
            float wv = g_WoT[(kt * 64 + kk) * O_ + n];
            #pragma unroll
            for (int r = 0; r < 8; ++r) acc[r] += a_sh[mg * 8 + r][kk] * wv;
        }
    }
    float bo = b_out[n];
    #pragma unroll
    for (int r = 0; r < 8; ++r) {
        int m = m0 + mg * 8 + r;
        int ts = m >> 5, bb = m & 31;
        out[(bb * T_ + ts) * O_ + n] = acc[r] + bo;
    }
}

// ---------------- final state copy: mem, h, c into d_out ----------------
__global__ void k_final(float* __restrict__ out) {
    const int OUT_N = B_ * T_ * O_;            // 262144
    const int NMEM  = B_ * MS_ * HS_;          // 4194304
    const int total = NMEM + 2 * B_ * H_;
    for (int i = blockIdx.x * blockDim.x + threadIdx.x; i < total; i += gridDim.x * blockDim.x) {
        if (i < NMEM)                 out[OUT_N + i] = (&g_mem[0][0][0])[i];
        else if (i < NMEM + B_ * H_)  out[OUT_N + i] = g_h[i - NMEM];
        else                          out[OUT_N + i] = g_c[i - NMEM - B_ * H_];
    }
}

extern "C" void kernel_launch(void* const* d_in, const int* in_sizes, int n_in,
                              void* d_out, int out_size) {
    const float* x      = (const float*)d_in[0];
    const float* W_ih   = (const float*)d_in[1];
    const float* W_hh   = (const float*)d_in[2];
    const float* b_ih   = (const float*)d_in[3];
    const float* b_hh   = (const float*)d_in[4];
    const float* W_head = (const float*)d_in[5];
    const float* b_head = (const float*)d_in[6];
    const float* W_out  = (const float*)d_in[7];
    const float* b_out  = (const float*)d_in[8];
    float* out = (float*)d_out;

    static int smem_set = 0;
    if (!smem_set) {
        cudaFuncSetAttribute(k_steps, cudaFuncAttributeMaxDynamicSharedMemorySize,
                             (int)sizeof(SmU));
        smem_set = 1;
    }

    k_prep<<<3024, 256>>>(W_ih, W_hh, W_head, W_out);
    k_nop<<<1, 32>>>();
    k_nop<<<1, 32>>>();
    k_steps<<<NBLK, NTHR, sizeof(SmU)>>>(x, b_ih, b_hh, b_head);
    k_out<<<dim3(32, 4), 256>>>(b_out, out);
    k_final<<<2048, 256>>>(out);
}

// round 11
// speedup vs baseline: 1.4320x; 1.2279x over previous
#include <cuda_runtime.h>
#include <math.h>

// Problem constants
#define B_  32
#define T_  32
#define I_  256
#define H_  512
#define NH_ 4
#define HS_ 64
#define MS_ 2048
#define O_  256
// derived
#define KG_ 1024
#define NG_ 2048        // 4*H, gate col index n = g*512 + j
#define NHP_ 516
#define HPROW_ 2115
#define NBLK 128
#define NTHR 512
#define NBAR (4*T_)

typedef unsigned long long u64;

__device__ __forceinline__ u64 ffma2(u64 a, u64 b, u64 c) {
    u64 d; asm("fma.rn.f32x2 %0, %1, %2, %3;" : "=l"(d) : "l"(a), "l"(b), "l"(c)); return d;
}
__device__ __forceinline__ u64 fadd2(u64 a, u64 b) {
    u64 d; asm("add.rn.f32x2 %0, %1, %2;" : "=l"(d) : "l"(a), "l"(b)); return d;
}
__device__ __forceinline__ u64 pack2(float lo, float hi) {
    u64 d; asm("mov.b64 %0, {%1, %2};" : "=l"(d) : "f"(lo), "f"(hi)); return d;
}
__device__ __forceinline__ float2 unpack2(u64 v) {
    float2 r; asm("mov.b64 {%0, %1}, %2;" : "=f"(r.x), "=f"(r.y) : "l"(v)); return r;
}

// ---------------- scratch (device globals; no allocation allowed) ----------------
__device__ float g_WgT[KG_*NG_];              // [k][n]  8MB
__device__ float g_WhT[H_*NHP_];              // [k][n*129+p]
__device__ float g_WoT[(H_+NH_*HS_)*O_];      // [k][o]
__device__ float g_h[B_*H_];
__device__ float g_c[B_*H_];
__device__ float g_gates_part[8][B_][NG_];
__device__ float g_hp_part[16][B_][NHP_];
__device__ float2 g_stats[B_][8][4];          // [b][key][mq] = {chunk max, chunk sumexp}
__device__ float g_read_part[T_][4][B_][NH_*HS_];
__device__ float g_hist_h[T_][B_][H_];
__device__ float g_mem[B_][MS_][HS_];         // 16.7MB
__device__ int   g_bar[NBAR];

__device__ __forceinline__ float sigm_acc(float v) { return 1.f / (1.f + expf(-v)); }

// ---------------- grid barrier: release-add + acquire-poll, no L1 flush ----------------
__device__ __forceinline__ void gridbar(int idx) {
    __syncthreads();
    if (threadIdx.x == 0) {
        int* p = &g_bar[idx];
        asm volatile("red.release.gpu.global.add.s32 [%0], 1;" :: "l"(p) : "memory");
        int v;
        do {
            asm volatile("ld.acquire.gpu.global.s32 %0, [%1];" : "=r"(v) : "l"(p) : "memory");
        } while (v < NBLK);
    }
    __syncthreads();
}

// ---------------- fused prep: transposes + zeroing in ONE launch ----------------
__global__ void k_prep(const float* __restrict__ W_ih, const float* __restrict__ W_hh,
                       const float* __restrict__ W_head, const float* __restrict__ W_out) {
    const int b = blockIdx.x;
    const int tid = threadIdx.x;                // 256
    const int tx = tid & 31, ty = tid >> 5;     // (32, 8)
    __shared__ float tile[32][33];
    if (b < 2048) {                             // WgT[k][n]
        int bx = (b & 31) * 32, by = (b >> 5) * 32;
        #pragma unroll
        for (int i = 0; i < 32; i += 8) {
            int row = by + ty + i, k = bx + tx;
            tile[ty + i][tx] = (k < 512) ? W_ih[row*512 + k] : W_hh[row*512 + (k - 512)];
        }
        __syncthreads();
        #pragma unroll
        for (int i = 0; i < 32; i += 8) {
            int k = bx + ty + i, row = by + tx;
            g_WgT[(size_t)k * NG_ + row] = tile[tx][ty + i];
        }
    } else if (b < 2048 + 272) {                // WhT[k][r]
        int bb = b - 2048;
        int bx = (bb & 15) * 32, by = (bb >> 4) * 32;
        #pragma unroll
        for (int i = 0; i < 32; i += 8) {
            int r = by + ty + i, k = bx + tx;
            float v = 0.f;
            if (r < NHP_) {
                int n = r / 129, p = r % 129;
                v = W_head[(size_t)(n * HPROW_ + p) * 512 + k];
            }
            tile[ty + i][tx] = v;
        }
        __syncthreads();
        #pragma unroll
        for (int i = 0; i < 32; i += 8) {
            int k = bx + ty + i, r = by + tx;
            if (r < NHP_) g_WhT[(size_t)k * NHP_ + r] = tile[tx][ty + i];
        }
    } else if (b < 2048 + 272 + 192) {          // WoT[k][o]
        int bb = b - 2320;
        int bx = (bb % 24) * 32, by = (bb / 24) * 32;
        #pragma unroll
        for (int i = 0; i < 32; i += 8) {
            int o = by + ty + i, k = bx + tx;
            tile[ty + i][tx] = W_out[o * (H_ + NH_*HS_) + k];
        }
        __syncthreads();
        #pragma unroll
        for (int i = 0; i < 32; i += 8) {
            int k = bx + ty + i, o = by + tx;
            g_WoT[(size_t)k * O_ + o] = tile[tx][ty + i];
        }
    } else {
        int bb = b - 2512;                      // 0..511
        int gtid = bb * 256 + tid;
        float4 z4 = make_float4(0.f, 0.f, 0.f, 0.f);
        #pragma unroll
        for (int i = 0; i < 8; ++i)
            ((float4*)g_mem)[gtid + i * 131072] = z4;
        if (gtid < 4096)            ((float4*)g_h)[gtid] = z4;
        else if (gtid < 8192)       ((float4*)g_c)[gtid - 4096] = z4;
        else if (gtid < 8192+NBAR)  g_bar[gtid - 8192] = 0;
    }
}

__global__ void k_nop() {}

// ---------------- the persistent recurrence kernel (512 threads) ----------------
struct SmGates { u64 vp[128][18]; };     // {v(2p), v(2p+1)} pairs; row 144B (16B aligned)
struct SmP2    { float h[4][32]; };
struct SmAttn  {
    float key[8][64];                    // scaled keys
    float sc[8][516];                    // raw scores -> exp(s - gm_chunk) in place
    float gm[8], inv[8], ws[4];
    float sk[4][64];
    float racc[16][4][64];
};
union __align__(16) SmU { SmGates g; SmP2 p2; SmAttn a; };

__global__ __launch_bounds__(NTHR, 1)
void k_steps(const float* __restrict__ x, const float* __restrict__ b_ih,
             const float* __restrict__ b_hh, const float* __restrict__ b_head) {
    __shared__ SmU sm;
    const int bid = blockIdx.x, tid = threadIdx.x;
    const int wrp = tid >> 5, lane = tid & 31;

    // P1 partition: (16 n-chunks of 128) x (8 k-slices of 128)
    const int nc = bid >> 3, ksg = bid & 7;
    const int n0 = nc * 128, k0g = ksg * 128;
    const int c_l = lane & 7, bgrp = lane >> 3;   // warp-distinct cols; 8-batch groups
    const int colP1 = n0 + wrp * 8 + c_l;
    // P2 partition
    const int bq2 = bid >> 4, ks2 = bid & 15;
    const int b02 = bq2 * 4, j0 = ks2 * 32;
    // P3/P4 partition
    const int ab = bid >> 2, mq = bid & 3;
    const int m0 = mq * 512;
    const int hq = lane & 7, msub = lane >> 3;    // attention lane mapping

    for (int t = 0; t < T_; ++t) {
        // ================= P1: gates GEMM (k-split partials) =================
        {
            // build v pair tile vp[k][p] = {v(2p), v(2p+1)}; k fastest for coalescing
            #pragma unroll
            for (int e = 0; e < 4; ++e) {
                int idx = e * 512 + tid;
                int kk = idx & 127, p = idx >> 7;
                int gk = k0g + kk;
                int bb = p * 2;
                float v0, v1;
                if (gk < 256) {
                    v0 = __ldg(&x[(bb * T_ + t) * I_ + gk]);
                    v1 = __ldg(&x[((bb+1) * T_ + t) * I_ + gk]);
                } else if (gk < 512) {
                    if (t == 0) { v0 = 0.f; v1 = 0.f; }
                    else {
                        int r = gk - 256;
                        v0 = __ldcg(&g_read_part[t-1][0][bb][r]) + __ldcg(&g_read_part[t-1][1][bb][r])
                           + __ldcg(&g_read_part[t-1][2][bb][r]) + __ldcg(&g_read_part[t-1][3][bb][r]);
                        v1 = __ldcg(&g_read_part[t-1][0][bb+1][r]) + __ldcg(&g_read_part[t-1][1][bb+1][r])
                           + __ldcg(&g_read_part[t-1][2][bb+1][r]) + __ldcg(&g_read_part[t-1][3][bb+1][r]);
                    }
                } else {
                    v0 = __ldcg(&g_h[bb * H_ + (gk - 512)]);
                    v1 = __ldcg(&g_h[(bb+1) * H_ + (gk - 512)]);
                }
                sm.g.vp[kk][p] = pack2(v0, v1);
            }
            __syncthreads();
            const float* wp = &g_WgT[(size_t)k0g * NG_ + colP1];
            u64 acc[4];
            {
                float bi = 0.f;
                if (ksg == 0) bi = __ldg(&b_ih[colP1]) + __ldg(&b_hh[colP1]);
                u64 bip = pack2(bi, bi);
                acc[0] = bip; acc[1] = bip; acc[2] = bip; acc[3] = bip;
            }
            const int p0 = bgrp * 4;
            #pragma unroll 8
            for (int k = 0; k < 128; ++k) {
                float w = __ldg(wp + (size_t)k * NG_);   // 32B broadcast sector per warp
                u64 w2 = pack2(w, w);
                ulonglong2 va = *(const ulonglong2*)&sm.g.vp[k][p0];
                ulonglong2 vb = *(const ulonglong2*)&sm.g.vp[k][p0 + 2];
                acc[0] = ffma2(va.x, w2, acc[0]);
                acc[1] = ffma2(va.y, w2, acc[1]);
                acc[2] = ffma2(vb.x, w2, acc[2]);
                acc[3] = ffma2(vb.y, w2, acc[3]);
            }
            #pragma unroll
            for (int j = 0; j < 4; ++j) {
                float2 pp = unpack2(acc[j]);
                int b = bgrp * 8 + j * 2;
                g_gates_part[ksg][b][colP1]     = pp.x;
                g_gates_part[ksg][b + 1][colP1] = pp.y;
            }
            __syncthreads();
        }
        gridbar(4*t + 0);

        // ================= P2: LSTM elementwise + partial head GEMM =================
        {
            if (tid < 128) {
                int bi = tid >> 5, jj = tid & 31;
                int b = b02 + bi, j = j0 + jj;
                float gi = 0.f, gf = 0.f, gg = 0.f, go = 0.f;
                #pragma unroll
                for (int p = 0; p < 8; ++p) {
                    gi += __ldcg(&g_gates_part[p][b][j]);
                    gf += __ldcg(&g_gates_part[p][b][512 + j]);
                    gg += __ldcg(&g_gates_part[p][b][1024 + j]);
                    go += __ldcg(&g_gates_part[p][b][1536 + j]);
                }
                float cold = g_c[b * H_ + j];
                float iv = sigm_acc(gi), fv = sigm_acc(gf);
                float gv = tanhf(gg),   ov = sigm_acc(go);
                float cn = fv * cold + iv * gv;
                float hn = ov * tanhf(cn);
                g_c[b * H_ + j] = cn;
                g_h[b * H_ + j] = hn;
                g_hist_h[t][b][j] = hn;
                sm.p2.h[bi][jj] = hn;
            }
            __syncthreads();
            #pragma unroll
            for (int e = 0; e < 2; ++e) {
                int nn = tid + e * 512;
                if (nn < NHP_) {
                    float a0 = 0.f, a1 = 0.f, a2 = 0.f, a3 = 0.f;
                    #pragma unroll
                    for (int k = 0; k < 32; ++k) {
                        float w = __ldcg(&g_WhT[(size_t)(j0 + k) * NHP_ + nn]);
                        a0 += sm.p2.h[0][k] * w;
                        a1 += sm.p2.h[1][k] * w;
                        a2 += sm.p2.h[2][k] * w;
                        a3 += sm.p2.h[3][k] * w;
                    }
                    g_hp_part[ks2][b02 + 0][nn] = a0;
                    g_hp_part[ks2][b02 + 1][nn] = a1;
                    g_hp_part[ks2][b02 + 2][nn] = a2;
                    g_hp_part[ks2][b02 + 3][nn] = a3;
                }
            }
        }
        // Hoist the block-private mem-row load ABOVE the barrier, fully coalesced:
        // warp owns rows {it*64 + wrp*4 + msub}, lane holds floats [hq*4..+4) and [32+hq*4..+4)
        ulonglong2 rows2[8][2];
        #pragma unroll
        for (int it = 0; it < 8; ++it) {
            const float* mp = &g_mem[ab][m0 + it*64 + wrp*4 + msub][0];
            rows2[it][0] = *(const ulonglong2*)(mp + hq * 4);
            rows2[it][1] = *(const ulonglong2*)(mp + 32 + hq * 4);
        }
        gridbar(4*t + 1);

        // ================= P3: keys + scores (register rows + shfl reduce) =================
        {
            {   // key build: 512 entries, 1 per thread
                int key = tid >> 6, h = tid & 63;
                int n = key & 3;
                int p = (key < 4) ? h : 64 + h;
                float v = __ldg(&b_head[n * HPROW_ + p]);
                #pragma unroll
                for (int ps = 0; ps < 16; ++ps) v += __ldcg(&g_hp_part[ps][ab][n * 129 + p]);
                sm.a.key[key][h] = v * 0.125f;
            }
            __syncthreads();
            #pragma unroll
            for (int key = 0; key < 8; ++key) {
                ulonglong2 klo = *(const ulonglong2*)&sm.a.key[key][hq * 4];
                ulonglong2 khi = *(const ulonglong2*)&sm.a.key[key][32 + hq * 4];
                #pragma unroll
                for (int it = 0; it < 8; ++it) {
                    u64 d2 = ffma2(rows2[it][0].x, klo.x, 0ull);
                    d2 = ffma2(rows2[it][0].y, klo.y, d2);
                    d2 = ffma2(rows2[it][1].x, khi.x, d2);
                    d2 = ffma2(rows2[it][1].y, khi.y, d2);
                    float2 pf = unpack2(d2);
                    float p = pf.x + pf.y;
                    p += __shfl_xor_sync(0xffffffffu, p, 1);
                    p += __shfl_xor_sync(0xffffffffu, p, 2);
                    p += __shfl_xor_sync(0xffffffffu, p, 4);
                    if (hq == key) sm.a.sc[key][it*64 + wrp*4 + msub] = p;
                }
            }
            __syncthreads();
            if (wrp < 8) {      // chunk max per key
                float mx = -1e30f;
                for (int i = lane; i < 512; i += 32) mx = fmaxf(mx, sm.a.sc[wrp][i]);
                #pragma unroll
                for (int sh = 16; sh; sh >>= 1) mx = fmaxf(mx, __shfl_xor_sync(0xffffffffu, mx, sh));
                if (lane == 0) sm.a.gm[wrp] = mx;
            }
            __syncthreads();
            #pragma unroll
            for (int key = 0; key < 8; ++key)     // exp in place
                sm.a.sc[key][tid] = __expf(sm.a.sc[key][tid] - sm.a.gm[key]);
            __syncthreads();
            if (wrp < 8) {      // chunk sumexp
                float se = 0.f;
                for (int i = lane; i < 512; i += 32) se += sm.a.sc[wrp][i];
                #pragma unroll
                for (int sh = 16; sh; sh >>= 1) se += __shfl_xor_sync(0xffffffffu, se, sh);
                if (lane == 0) g_stats[ab][wrp][mq] = make_float2(sm.a.gm[wrp], se);
            }
        }
        gridbar(4*t + 2);

        // ================= P4: softmax apply on register rows, read acc, mem update ==========
        {
            if (tid < 8) {
                float2 st0 = __ldcg(&g_stats[ab][tid][0]);
                float2 st1 = __ldcg(&g_stats[ab][tid][1]);
                float2 st2 = __ldcg(&g_stats[ab][tid][2]);
                float2 st3 = __ldcg(&g_stats[ab][tid][3]);
                float gm = fmaxf(fmaxf(st0.x, st1.x), fmaxf(st2.x, st3.x));
                float ssum = st0.y * __expf(st0.x - gm) + st1.y * __expf(st1.x - gm)
                           + st2.y * __expf(st2.x - gm) + st3.y * __expf(st3.x - gm);
                // per-key scale: exp(gm_chunk - gm_global) / ssum  (sc already holds exp-chunk)
                sm.a.inv[tid] = __expf(sm.a.gm[tid] - gm) / ssum;
            } else if (tid < 12) {
                int n = tid - 8;
                float v = __ldg(&b_head[n * HPROW_ + 128]);
                #pragma unroll
                for (int ps = 0; ps < 16; ++ps) v += __ldcg(&g_hp_part[ps][ab][n * 129 + 128]);
                sm.a.ws[n] = sigm_acc(v);
            }
            __syncthreads();
            if (tid < 256) {
                int n = tid >> 6, h = tid & 63;
                float v = __ldg(&b_head[n * HPROW_ + 64 + h]);
                #pragma unroll
                for (int ps = 0; ps < 16; ++ps) v += __ldcg(&g_hp_part[ps][ab][n * 129 + 64 + h]);
                sm.a.sk[n][h] = v * sm.a.ws[n];
            }
            __syncthreads();
            float scl[8];
            #pragma unroll
            for (int key = 0; key < 8; ++key) scl[key] = sm.a.inv[key];

            u64 racc2[4][4];
            #pragma unroll
            for (int n = 0; n < 4; ++n)
                #pragma unroll
                for (int q2 = 0; q2 < 4; ++q2) racc2[n][q2] = 0ull;

            #pragma unroll
            for (int it = 0; it < 8; ++it) {
                const int ml = it*64 + wrp*4 + msub;
                float wv[8];
                #pragma unroll
                for (int n = 0; n < 8; ++n) wv[n] = sm.a.sc[n][ml] * scl[n];
                ulonglong2 rlo = rows2[it][0], rhi = rows2[it][1];
                #pragma unroll
                for (int n = 0; n < 4; ++n) {
                    u64 rw2 = pack2(wv[n], wv[n]);
                    racc2[n][0] = ffma2(rw2, rlo.x, racc2[n][0]);
                    racc2[n][1] = ffma2(rw2, rlo.y, racc2[n][1]);
                    racc2[n][2] = ffma2(rw2, rhi.x, racc2[n][2]);
                    racc2[n][3] = ffma2(rw2, rhi.y, racc2[n][3]);
                }
                #pragma unroll
                for (int n = 0; n < 4; ++n) {
                    u64 ww2 = pack2(wv[4 + n], wv[4 + n]);
                    ulonglong2 slo = *(const ulonglong2*)&sm.a.sk[n][hq * 4];
                    ulonglong2 shi = *(const ulonglong2*)&sm.a.sk[n][32 + hq * 4];
                    rlo.x = ffma2(ww2, slo.x, rlo.x);
                    rlo.y = ffma2(ww2, slo.y, rlo.y);
                    rhi.x = ffma2(ww2, shi.x, rhi.x);
                    rhi.y = ffma2(ww2, shi.y, rhi.y);
                }
                float* mp = &g_mem[ab][m0 + ml][0];
                *(ulonglong2*)(mp + hq * 4) = rlo;
                *(ulonglong2*)(mp + 32 + hq * 4) = rhi;
            }
            // reduce read partials over msub (xor 8, 16)
            #pragma unroll
            for (int n = 0; n < 4; ++n)
                #pragma unroll
                for (int q2 = 0; q2 < 4; ++q2) {
                    racc2[n][q2] = fadd2(racc2[n][q2], __shfl_xor_sync(0xffffffffu, racc2[n][q2], 8));
                    racc2[n][q2] = fadd2(racc2[n][q2], __shfl_xor_sync(0xffffffffu, racc2[n][q2], 16));
                }
            if (lane < 8) {   // msub == 0, hq == lane
                #pragma unroll
                for (int n = 0; n < 4; ++n) {
                    float2 p0 = unpack2(racc2[n][0]);
                    float2 p1 = unpack2(racc2[n][1]);
                    float2 p2 = unpack2(racc2[n][2]);
                    float2 p3 = unpack2(racc2[n][3]);
                    *(float2*)&sm.a.racc[wrp][n][hq*4]          = p0;
                    *(float2*)&sm.a.racc[wrp][n][hq*4 + 2]      = p1;
                    *(float2*)&sm.a.racc[wrp][n][32 + hq*4]     = p2;
                    *(float2*)&sm.a.racc[wrp][n][32 + hq*4 + 2] = p3;
                }
            }
            __syncthreads();
            if (tid < 256) {
                int n = tid >> 6, h = tid & 63;
                float ssum = 0.f;
                #pragma unroll
                for (int wr = 0; wr < 16; ++wr) ssum += sm.a.racc[wr][n][h];
                g_read_part[t][mq][ab][n * 64 + h] = ssum;
            }
        }
        gridbar(4*t + 3);
    }
}

// ---------------- final output GEMM: outputs[b][t][o] ----------------
__global__ void k_out(const float* __restrict__ b_out, float* __restrict__ out) {
    const int m0 = blockIdx.x * 32, nc = blockIdx.y;
    const int tid = threadIdx.x;
    __shared__ float a_sh[32][64];
    const int n_l = tid & 63, mg = tid >> 6;
    const int n = nc * 64 + n_l;
    float acc[8];
    #pragma unroll
    for (int r = 0; r < 8; ++r) acc[r] = 0.f;
    for (int kt = 0; kt < 12; ++kt) {
        __syncthreads();
        #pragma unroll
        for (int e = 0; e < 8; ++e) {
            int lidx = e * 256 + tid;
            int mrow = lidx >> 6, kk = lidx & 63;
            int m = m0 + mrow;
            int ts = m >> 5, bb = m & 31;
            int gk = kt * 64 + kk;
            float v;
            if (gk < 512) v = g_hist_h[ts][bb][gk];
            else {
                int r = gk - 512;
                v = g_read_part[ts][0][bb][r] + g_read_part[ts][1][bb][r]
                  + g_read_part[ts][2][bb][r] + g_read_part[ts][3][bb][r];
            }
            a_sh[mrow][kk] = v;
        }
        __syncthreads();
        #pragma unroll 4
        for (int kk = 0; kk < 64; ++kk) {
            float wv = g_WoT[(kt * 64 + kk) * O_ + n];
            #pragma unroll
            for (int r = 0; r < 8; ++r) acc[r] += a_sh[mg * 8 + r][kk] * wv;
        }
    }
    float bo = b_out[n];
    #pragma unroll
    for (int r = 0; r < 8; ++r) {
        int m = m0 + mg * 8 + r;
        int ts = m >> 5, bb = m & 31;
        out[(bb * T_ + ts) * O_ + n] = acc[r] + bo;
    }
}

// ---------------- final state copy: mem, h, c into d_out ----------------
__global__ void k_final(float* __restrict__ out) {
    const int OUT_N = B_ * T_ * O_;
    const int NMEM  = B_ * MS_ * HS_;
    const int total = NMEM + 2 * B_ * H_;
    for (int i = blockIdx.x * blockDim.x + threadIdx.x; i < total; i += gridDim.x * blockDim.x) {
        if (i < NMEM)                 out[OUT_N + i] = (&g_mem[0][0][0])[i];
        else if (i < NMEM + B_ * H_)  out[OUT_N + i] = g_h[i - NMEM];
        else                          out[OUT_N + i] = g_c[i - NMEM - B_ * H_];
    }
}

extern "C" void kernel_launch(void* const* d_in, const int* in_sizes, int n_in,
                              void* d_out, int out_size) {
    const float* x      = (const float*)d_in[0];
    const float* W_ih   = (const float*)d_in[1];
    const float* W_hh   = (const float*)d_in[2];
    const float* b_ih   = (const float*)d_in[3];
    const float* b_hh   = (const float*)d_in[4];
    const float* W_head = (const float*)d_in[5];
    const float* b_head = (const float*)d_in[6];
    const float* W_out  = (const float*)d_in[7];
    const float* b_out  = (const float*)d_in[8];
    float* out = (float*)d_out;

    k_prep<<<3024, 256>>>(W_ih, W_hh, W_head, W_out);
    k_nop<<<1, 32>>>();
    k_nop<<<1, 32>>>();
    k_steps<<<NBLK, NTHR>>>(x, b_ih, b_hh, b_head);
    k_out<<<dim3(32, 4), 256>>>(b_out, out);
    k_final<<<2048, 256>>>(out);
}

// round 12
// speedup vs baseline: 1.5396x; 1.0752x over previous
#include <cuda_runtime.h>
#include <math.h>

// Problem constants
#define B_  32
#define T_  32
#define I_  256
#define H_  512
#define NH_ 4
#define HS_ 64
#define MS_ 2048
#define O_  256
// derived
#define KG_ 1024
#define NG_ 2048        // 4*H, gate col index n = g*512 + j
#define NHP_ 516
#define HPROW_ 2115
#define NBLK 128
#define NTHR 512
#define NBAR (4*T_)

typedef unsigned long long u64;

__device__ __forceinline__ u64 ffma2(u64 a, u64 b, u64 c) {
    u64 d; asm("fma.rn.f32x2 %0, %1, %2, %3;" : "=l"(d) : "l"(a), "l"(b), "l"(c)); return d;
}
__device__ __forceinline__ u64 fadd2(u64 a, u64 b) {
    u64 d; asm("add.rn.f32x2 %0, %1, %2;" : "=l"(d) : "l"(a), "l"(b)); return d;
}
__device__ __forceinline__ u64 pack2(float lo, float hi) {
    u64 d; asm("mov.b64 %0, {%1, %2};" : "=l"(d) : "f"(lo), "f"(hi)); return d;
}
__device__ __forceinline__ float2 unpack2(u64 v) {
    float2 r; asm("mov.b64 {%0, %1}, %2;" : "=f"(r.x), "=f"(r.y) : "l"(v)); return r;
}

// ---------------- scratch (device globals; no allocation allowed) ----------------
__device__ float g_WgT[KG_*NG_];              // [k][n]  8MB
__device__ float g_WhT[H_*NHP_];              // [k][n*129+p]
__device__ float g_WoT[(H_+NH_*HS_)*O_];      // [k][o]
__device__ float g_h[B_*H_];
__device__ float g_c[B_*H_];
__device__ float g_gates_part[16][B_][NG_];   // k-split (16 slices of 64) partial gates
__device__ float g_hp_part[16][B_][NHP_];
__device__ float2 g_stats[B_][8][4];          // [b][key][mq] = {chunk max, chunk sumexp}
__device__ float g_read_part[T_][4][B_][NH_*HS_];
__device__ float g_hist_h[T_][B_][H_];
__device__ float g_mem[B_][MS_][HS_];         // 16.7MB
__device__ int   g_bar[NBAR];

// fast transcendentals (approx exp/div; errors ~1e-7, contractive in LSTM)
__device__ __forceinline__ float sigm_f(float v) {
    return __fdividef(1.f, 1.f + __expf(-v));
}
__device__ __forceinline__ float tanh_f(float v) {
    float e = __expf(-2.f * v);
    return __fdividef(1.f - e, 1.f + e);
}

// ---------------- grid barrier: release-add + acquire-poll, no L1 flush ----------------
__device__ __forceinline__ void gridbar(int idx) {
    __syncthreads();
    if (threadIdx.x == 0) {
        int* p = &g_bar[idx];
        asm volatile("red.release.gpu.global.add.s32 [%0], 1;" :: "l"(p) : "memory");
        int v;
        do {
            asm volatile("ld.acquire.gpu.global.s32 %0, [%1];" : "=r"(v) : "l"(p) : "memory");
        } while (v < NBLK);
    }
    __syncthreads();
}

// ---------------- fused prep: transposes + zeroing in ONE launch ----------------
__global__ void k_prep(const float* __restrict__ W_ih, const float* __restrict__ W_hh,
                       const float* __restrict__ W_head, const float* __restrict__ W_out) {
    const int b = blockIdx.x;
    const int tid = threadIdx.x;                // 256
    const int tx = tid & 31, ty = tid >> 5;     // (32, 8)
    __shared__ float tile[32][33];
    if (b < 2048) {                             // WgT[k][n]
        int bx = (b & 31) * 32, by = (b >> 5) * 32;
        #pragma unroll
        for (int i = 0; i < 32; i += 8) {
            int row = by + ty + i, k = bx + tx;
            tile[ty + i][tx] = (k < 512) ? W_ih[row*512 + k] : W_hh[row*512 + (k - 512)];
        }
        __syncthreads();
        #pragma unroll
        for (int i = 0; i < 32; i += 8) {
            int k = bx + ty + i, row = by + tx;
            g_WgT[(size_t)k * NG_ + row] = tile[tx][ty + i];
        }
    } else if (b < 2048 + 272) {                // WhT[k][r]
        int bb = b - 2048;
        int bx = (bb & 15) * 32, by = (bb >> 4) * 32;
        #pragma unroll
        for (int i = 0; i < 32; i += 8) {
            int r = by + ty + i, k = bx + tx;
            float v = 0.f;
            if (r < NHP_) {
                int n = r / 129, p = r % 129;
                v = W_head[(size_t)(n * HPROW_ + p) * 512 + k];
            }
            tile[ty + i][tx] = v;
        }
        __syncthreads();
        #pragma unroll
        for (int i = 0; i < 32; i += 8) {
            int k = bx + ty + i, r = by + tx;
            if (r < NHP_) g_WhT[(size_t)k * NHP_ + r] = tile[tx][ty + i];
        }
    } else if (b < 2048 + 272 + 192) {          // WoT[k][o]
        int bb = b - 2320;
        int bx = (bb % 24) * 32, by = (bb / 24) * 32;
        #pragma unroll
        for (int i = 0; i < 32; i += 8) {
            int o = by + ty + i, k = bx + tx;
            tile[ty + i][tx] = W_out[o * (H_ + NH_*HS_) + k];
        }
        __syncthreads();
        #pragma unroll
        for (int i = 0; i < 32; i += 8) {
            int k = bx + ty + i, o = by + tx;
            g_WoT[(size_t)k * O_ + o] = tile[tx][ty + i];
        }
    } else {
        int bb = b - 2512;                      // 0..511
        int gtid = bb * 256 + tid;
        float4 z4 = make_float4(0.f, 0.f, 0.f, 0.f);
        #pragma unroll
        for (int i = 0; i < 8; ++i)
            ((float4*)g_mem)[gtid + i * 131072] = z4;
        if (gtid < 4096)            ((float4*)g_h)[gtid] = z4;
        else if (gtid < 8192)       ((float4*)g_c)[gtid - 4096] = z4;
        else if (gtid < 8192+NBAR)  g_bar[gtid - 8192] = 0;
    }
}

__global__ void k_nop() {}

// ---------------- the persistent recurrence kernel (512 threads) ----------------
struct SmGates { u64 vp[128][18]; };     // {v(2p), v(2p+1)} pairs; row 144B
struct SmP2    { float h[4][32]; };
struct SmAttn  {
    float key[8][64];
    float sc[8][516];                    // raw scores -> exp(s - gm_chunk) in place
    float gm[8], inv[8], ws[4];
    float sk[4][64];
    float racc[16][4][64];
};
union __align__(16) SmU { SmGates g; SmP2 p2; SmAttn a; };

__global__ __launch_bounds__(NTHR, 1)
void k_steps(const float* __restrict__ x, const float* __restrict__ b_ih,
             const float* __restrict__ b_hh, const float* __restrict__ b_head) {
    __shared__ SmU sm;
    const int bid = blockIdx.x, tid = threadIdx.x;
    const int wrp = tid >> 5, lane = tid & 31;

    // P1 partition: (16 n-chunks of 128) x (8 k-slices of 128); warp k-halves
    const int nc = bid >> 3, ksg = bid & 7;
    const int n0 = nc * 128, k0g = ksg * 128;
    const int khalf = wrp >> 3, colgrp = wrp & 7;
    const int c_l = lane & 7, bgrp = lane >> 3;
    const int col0 = n0 + colgrp * 16 + c_l * 2;
    const int kbase = khalf * 64;
    const int sliceP1 = ksg * 2 + khalf;
    // P2 partition
    const int bq2 = bid >> 4, ks2 = bid & 15;
    const int b02 = bq2 * 4, j0 = ks2 * 32;
    // P3/P4 partition
    const int ab = bid >> 2, mq = bid & 3;
    const int m0 = mq * 512;
    const int hq = lane & 7, msub = lane >> 3;

    for (int t = 0; t < T_; ++t) {
        // ================= P1: gates GEMM (16 k-slice partials) =================
        {
            // build v pair tile vp[k][p] = {v(2p), v(2p+1)}
            #pragma unroll
            for (int e = 0; e < 4; ++e) {
                int idx = e * 512 + tid;
                int kk = idx & 127, p = idx >> 7;
                int gk = k0g + kk;
                int bb = p * 2;
                float v0, v1;
                if (gk < 256) {
                    v0 = __ldg(&x[(bb * T_ + t) * I_ + gk]);
                    v1 = __ldg(&x[((bb+1) * T_ + t) * I_ + gk]);
                } else if (gk < 512) {
                    if (t == 0) { v0 = 0.f; v1 = 0.f; }
                    else {
                        int r = gk - 256;
                        v0 = __ldcg(&g_read_part[t-1][0][bb][r]) + __ldcg(&g_read_part[t-1][1][bb][r])
                           + __ldcg(&g_read_part[t-1][2][bb][r]) + __ldcg(&g_read_part[t-1][3][bb][r]);
                        v1 = __ldcg(&g_read_part[t-1][0][bb+1][r]) + __ldcg(&g_read_part[t-1][1][bb+1][r])
                           + __ldcg(&g_read_part[t-1][2][bb+1][r]) + __ldcg(&g_read_part[t-1][3][bb+1][r]);
                    }
                } else {
                    v0 = __ldcg(&g_h[bb * H_ + (gk - 512)]);
                    v1 = __ldcg(&g_h[(bb+1) * H_ + (gk - 512)]);
                }
                sm.g.vp[kk][p] = pack2(v0, v1);
            }
            __syncthreads();
            u64 acc[2][4];
            {
                u64 b0p = 0ull, b1p = 0ull;
                if (sliceP1 == 0) {
                    float bi0 = __ldg(&b_ih[col0])   + __ldg(&b_hh[col0]);
                    float bi1 = __ldg(&b_ih[col0+1]) + __ldg(&b_hh[col0+1]);
                    b0p = pack2(bi0, bi0); b1p = pack2(bi1, bi1);
                }
                #pragma unroll
                for (int p = 0; p < 4; ++p) { acc[0][p] = b0p; acc[1][p] = b1p; }
            }
            const float2* wp2 = (const float2*)&g_WgT[(size_t)(k0g + kbase) * NG_ + col0];
            const int p0 = bgrp * 4;
            #pragma unroll 8
            for (int kk = 0; kk < 64; ++kk) {
                float2 w = __ldg(wp2 + (size_t)kk * (NG_/2));
                u64 w20 = pack2(w.x, w.x);
                u64 w21 = pack2(w.y, w.y);
                ulonglong2 va = *(const ulonglong2*)&sm.g.vp[kbase + kk][p0];
                ulonglong2 vb = *(const ulonglong2*)&sm.g.vp[kbase + kk][p0 + 2];
                acc[0][0] = ffma2(va.x, w20, acc[0][0]);
                acc[0][1] = ffma2(va.y, w20, acc[0][1]);
                acc[0][2] = ffma2(vb.x, w20, acc[0][2]);
                acc[0][3] = ffma2(vb.y, w20, acc[0][3]);
                acc[1][0] = ffma2(va.x, w21, acc[1][0]);
                acc[1][1] = ffma2(va.y, w21, acc[1][1]);
                acc[1][2] = ffma2(vb.x, w21, acc[1][2]);
                acc[1][3] = ffma2(vb.y, w21, acc[1][3]);
            }
            #pragma unroll
            for (int p = 0; p < 4; ++p) {
                float2 c0 = unpack2(acc[0][p]);
                float2 c1 = unpack2(acc[1][p]);
                int b = bgrp * 8 + p * 2;
                *(float2*)&g_gates_part[sliceP1][b][col0]     = make_float2(c0.x, c1.x);
                *(float2*)&g_gates_part[sliceP1][b + 1][col0] = make_float2(c0.y, c1.y);
            }
            __syncthreads();
        }
        gridbar(4*t + 0);

        // ================= P2: LSTM (quad-spread) + partial head GEMM =================
        {
            {
                const int cell = tid >> 2, q = tid & 3;
                const int bi = cell >> 5, jj = cell & 31;
                const int b = b02 + bi, j = j0 + jj;
                float gs0 = 0.f, gs1 = 0.f, gs2 = 0.f, gs3 = 0.f;
                #pragma unroll
                for (int e = 0; e < 4; ++e) {
                    int s = q * 4 + e;
                    gs0 += __ldcg(&g_gates_part[s][b][j]);
                    gs1 += __ldcg(&g_gates_part[s][b][512 + j]);
                    gs2 += __ldcg(&g_gates_part[s][b][1024 + j]);
                    gs3 += __ldcg(&g_gates_part[s][b][1536 + j]);
                }
                gs0 += __shfl_xor_sync(0xffffffffu, gs0, 1);
                gs1 += __shfl_xor_sync(0xffffffffu, gs1, 1);
                gs2 += __shfl_xor_sync(0xffffffffu, gs2, 1);
                gs3 += __shfl_xor_sync(0xffffffffu, gs3, 1);
                gs0 += __shfl_xor_sync(0xffffffffu, gs0, 2);
                gs1 += __shfl_xor_sync(0xffffffffu, gs1, 2);
                gs2 += __shfl_xor_sync(0xffffffffu, gs2, 2);
                gs3 += __shfl_xor_sync(0xffffffffu, gs3, 2);
                if (q == 0) {
                    float cold = g_c[b * H_ + j];
                    float iv = sigm_f(gs0), fv = sigm_f(gs1);
                    float gv = tanh_f(gs2), ov = sigm_f(gs3);
                    float cn = fv * cold + iv * gv;
                    float hn = ov * tanh_f(cn);
                    g_c[b * H_ + j] = cn;
                    g_h[b * H_ + j] = hn;
                    g_hist_h[t][b][j] = hn;
                    sm.p2.h[bi][jj] = hn;
                }
            }
            __syncthreads();
            #pragma unroll
            for (int e = 0; e < 2; ++e) {
                int nn = tid + e * 512;
                if (nn < NHP_) {
                    float a0 = 0.f, a1 = 0.f, a2 = 0.f, a3 = 0.f;
                    #pragma unroll
                    for (int k = 0; k < 32; ++k) {
                        float w = __ldcg(&g_WhT[(size_t)(j0 + k) * NHP_ + nn]);
                        a0 += sm.p2.h[0][k] * w;
                        a1 += sm.p2.h[1][k] * w;
                        a2 += sm.p2.h[2][k] * w;
                        a3 += sm.p2.h[3][k] * w;
                    }
                    g_hp_part[ks2][b02 + 0][nn] = a0;
                    g_hp_part[ks2][b02 + 1][nn] = a1;
                    g_hp_part[ks2][b02 + 2][nn] = a2;
                    g_hp_part[ks2][b02 + 3][nn] = a3;
                }
            }
        }
        // hoist block-private mem-row loads above the barrier (coalesced)
        ulonglong2 rows2[8][2];
        #pragma unroll
        for (int it = 0; it < 8; ++it) {
            const float* mp = &g_mem[ab][m0 + it*64 + wrp*4 + msub][0];
            rows2[it][0] = *(const ulonglong2*)(mp + hq * 4);
            rows2[it][1] = *(const ulonglong2*)(mp + 32 + hq * 4);
        }
        gridbar(4*t + 1);

        // ================= P3: keys + scores (butterfly multi-key reduce) =================
        {
            {   // key build: 512 entries, 1 per thread
                int key = tid >> 6, h = tid & 63;
                int n = key & 3;
                int p = (key < 4) ? h : 64 + h;
                float v = __ldg(&b_head[n * HPROW_ + p]);
                #pragma unroll
                for (int ps = 0; ps < 16; ++ps) v += __ldcg(&g_hp_part[ps][ab][n * 129 + p]);
                sm.a.key[key][h] = v * 0.125f;
            }
            __syncthreads();
            #pragma unroll
            for (int it = 0; it < 8; ++it) {
                float pv[8];
                #pragma unroll
                for (int key = 0; key < 8; ++key) {
                    ulonglong2 klo = *(const ulonglong2*)&sm.a.key[key][hq * 4];
                    ulonglong2 khi = *(const ulonglong2*)&sm.a.key[key][32 + hq * 4];
                    u64 d2 = ffma2(rows2[it][0].x, klo.x, 0ull);
                    d2 = ffma2(rows2[it][0].y, klo.y, d2);
                    d2 = ffma2(rows2[it][1].x, khi.x, d2);
                    d2 = ffma2(rows2[it][1].y, khi.y, d2);
                    float2 pf = unpack2(d2);
                    pv[key] = pf.x + pf.y;
                }
                // multi-key butterfly: lane (hq) ends with total for key == hq
                float q4[4];
                #pragma unroll
                for (int k2 = 0; k2 < 4; ++k2) {
                    float send = (hq & 1) ? pv[2*k2] : pv[2*k2+1];
                    float recv = __shfl_xor_sync(0xffffffffu, send, 1);
                    float keepv = (hq & 1) ? pv[2*k2+1] : pv[2*k2];
                    q4[k2] = keepv + recv;
                }
                float r2v[2];
                #pragma unroll
                for (int k2 = 0; k2 < 2; ++k2) {
                    float send = (hq & 2) ? q4[2*k2] : q4[2*k2+1];
                    float recv = __shfl_xor_sync(0xffffffffu, send, 2);
                    float keepv = (hq & 2) ? q4[2*k2+1] : q4[2*k2];
                    r2v[k2] = keepv + recv;
                }
                {
                    float send = (hq & 4) ? r2v[0] : r2v[1];
                    float recv = __shfl_xor_sync(0xffffffffu, send, 4);
                    float keepv = (hq & 4) ? r2v[1] : r2v[0];
                    sm.a.sc[hq][it*64 + wrp*4 + msub] = keepv + recv;
                }
            }
            __syncthreads();
            if (wrp < 8) {      // chunk max per key
                float mx = -1e30f;
                for (int i = lane; i < 512; i += 32) mx = fmaxf(mx, sm.a.sc[wrp][i]);
                #pragma unroll
                for (int sh = 16; sh; sh >>= 1) mx = fmaxf(mx, __shfl_xor_sync(0xffffffffu, mx, sh));
                if (lane == 0) sm.a.gm[wrp] = mx;
            }
            __syncthreads();
            #pragma unroll
            for (int key = 0; key < 8; ++key)     // exp in place
                sm.a.sc[key][tid] = __expf(sm.a.sc[key][tid] - sm.a.gm[key]);
            __syncthreads();
            if (wrp < 8) {      // chunk sumexp
                float se = 0.f;
                for (int i = lane; i < 512; i += 32) se += sm.a.sc[wrp][i];
                #pragma unroll
                for (int sh = 16; sh; sh >>= 1) se += __shfl_xor_sync(0xffffffffu, se, sh);
                if (lane == 0) g_stats[ab][wrp][mq] = make_float2(sm.a.gm[wrp], se);
            }
        }
        gridbar(4*t + 2);

        // ================= P4: softmax apply on register rows, read acc, mem update ==========
        {
            if (tid < 8) {
                float2 st0 = __ldcg(&g_stats[ab][tid][0]);
                float2 st1 = __ldcg(&g_stats[ab][tid][1]);
                float2 st2 = __ldcg(&g_stats[ab][tid][2]);
                float2 st3 = __ldcg(&g_stats[ab][tid][3]);
                float gm = fmaxf(fmaxf(st0.x, st1.x), fmaxf(st2.x, st3.x));
                float ssum = st0.y * __expf(st0.x - gm) + st1.y * __expf(st1.x - gm)
                           + st2.y * __expf(st2.x - gm) + st3.y * __expf(st3.x - gm);
                sm.a.inv[tid] = __expf(sm.a.gm[tid] - gm) / ssum;
            } else if (tid < 12) {
                int n = tid - 8;
                float v = __ldg(&b_head[n * HPROW_ + 128]);
                #pragma unroll
                for (int ps = 0; ps < 16; ++ps) v += __ldcg(&g_hp_part[ps][ab][n * 129 + 128]);
                sm.a.ws[n] = sigm_f(v);
            }
            __syncthreads();
            if (tid < 256) {
                int n = tid >> 6, h = tid & 63;
                float v = __ldg(&b_head[n * HPROW_ + 64 + h]);
                #pragma unroll
                for (int ps = 0; ps < 16; ++ps) v += __ldcg(&g_hp_part[ps][ab][n * 129 + 64 + h]);
                sm.a.sk[n][h] = v * sm.a.ws[n];
            }
            __syncthreads();
            float scl[8];
            #pragma unroll
            for (int key = 0; key < 8; ++key) scl[key] = sm.a.inv[key];

            u64 racc2[4][4];
            #pragma unroll
            for (int n = 0; n < 4; ++n)
                #pragma unroll
                for (int q2 = 0; q2 < 4; ++q2) racc2[n][q2] = 0ull;

            #pragma unroll
            for (int it = 0; it < 8; ++it) {
                const int ml = it*64 + wrp*4 + msub;
                float wv[8];
                #pragma unroll
                for (int n = 0; n < 8; ++n) wv[n] = sm.a.sc[n][ml] * scl[n];
                ulonglong2 rlo = rows2[it][0], rhi = rows2[it][1];
                #pragma unroll
                for (int n = 0; n < 4; ++n) {
                    u64 rw2 = pack2(wv[n], wv[n]);
                    racc2[n][0] = ffma2(rw2, rlo.x, racc2[n][0]);
                    racc2[n][1] = ffma2(rw2, rlo.y, racc2[n][1]);
                    racc2[n][2] = ffma2(rw2, rhi.x, racc2[n][2]);
                    racc2[n][3] = ffma2(rw2, rhi.y, racc2[n][3]);
                }
                #pragma unroll
                for (int n = 0; n < 4; ++n) {
                    u64 ww2 = pack2(wv[4 + n], wv[4 + n]);
                    ulonglong2 slo = *(const ulonglong2*)&sm.a.sk[n][hq * 4];
                    ulonglong2 shi = *(const ulonglong2*)&sm.a.sk[n][32 + hq * 4];
                    rlo.x = ffma2(ww2, slo.x, rlo.x);
                    rlo.y = ffma2(ww2, slo.y, rlo.y);
                    rhi.x = ffma2(ww2, shi.x, rhi.x);
                    rhi.y = ffma2(ww2, shi.y, rhi.y);
                }
                float* mp = &g_mem[ab][m0 + ml][0];
                *(ulonglong2*)(mp + hq * 4) = rlo;
                *(ulonglong2*)(mp + 32 + hq * 4) = rhi;
            }
            // reduce read partials over msub (xor 8, 16)
            #pragma unroll
            for (int n = 0; n < 4; ++n)
                #pragma unroll
                for (int q2 = 0; q2 < 4; ++q2) {
                    racc2[n][q2] = fadd2(racc2[n][q2], __shfl_xor_sync(0xffffffffu, racc2[n][q2], 8));
                    racc2[n][q2] = fadd2(racc2[n][q2], __shfl_xor_sync(0xffffffffu, racc2[n][q2], 16));
                }
            if (lane < 8) {   // msub == 0, hq == lane
                #pragma unroll
                for (int n = 0; n < 4; ++n) {
                    float2 p0 = unpack2(racc2[n][0]);
                    float2 p1 = unpack2(racc2[n][1]);
                    float2 p2 = unpack2(racc2[n][2]);
                    float2 p3 = unpack2(racc2[n][3]);
                    *(float2*)&sm.a.racc[wrp][n][hq*4]          = p0;
                    *(float2*)&sm.a.racc[wrp][n][hq*4 + 2]      = p1;
                    *(float2*)&sm.a.racc[wrp][n][32 + hq*4]     = p2;
                    *(float2*)&sm.a.racc[wrp][n][32 + hq*4 + 2] = p3;
                }
            }
            __syncthreads();
            if (tid < 256) {
                int n = tid >> 6, h = tid & 63;
                float ssum = 0.f;
                #pragma unroll
                for (int wr = 0; wr < 16; ++wr) ssum += sm.a.racc[wr][n][h];
                g_read_part[t][mq][ab][n * 64 + h] = ssum;
            }
        }
        gridbar(4*t + 3);
    }
}

// ---------------- final output GEMM: outputs[b][t][o] ----------------
__global__ void k_out(const float* __restrict__ b_out, float* __restrict__ out) {
    const int m0 = blockIdx.x * 32, nc = blockIdx.y;
    const int tid = threadIdx.x;
    __shared__ float a_sh[32][64];
    const int n_l = tid & 63, mg = tid >> 6;
    const int n = nc * 64 + n_l;
    float acc[8];
    #pragma unroll
    for (int r = 0; r < 8; ++r) acc[r] = 0.f;
    for (int kt = 0; kt < 12; ++kt) {
        __syncthreads();
        #pragma unroll
        for (int e = 0; e < 8; ++e) {
            int lidx = e * 256 + tid;
            int mrow = lidx >> 6, kk = lidx & 63;
            int m = m0 + mrow;
            int ts = m >> 5, bb = m & 31;
            int gk = kt * 64 + kk;
            float v;
            if (gk < 512) v = g_hist_h[ts][bb][gk];
            else {
                int r = gk - 512;
                v = g_read_part[ts][0][bb][r] + g_read_part[ts][1][bb][r]
                  + g_read_part[ts][2][bb][r] + g_read_part[ts][3][bb][r];
            }
            a_sh[mrow][kk] = v;
        }
        __syncthreads();
        #pragma unroll 4
        for (int kk = 0; kk < 64; ++kk) {
            float wv = g_WoT[(kt * 64 + kk) * O_ + n];
            #pragma unroll
            for (int r = 0; r < 8; ++r) acc[r] += a_sh[mg * 8 + r][kk] * wv;
        }
    }
    float bo = b_out[n];
    #pragma unroll
    for (int r = 0; r < 8; ++r) {
        int m = m0 + mg * 8 + r;
        int ts = m >> 5, bb = m & 31;
        out[(bb * T_ + ts) * O_ + n] = acc[r] + bo;
    }
}

// ---------------- final state copy: mem, h, c into d_out ----------------
__global__ void k_final(float* __restrict__ out) {
    const int OUT_N = B_ * T_ * O_;
    const int NMEM  = B_ * MS_ * HS_;
    const int total = NMEM + 2 * B_ * H_;
    for (int i = blockIdx.x * blockDim.x + threadIdx.x; i < total; i += gridDim.x * blockDim.x) {
        if (i < NMEM)                 out[OUT_N + i] = (&g_mem[0][0][0])[i];
        else if (i < NMEM + B_ * H_)  out[OUT_N + i] = g_h[i - NMEM];
        else                          out[OUT_N + i] = g_c[i - NMEM - B_ * H_];
    }
}

extern "C" void kernel_launch(void* const* d_in, const int* in_sizes, int n_in,
                              void* d_out, int out_size) {
    const float* x      = (const float*)d_in[0];
    const float* W_ih   = (const float*)d_in[1];
    const float* W_hh   = (const float*)d_in[2];
    const float* b_ih   = (const float*)d_in[3];
    const float* b_hh   = (const float*)d_in[4];
    const float* W_head = (const float*)d_in[5];
    const float* b_head = (const float*)d_in[6];
    const float* W_out  = (const float*)d_in[7];
    const float* b_out  = (const float*)d_in[8];
    float* out = (float*)d_out;

    k_prep<<<3024, 256>>>(W_ih, W_hh, W_head, W_out);
    k_nop<<<1, 32>>>();
    k_nop<<<1, 32>>>();
    k_steps<<<NBLK, NTHR>>>(x, b_ih, b_hh, b_head);
    k_out<<<dim3(32, 4), 256>>>(b_out, out);
    k_final<<<2048, 256>>>(out);
}

// round 13
// speedup vs baseline: 1.5669x; 1.0178x over previous
#include <cuda_runtime.h>
#include <math.h>

// Problem constants
#define B_  32
#define T_  32
#define I_  256
#define H_  512
#define NH_ 4
#define HS_ 64
#define MS_ 2048
#define O_  256
// derived
#define KG_ 1024
#define NG_ 2048        // 4*H, gate col index n = g*512 + j
#define NHP_ 516
#define HPROW_ 2115
#define NBLK 128
#define NTHR 512
#define NBARG (2*T_)    // global barriers (2 per step)

typedef unsigned long long u64;

__device__ __forceinline__ u64 ffma2(u64 a, u64 b, u64 c) {
    u64 d; asm("fma.rn.f32x2 %0, %1, %2, %3;" : "=l"(d) : "l"(a), "l"(b), "l"(c)); return d;
}
__device__ __forceinline__ u64 fadd2(u64 a, u64 b) {
    u64 d; asm("add.rn.f32x2 %0, %1, %2;" : "=l"(d) : "l"(a), "l"(b)); return d;
}
__device__ __forceinline__ u64 pack2(float lo, float hi) {
    u64 d; asm("mov.b64 %0, {%1, %2};" : "=l"(d) : "f"(lo), "f"(hi)); return d;
}
__device__ __forceinline__ float2 unpack2(u64 v) {
    float2 r; asm("mov.b64 {%0, %1}, %2;" : "=f"(r.x), "=f"(r.y) : "l"(v)); return r;
}

// ---------------- scratch (device globals; no allocation allowed) ----------------
__device__ float g_WgT[KG_*NG_];              // [k][n]  8MB
__device__ float g_WhT[H_*NHP_];              // [k][n*129+p]
__device__ float g_WoT[(H_+NH_*HS_)*O_];      // [k][o]
__device__ float g_h[B_*H_];
__device__ float g_c[B_*H_];
__device__ float g_gates_part[16][B_][NG_];   // k-split (16 slices of 64) partial gates
__device__ float g_hp_part[16][B_][NHP_];
__device__ float2 g_stats[B_][8][4];          // [b][key][mq] = {chunk max, chunk sumexp}
__device__ float g_read_part[T_][4][B_][NH_*HS_];
__device__ float g_hist_h[T_][B_][H_];
__device__ float g_mem[B_][MS_][HS_];         // 16.7MB
__device__ int   g_bar[NBARG];                // global barrier counters
__device__ int   g_barG[T_][48];              // per-step: [0..7]=16-groups, [8..39]=4-groups

// fast transcendentals (approx exp/div; errors ~1e-7, contractive in LSTM)
__device__ __forceinline__ float sigm_f(float v) {
    return __fdividef(1.f, 1.f + __expf(-v));
}
__device__ __forceinline__ float tanh_f(float v) {
    float e = __expf(-2.f * v);
    return __fdividef(1.f - e, 1.f + e);
}

// ---------------- barriers: release-add + acquire-poll, no L1 flush ----------------
__device__ __forceinline__ void barwait(int* p, int cnt) {
    __syncthreads();
    if (threadIdx.x == 0) {
        asm volatile("red.release.gpu.global.add.s32 [%0], 1;" :: "l"(p) : "memory");
        int v;
        do {
            asm volatile("ld.acquire.gpu.global.s32 %0, [%1];" : "=r"(v) : "l"(p) : "memory");
        } while (v < cnt);
    }
    __syncthreads();
}

// ---------------- fused prep: transposes + zeroing in ONE launch ----------------
__global__ void k_prep(const float* __restrict__ W_ih, const float* __restrict__ W_hh,
                       const float* __restrict__ W_head, const float* __restrict__ W_out) {
    const int b = blockIdx.x;
    const int tid = threadIdx.x;                // 256
    const int tx = tid & 31, ty = tid >> 5;     // (32, 8)
    __shared__ float tile[32][33];
    if (b < 2048) {                             // WgT[k][n]
        int bx = (b & 31) * 32, by = (b >> 5) * 32;
        #pragma unroll
        for (int i = 0; i < 32; i += 8) {
            int row = by + ty + i, k = bx + tx;
            tile[ty + i][tx] = (k < 512) ? W_ih[row*512 + k] : W_hh[row*512 + (k - 512)];
        }
        __syncthreads();
        #pragma unroll
        for (int i = 0; i < 32; i += 8) {
            int k = bx + ty + i, row = by + tx;
            g_WgT[(size_t)k * NG_ + row] = tile[tx][ty + i];
        }
    } else if (b < 2048 + 272) {                // WhT[k][r]
        int bb = b - 2048;
        int bx = (bb & 15) * 32, by = (bb >> 4) * 32;
        #pragma unroll
        for (int i = 0; i < 32; i += 8) {
            int r = by + ty + i, k = bx + tx;
            float v = 0.f;
            if (r < NHP_) {
                int n = r / 129, p = r % 129;
                v = W_head[(size_t)(n * HPROW_ + p) * 512 + k];
            }
            tile[ty + i][tx] = v;
        }
        __syncthreads();
        #pragma unroll
        for (int i = 0; i < 32; i += 8) {
            int k = bx + ty + i, r = by + tx;
            if (r < NHP_) g_WhT[(size_t)k * NHP_ + r] = tile[tx][ty + i];
        }
    } else if (b < 2048 + 272 + 192) {          // WoT[k][o]
        int bb = b - 2320;
        int bx = (bb % 24) * 32, by = (bb / 24) * 32;
        #pragma unroll
        for (int i = 0; i < 32; i += 8) {
            int o = by + ty + i, k = bx + tx;
            tile[ty + i][tx] = W_out[o * (H_ + NH_*HS_) + k];
        }
        __syncthreads();
        #pragma unroll
        for (int i = 0; i < 32; i += 8) {
            int k = bx + ty + i, o = by + tx;
            g_WoT[(size_t)k * O_ + o] = tile[tx][ty + i];
        }
    } else {
        int bb = b - 2512;                      // 0..511
        int gtid = bb * 256 + tid;
        float4 z4 = make_float4(0.f, 0.f, 0.f, 0.f);
        #pragma unroll
        for (int i = 0; i < 8; ++i)
            ((float4*)g_mem)[gtid + i * 131072] = z4;
        if (gtid < 4096)                  ((float4*)g_h)[gtid] = z4;
        else if (gtid < 8192)             ((float4*)g_c)[gtid - 4096] = z4;
        else if (gtid < 8192 + NBARG)     g_bar[gtid - 8192] = 0;
        else if (gtid < 8192 + NBARG + T_*48)
            (&g_barG[0][0])[gtid - 8192 - NBARG] = 0;
    }
}

__global__ void k_nop() {}

// ---------------- the persistent recurrence kernel (512 threads) ----------------
struct SmGates { u64 vp[128][18]; };     // {v(2p), v(2p+1)} pairs; row 144B
struct SmP2    { float h[4][32]; };
struct SmAttn  {
    float key[8][64];
    float sc[8][516];                    // raw scores -> exp(s - gm_chunk) in place
    float gm[8], inv[8], ws[4];
    float sk[4][64];
    float racc[16][4][64];
};
union __align__(16) SmU { SmGates g; SmP2 p2; SmAttn a; };

__global__ __launch_bounds__(NTHR, 1)
void k_steps(const float* __restrict__ x, const float* __restrict__ b_ih,
             const float* __restrict__ b_hh, const float* __restrict__ b_head) {
    __shared__ SmU sm;
    const int bid = blockIdx.x, tid = threadIdx.x;
    const int wrp = tid >> 5, lane = tid & 31;

    // P1 partition: (16 n-chunks of 128) x (8 k-slices of 128); warp k-halves
    const int nc = bid >> 3, ksg = bid & 7;
    const int n0 = nc * 128, k0g = ksg * 128;
    const int khalf = wrp >> 3, colgrp = wrp & 7;
    const int c_l = lane & 7, bgrp = lane >> 3;
    const int col0 = n0 + colgrp * 16 + c_l * 2;
    const int kbase = khalf * 64;
    const int sliceP1 = ksg * 2 + khalf;
    // P2 partition
    const int bq2 = bid >> 4, ks2 = bid & 15;
    const int b02 = bq2 * 4, j0 = ks2 * 32;
    // P3/P4 partition
    const int ab = bid >> 2, mq = bid & 3;
    const int m0 = mq * 512;
    const int hq = lane & 7, msub = lane >> 3;

    for (int t = 0; t < T_; ++t) {
        // ================= P1: gates GEMM (16 k-slice partials) =================
        {
            // build v pair tile vp[k][p] = {v(2p), v(2p+1)}
            #pragma unroll
            for (int e = 0; e < 4; ++e) {
                int idx = e * 512 + tid;
                int kk = idx & 127, p = idx >> 7;
                int gk = k0g + kk;
                int bb = p * 2;
                float v0, v1;
                if (gk < 256) {
                    v0 = __ldg(&x[(bb * T_ + t) * I_ + gk]);
                    v1 = __ldg(&x[((bb+1) * T_ + t) * I_ + gk]);
                } else if (gk < 512) {
                    if (t == 0) { v0 = 0.f; v1 = 0.f; }
                    else {
                        int r = gk - 256;
                        v0 = __ldcg(&g_read_part[t-1][0][bb][r]) + __ldcg(&g_read_part[t-1][1][bb][r])
                           + __ldcg(&g_read_part[t-1][2][bb][r]) + __ldcg(&g_read_part[t-1][3][bb][r]);
                        v1 = __ldcg(&g_read_part[t-1][0][bb+1][r]) + __ldcg(&g_read_part[t-1][1][bb+1][r])
                           + __ldcg(&g_read_part[t-1][2][bb+1][r]) + __ldcg(&g_read_part[t-1][3][bb+1][r]);
                    }
                } else {
                    v0 = __ldcg(&g_h[bb * H_ + (gk - 512)]);
                    v1 = __ldcg(&g_h[(bb+1) * H_ + (gk - 512)]);
                }
                sm.g.vp[kk][p] = pack2(v0, v1);
            }
            __syncthreads();
            u64 acc[2][4];
            {
                u64 b0p = 0ull, b1p = 0ull;
                if (sliceP1 == 0) {
                    float bi0 = __ldg(&b_ih[col0])   + __ldg(&b_hh[col0]);
                    float bi1 = __ldg(&b_ih[col0+1]) + __ldg(&b_hh[col0+1]);
                    b0p = pack2(bi0, bi0); b1p = pack2(bi1, bi1);
                }
                #pragma unroll
                for (int p = 0; p < 4; ++p) { acc[0][p] = b0p; acc[1][p] = b1p; }
            }
            const float2* wp2 = (const float2*)&g_WgT[(size_t)(k0g + kbase) * NG_ + col0];
            const int p0 = bgrp * 4;
            #pragma unroll 8
            for (int kk = 0; kk < 64; ++kk) {
                float2 w = __ldg(wp2 + (size_t)kk * (NG_/2));
                u64 w20 = pack2(w.x, w.x);
                u64 w21 = pack2(w.y, w.y);
                ulonglong2 va = *(const ulonglong2*)&sm.g.vp[kbase + kk][p0];
                ulonglong2 vb = *(const ulonglong2*)&sm.g.vp[kbase + kk][p0 + 2];
                acc[0][0] = ffma2(va.x, w20, acc[0][0]);
                acc[0][1] = ffma2(va.y, w20, acc[0][1]);
                acc[0][2] = ffma2(vb.x, w20, acc[0][2]);
                acc[0][3] = ffma2(vb.y, w20, acc[0][3]);
                acc[1][0] = ffma2(va.x, w21, acc[1][0]);
                acc[1][1] = ffma2(va.y, w21, acc[1][1]);
                acc[1][2] = ffma2(vb.x, w21, acc[1][2]);
                acc[1][3] = ffma2(vb.y, w21, acc[1][3]);
            }
            #pragma unroll
            for (int p = 0; p < 4; ++p) {
                float2 c0 = unpack2(acc[0][p]);
                float2 c1 = unpack2(acc[1][p]);
                int b = bgrp * 8 + p * 2;
                *(float2*)&g_gates_part[sliceP1][b][col0]     = make_float2(c0.x, c1.x);
                *(float2*)&g_gates_part[sliceP1][b + 1][col0] = make_float2(c0.y, c1.y);
            }
            __syncthreads();
        }
        barwait(&g_bar[2*t + 0], NBLK * 1);     // global: P1 -> P2 (scattered writers)

        // ================= P2: LSTM (quad-spread) + partial head GEMM =================
        {
            {
                const int cell = tid >> 2, q = tid & 3;
                const int bi = cell >> 5, jj = cell & 31;
                const int b = b02 + bi, j = j0 + jj;
                float gs0 = 0.f, gs1 = 0.f, gs2 = 0.f, gs3 = 0.f;
                #pragma unroll
                for (int e = 0; e < 4; ++e) {
                    int s = q * 4 + e;
                    gs0 += __ldcg(&g_gates_part[s][b][j]);
                    gs1 += __ldcg(&g_gates_part[s][b][512 + j]);
                    gs2 += __ldcg(&g_gates_part[s][b][1024 + j]);
                    gs3 += __ldcg(&g_gates_part[s][b][1536 + j]);
                }
                gs0 += __shfl_xor_sync(0xffffffffu, gs0, 1);
                gs1 += __shfl_xor_sync(0xffffffffu, gs1, 1);
                gs2 += __shfl_xor_sync(0xffffffffu, gs2, 1);
                gs3 += __shfl_xor_sync(0xffffffffu, gs3, 1);
                gs0 += __shfl_xor_sync(0xffffffffu, gs0, 2);
                gs1 += __shfl_xor_sync(0xffffffffu, gs1, 2);
                gs2 += __shfl_xor_sync(0xffffffffu, gs2, 2);
                gs3 += __shfl_xor_sync(0xffffffffu, gs3, 2);
                if (q == 0) {
                    float cold = g_c[b * H_ + j];
                    float iv = sigm_f(gs0), fv = sigm_f(gs1);
                    float gv = tanh_f(gs2), ov = sigm_f(gs3);
                    float cn = fv * cold + iv * gv;
                    float hn = ov * tanh_f(cn);
                    g_c[b * H_ + j] = cn;
                    g_h[b * H_ + j] = hn;
                    g_hist_h[t][b][j] = hn;
                    sm.p2.h[bi][jj] = hn;
                }
            }
            __syncthreads();
            #pragma unroll
            for (int e = 0; e < 2; ++e) {
                int nn = tid + e * 512;
                if (nn < NHP_) {
                    float a0 = 0.f, a1 = 0.f, a2 = 0.f, a3 = 0.f;
                    #pragma unroll
                    for (int k = 0; k < 32; ++k) {
                        float w = __ldcg(&g_WhT[(size_t)(j0 + k) * NHP_ + nn]);
                        a0 += sm.p2.h[0][k] * w;
                        a1 += sm.p2.h[1][k] * w;
                        a2 += sm.p2.h[2][k] * w;
                        a3 += sm.p2.h[3][k] * w;
                    }
                    g_hp_part[ks2][b02 + 0][nn] = a0;
                    g_hp_part[ks2][b02 + 1][nn] = a1;
                    g_hp_part[ks2][b02 + 2][nn] = a2;
                    g_hp_part[ks2][b02 + 3][nn] = a3;
                }
            }
        }
        // hoist block-private mem-row loads above the barrier (coalesced)
        ulonglong2 rows2[8][2];
        #pragma unroll
        for (int it = 0; it < 8; ++it) {
            const float* mp = &g_mem[ab][m0 + it*64 + wrp*4 + msub][0];
            rows2[it][0] = *(const ulonglong2*)(mp + hq * 4);
            rows2[it][1] = *(const ulonglong2*)(mp + 32 + hq * 4);
        }
        barwait(&g_barG[t][bid >> 4], 16);      // 16-group: P2 -> P3 (hp_part local)

        // ================= P3: keys + ws + scores + sk + chunk stats =================
        {
            {   // key build: 512 entries, 1 per thread; ws piggybacked on tid<4
                int key = tid >> 6, h = tid & 63;
                int n = key & 3;
                int p = (key < 4) ? h : 64 + h;
                float v = __ldg(&b_head[n * HPROW_ + p]);
                #pragma unroll
                for (int ps = 0; ps < 16; ++ps) v += __ldcg(&g_hp_part[ps][ab][n * 129 + p]);
                sm.a.key[key][h] = v * 0.125f;
                if (tid < 4) {
                    int nw = tid;
                    float vw = __ldg(&b_head[nw * HPROW_ + 128]);
                    #pragma unroll
                    for (int ps = 0; ps < 16; ++ps) vw += __ldcg(&g_hp_part[ps][ab][nw * 129 + 128]);
                    sm.a.ws[nw] = sigm_f(vw);
                }
            }
            __syncthreads();
            #pragma unroll
            for (int it = 0; it < 8; ++it) {
                float pv[8];
                #pragma unroll
                for (int key = 0; key < 8; ++key) {
                    ulonglong2 klo = *(const ulonglong2*)&sm.a.key[key][hq * 4];
                    ulonglong2 khi = *(const ulonglong2*)&sm.a.key[key][32 + hq * 4];
                    u64 d2 = ffma2(rows2[it][0].x, klo.x, 0ull);
                    d2 = ffma2(rows2[it][0].y, klo.y, d2);
                    d2 = ffma2(rows2[it][1].x, khi.x, d2);
                    d2 = ffma2(rows2[it][1].y, khi.y, d2);
                    float2 pf = unpack2(d2);
                    pv[key] = pf.x + pf.y;
                }
                // multi-key butterfly: lane (hq) ends with total for key == hq
                float q4[4];
                #pragma unroll
                for (int k2 = 0; k2 < 4; ++k2) {
                    float send = (hq & 1) ? pv[2*k2] : pv[2*k2+1];
                    float recv = __shfl_xor_sync(0xffffffffu, send, 1);
                    float keepv = (hq & 1) ? pv[2*k2+1] : pv[2*k2];
                    q4[k2] = keepv + recv;
                }
                float r2v[2];
                #pragma unroll
                for (int k2 = 0; k2 < 2; ++k2) {
                    float send = (hq & 2) ? q4[2*k2] : q4[2*k2+1];
                    float recv = __shfl_xor_sync(0xffffffffu, send, 2);
                    float keepv = (hq & 2) ? q4[2*k2+1] : q4[2*k2];
                    r2v[k2] = keepv + recv;
                }
                {
                    float send = (hq & 4) ? r2v[0] : r2v[1];
                    float recv = __shfl_xor_sync(0xffffffffu, send, 4);
                    float keepv = (hq & 4) ? r2v[1] : r2v[0];
                    sm.a.sc[hq][it*64 + wrp*4 + msub] = keepv + recv;
                }
            }
            // sk build (needs ws + hp_part; independent of sc stats below)
            if (tid < 256) {
                int n = tid >> 6, h = tid & 63;
                float v = __ldg(&b_head[n * HPROW_ + 64 + h]);
                #pragma unroll
                for (int ps = 0; ps < 16; ++ps) v += __ldcg(&g_hp_part[ps][ab][n * 129 + 64 + h]);
                sm.a.sk[n][h] = v * sm.a.ws[n];
            }
            __syncthreads();
            if (wrp < 8) {      // chunk max per key
                float mx = -1e30f;
                for (int i = lane; i < 512; i += 32) mx = fmaxf(mx, sm.a.sc[wrp][i]);
                #pragma unroll
                for (int sh = 16; sh; sh >>= 1) mx = fmaxf(mx, __shfl_xor_sync(0xffffffffu, mx, sh));
                if (lane == 0) sm.a.gm[wrp] = mx;
            }
            __syncthreads();
            #pragma unroll
            for (int key = 0; key < 8; ++key)     // exp in place
                sm.a.sc[key][tid] = __expf(sm.a.sc[key][tid] - sm.a.gm[key]);
            __syncthreads();
            if (wrp < 8) {      // chunk sumexp
                float se = 0.f;
                for (int i = lane; i < 512; i += 32) se += sm.a.sc[wrp][i];
                #pragma unroll
                for (int sh = 16; sh; sh >>= 1) se += __shfl_xor_sync(0xffffffffu, se, sh);
                if (lane == 0) g_stats[ab][wrp][mq] = make_float2(sm.a.gm[wrp], se);
            }
        }
        barwait(&g_barG[t][8 + (bid >> 2)], 4); // 4-group: P3 -> P4 (stats local)

        // ================= P4: softmax apply on register rows, read acc, mem update ==========
        {
            if (tid < 8) {
                float2 st0 = __ldcg(&g_stats[ab][tid][0]);
                float2 st1 = __ldcg(&g_stats[ab][tid][1]);
                float2 st2 = __ldcg(&g_stats[ab][tid][2]);
                float2 st3 = __ldcg(&g_stats[ab][tid][3]);
                float gm = fmaxf(fmaxf(st0.x, st1.x), fmaxf(st2.x, st3.x));
                float ssum = st0.y * __expf(st0.x - gm) + st1.y * __expf(st1.x - gm)
                           + st2.y * __expf(st2.x - gm) + st3.y * __expf(st3.x - gm);
                sm.a.inv[tid] = __expf(sm.a.gm[tid] - gm) / ssum;
            }
            __syncthreads();
            float scl[8];
            #pragma unroll
            for (int key = 0; key < 8; ++key) scl[key] = sm.a.inv[key];

            u64 racc2[4][4];
            #pragma unroll
            for (int n = 0; n < 4; ++n)
                #pragma unroll
                for (int q2 = 0; q2 < 4; ++q2) racc2[n][q2] = 0ull;

            #pragma unroll
            for (int it = 0; it < 8; ++it) {
                const int ml = it*64 + wrp*4 + msub;
                float wv[8];
                #pragma unroll
                for (int n = 0; n < 8; ++n) wv[n] = sm.a.sc[n][ml] * scl[n];
                ulonglong2 rlo = rows2[it][0], rhi = rows2[it][1];
                #pragma unroll
                for (int n = 0; n < 4; ++n) {
                    u64 rw2 = pack2(wv[n], wv[n]);
                    racc2[n][0] = ffma2(rw2, rlo.x, racc2[n][0]);
                    racc2[n][1] = ffma2(rw2, rlo.y, racc2[n][1]);
                    racc2[n][2] = ffma2(rw2, rhi.x, racc2[n][2]);
                    racc2[n][3] = ffma2(rw2, rhi.y, racc2[n][3]);
                }
                #pragma unroll
                for (int n = 0; n < 4; ++n) {
                    u64 ww2 = pack2(wv[4 + n], wv[4 + n]);
                    ulonglong2 slo = *(const ulonglong2*)&sm.a.sk[n][hq * 4];
                    ulonglong2 shi = *(const ulonglong2*)&sm.a.sk[n][32 + hq * 4];
                    rlo.x = ffma2(ww2, slo.x, rlo.x);
                    rlo.y = ffma2(ww2, slo.y, rlo.y);
                    rhi.x = ffma2(ww2, shi.x, rhi.x);
                    rhi.y = ffma2(ww2, shi.y, rhi.y);
                }
                float* mp = &g_mem[ab][m0 + ml][0];
                *(ulonglong2*)(mp + hq * 4) = rlo;
                *(ulonglong2*)(mp + 32 + hq * 4) = rhi;
            }
            // reduce read partials over msub (xor 8, 16)
            #pragma unroll
            for (int n = 0; n < 4; ++n)
                #pragma unroll
                for (int q2 = 0; q2 < 4; ++q2) {
                    racc2[n][q2] = fadd2(racc2[n][q2], __shfl_xor_sync(0xffffffffu, racc2[n][q2], 8));
                    racc2[n][q2] = fadd2(racc2[n][q2], __shfl_xor_sync(0xffffffffu, racc2[n][q2], 16));
                }
            if (lane < 8) {   // msub == 0, hq == lane
                #pragma unroll
                for (int n = 0; n < 4; ++n) {
                    float2 p0 = unpack2(racc2[n][0]);
                    float2 p1 = unpack2(racc2[n][1]);
                    float2 p2 = unpack2(racc2[n][2]);
                    float2 p3 = unpack2(racc2[n][3]);
                    *(float2*)&sm.a.racc[wrp][n][hq*4]          = p0;
                    *(float2*)&sm.a.racc[wrp][n][hq*4 + 2]      = p1;
                    *(float2*)&sm.a.racc[wrp][n][32 + hq*4]     = p2;
                    *(float2*)&sm.a.racc[wrp][n][32 + hq*4 + 2] = p3;
                }
            }
            __syncthreads();
            if (tid < 256) {
                int n = tid >> 6, h = tid & 63;
                float ssum = 0.f;
                #pragma unroll
                for (int wr = 0; wr < 16; ++wr) ssum += sm.a.racc[wr][n][h];
                g_read_part[t][mq][ab][n * 64 + h] = ssum;
            }
        }
        barwait(&g_bar[2*t + 1], NBLK * 1);     // global: P4 -> next P1
    }
}

// ---------------- final output GEMM: outputs[b][t][o] ----------------
__global__ void k_out(const float* __restrict__ b_out, float* __restrict__ out) {
    const int m0 = blockIdx.x * 32, nc = blockIdx.y;
    const int tid = threadIdx.x;
    __shared__ float a_sh[32][64];
    const int n_l = tid & 63, mg = tid >> 6;
    const int n = nc * 64 + n_l;
    float acc[8];
    #pragma unroll
    for (int r = 0; r < 8; ++r) acc[r] = 0.f;
    for (int kt = 0; kt < 12; ++kt) {
        __syncthreads();
        #pragma unroll
        for (int e = 0; e < 8; ++e) {
            int lidx = e * 256 + tid;
            int mrow = lidx >> 6, kk = lidx & 63;
            int m = m0 + mrow;
            int ts = m >> 5, bb = m & 31;
            int gk = kt * 64 + kk;
            float v;
            if (gk < 512) v = g_hist_h[ts][bb][gk];
            else {
                int r = gk - 512;
                v = g_read_part[ts][0][bb][r] + g_read_part[ts][1][bb][r]
                  + g_read_part[ts][2][bb][r] + g_read_part[ts][3][bb][r];
            }
            a_sh[mrow][kk] = v;
        }
        __syncthreads();
        #pragma unroll 4
        for (int kk = 0; kk < 64; ++kk) {
            float wv = g_WoT[(kt * 64 + kk) * O_ + n];
            #pragma unroll
            for (int r = 0; r < 8; ++r) acc[r] += a_sh[mg * 8 + r][kk] * wv;
        }
    }
    float bo = b_out[n];
    #pragma unroll
    for (int r = 0; r < 8; ++r) {
        int m = m0 + mg * 8 + r;
        int ts = m >> 5, bb = m & 31;
        out[(bb * T_ + ts) * O_ + n] = acc[r] + bo;
    }
}

// ---------------- final state copy: mem, h, c into d_out ----------------
__global__ void k_final(float* __restrict__ out) {
    const int OUT_N = B_ * T_ * O_;
    const int NMEM  = B_ * MS_ * HS_;
    const int total = NMEM + 2 * B_ * H_;
    for (int i = blockIdx.x * blockDim.x + threadIdx.x; i < total; i += gridDim.x * blockDim.x) {
        if (i < NMEM)                 out[OUT_N + i] = (&g_mem[0][0][0])[i];
        else if (i < NMEM + B_ * H_)  out[OUT_N + i] = g_h[i - NMEM];
        else                          out[OUT_N + i] = g_c[i - NMEM - B_ * H_];
    }
}

extern "C" void kernel_launch(void* const* d_in, const int* in_sizes, int n_in,
                              void* d_out, int out_size) {
    const float* x      = (const float*)d_in[0];
    const float* W_ih   = (const float*)d_in[1];
    const float* W_hh   = (const float*)d_in[2];
    const float* b_ih   = (const float*)d_in[3];
    const float* b_hh   = (const float*)d_in[4];
    const float* W_head = (const float*)d_in[5];
    const float* b_head = (const float*)d_in[6];
    const float* W_out  = (const float*)d_in[7];
    const float* b_out  = (const float*)d_in[8];
    float* out = (float*)d_out;

    k_prep<<<3024, 256>>>(W_ih, W_hh, W_head, W_out);
    k_nop<<<1, 32>>>();
    k_nop<<<1, 32>>>();
    k_steps<<<NBLK, NTHR>>>(x, b_ih, b_hh, b_head);
    k_out<<<dim3(32, 4), 256>>>(b_out, out);
    k_final<<<2048, 256>>>(out);
}

// round 14
// speedup vs baseline: 1.5939x; 1.0172x over previous
#include <cuda_runtime.h>
#include <math.h>

// Problem constants
#define B_  32
#define T_  32
#define I_  256
#define H_  512
#define NH_ 4
#define HS_ 64
#define MS_ 2048
#define O_  256
// derived
#define KG_ 1024
#define NG_ 2048        // 4*H, gate col index n = g*512 + j
#define NHP_ 516
#define HPROW_ 2115
#define NBLK 256
#define NTHR 256
#define NBARG (2*T_)    // global barriers (2 per step)

typedef unsigned long long u64;

__device__ __forceinline__ u64 ffma2(u64 a, u64 b, u64 c) {
    u64 d; asm("fma.rn.f32x2 %0, %1, %2, %3;" : "=l"(d) : "l"(a), "l"(b), "l"(c)); return d;
}
__device__ __forceinline__ u64 fadd2(u64 a, u64 b) {
    u64 d; asm("add.rn.f32x2 %0, %1, %2;" : "=l"(d) : "l"(a), "l"(b)); return d;
}
__device__ __forceinline__ u64 pack2(float lo, float hi) {
    u64 d; asm("mov.b64 %0, {%1, %2};" : "=l"(d) : "f"(lo), "f"(hi)); return d;
}
__device__ __forceinline__ float2 unpack2(u64 v) {
    float2 r; asm("mov.b64 {%0, %1}, %2;" : "=f"(r.x), "=f"(r.y) : "l"(v)); return r;
}

// ---------------- scratch (device globals; no allocation allowed) ----------------
__device__ float g_WgT[KG_*NG_];              // [k][n]  8MB
__device__ float g_WhT[H_*NHP_];              // [k][n*129+p]
__device__ float g_WoT[(H_+NH_*HS_)*O_];      // [k][o]
__device__ float g_h[B_*H_];
__device__ float g_c[B_*H_];
__device__ float g_gates_part[16][B_][NG_];   // k-split (16 slices of 64) partial gates
__device__ float g_hp_part[16][B_][NHP_];
__device__ float2 g_stats[B_][8][8];          // [b][key][mq] = {chunk max, chunk sumexp}
__device__ float g_read_part[T_][8][B_][NH_*HS_];
__device__ float g_hist_h[T_][B_][H_];
__device__ float g_mem[B_][MS_][HS_];         // 16.7MB
__device__ int   g_bar[NBARG];                // global barrier counters
__device__ int   g_barG[T_][48];              // per-step: [0..15]=16-groups, [16..47]=8-groups

// fast transcendentals (approx exp/div; errors ~1e-7, contractive in LSTM)
__device__ __forceinline__ float sigm_f(float v) {
    return __fdividef(1.f, 1.f + __expf(-v));
}
__device__ __forceinline__ float tanh_f(float v) {
    float e = __expf(-2.f * v);
    return __fdividef(1.f - e, 1.f + e);
}

// ---------------- barriers: release-add + acquire-poll, no L1 flush ----------------
__device__ __forceinline__ void barwait(int* p, int cnt) {
    __syncthreads();
    if (threadIdx.x == 0) {
        asm volatile("red.release.gpu.global.add.s32 [%0], 1;" :: "l"(p) : "memory");
        int v;
        do {
            asm volatile("ld.acquire.gpu.global.s32 %0, [%1];" : "=r"(v) : "l"(p) : "memory");
        } while (v < cnt);
    }
    __syncthreads();
}

// ---------------- fused prep: transposes + zeroing in ONE launch ----------------
__global__ void k_prep(const float* __restrict__ W_ih, const float* __restrict__ W_hh,
                       const float* __restrict__ W_head, const float* __restrict__ W_out) {
    const int b = blockIdx.x;
    const int tid = threadIdx.x;                // 256
    const int tx = tid & 31, ty = tid >> 5;     // (32, 8)
    __shared__ float tile[32][33];
    if (b < 2048) {                             // WgT[k][n]
        int bx = (b & 31) * 32, by = (b >> 5) * 32;
        #pragma unroll
        for (int i = 0; i < 32; i += 8) {
            int row = by + ty + i, k = bx + tx;
            tile[ty + i][tx] = (k < 512) ? W_ih[row*512 + k] : W_hh[row*512 + (k - 512)];
        }
        __syncthreads();
        #pragma unroll
        for (int i = 0; i < 32; i += 8) {
            int k = bx + ty + i, row = by + tx;
            g_WgT[(size_t)k * NG_ + row] = tile[tx][ty + i];
        }
    } else if (b < 2048 + 272) {                // WhT[k][r]
        int bb = b - 2048;
        int bx = (bb & 15) * 32, by = (bb >> 4) * 32;
        #pragma unroll
        for (int i = 0; i < 32; i += 8) {
            int r = by + ty + i, k = bx + tx;
            float v = 0.f;
            if (r < NHP_) {
                int n = r / 129, p = r % 129;
                v = W_head[(size_t)(n * HPROW_ + p) * 512 + k];
            }
            tile[ty + i][tx] = v;
        }
        __syncthreads();
        #pragma unroll
        for (int i = 0; i < 32; i += 8) {
            int k = bx + ty + i, r = by + tx;
            if (r < NHP_) g_WhT[(size_t)k * NHP_ + r] = tile[tx][ty + i];
        }
    } else if (b < 2048 + 272 + 192) {          // WoT[k][o]
        int bb = b - 2320;
        int bx = (bb % 24) * 32, by = (bb / 24) * 32;
        #pragma unroll
        for (int i = 0; i < 32; i += 8) {
            int o = by + ty + i, k = bx + tx;
            tile[ty + i][tx] = W_out[o * (H_ + NH_*HS_) + k];
        }
        __syncthreads();
        #pragma unroll
        for (int i = 0; i < 32; i += 8) {
            int k = bx + ty + i, o = by + tx;
            g_WoT[(size_t)k * O_ + o] = tile[tx][ty + i];
        }
    } else {
        int bb = b - 2512;                      // 0..511
        int gtid = bb * 256 + tid;
        float4 z4 = make_float4(0.f, 0.f, 0.f, 0.f);
        #pragma unroll
        for (int i = 0; i < 8; ++i)
            ((float4*)g_mem)[gtid + i * 131072] = z4;
        if (gtid < 4096)                  ((float4*)g_h)[gtid] = z4;
        else if (gtid < 8192)             ((float4*)g_c)[gtid - 4096] = z4;
        else if (gtid < 8192 + NBARG)     g_bar[gtid - 8192] = 0;
        else if (gtid < 8192 + NBARG + T_*48)
            (&g_barG[0][0])[gtid - 8192 - NBARG] = 0;
    }
}

__global__ void k_nop() {}

// ---------------- the persistent recurrence kernel (256 blocks x 256 threads, 2/SM) --------
struct SmGates { u64 vp[64][18]; };      // {v(2p), v(2p+1)} pairs
struct SmP2    { float h[2][32]; };
struct SmAttn  {
    float key[8][64];
    float sc[8][260];                    // raw scores -> exp(s - gm_chunk) in place
    float gm[8], inv[8], ws[4];
    float sk[4][64];
    float racc[8][4][64];
};
union __align__(16) SmU { SmGates g; SmP2 p2; SmAttn a; };

__global__ __launch_bounds__(NTHR, 2)
void k_steps(const float* __restrict__ x, const float* __restrict__ b_ih,
             const float* __restrict__ b_hh, const float* __restrict__ b_head) {
    __shared__ SmU sm;
    const int bid = blockIdx.x, tid = threadIdx.x;
    const int wrp = tid >> 5, lane = tid & 31;

    // P1 partition: (16 n-chunks of 128) x (16 k-slices of 64)
    const int nc = bid >> 4, ksl = bid & 15;
    const int n0 = nc * 128, k0g = ksl * 64;
    const int c_l = lane & 7, bgrp = lane >> 3;      // 8 col-subs x 4 batch-groups
    const int col0 = n0 + wrp * 16 + c_l * 2;        // warp = colgrp
    // P2 partition: (16 batch-pairs) x (16 j-slices of 32)
    const int bq2 = bid >> 4, ks2 = bid & 15;
    const int b02 = bq2 * 2, j0 = ks2 * 32;
    // P3/P4 partition: batch x 8 m-chunks of 256 rows
    const int ab = bid >> 3, mq = bid & 7;
    const int m0 = mq * 256;
    const int hq = lane & 7, msub = lane >> 3;

    for (int t = 0; t < T_; ++t) {
        // ================= P1: gates GEMM (16 k-slice partials) =================
        {
            // build v pair tile vp[k][p] = {v(2p), v(2p+1)} : 64k x 16 pairs
            #pragma unroll
            for (int e = 0; e < 4; ++e) {
                int idx = e * 256 + tid;
                int kk = idx & 63, p = idx >> 6;
                int gk = k0g + kk;
                int bb = p * 2;
                float v0, v1;
                if (gk < 256) {
                    v0 = __ldg(&x[(bb * T_ + t) * I_ + gk]);
                    v1 = __ldg(&x[((bb+1) * T_ + t) * I_ + gk]);
                } else if (gk < 512) {
                    if (t == 0) { v0 = 0.f; v1 = 0.f; }
                    else {
                        int r = gk - 256;
                        v0 = 0.f; v1 = 0.f;
                        #pragma unroll
                        for (int mc = 0; mc < 8; ++mc) {
                            v0 += __ldcg(&g_read_part[t-1][mc][bb][r]);
                            v1 += __ldcg(&g_read_part[t-1][mc][bb+1][r]);
                        }
                    }
                } else {
                    v0 = __ldcg(&g_h[bb * H_ + (gk - 512)]);
                    v1 = __ldcg(&g_h[(bb+1) * H_ + (gk - 512)]);
                }
                sm.g.vp[kk][p] = pack2(v0, v1);
            }
            __syncthreads();
            u64 acc[2][4];
            {
                u64 b0p = 0ull, b1p = 0ull;
                if (ksl == 0) {
                    float bi0 = __ldg(&b_ih[col0])   + __ldg(&b_hh[col0]);
                    float bi1 = __ldg(&b_ih[col0+1]) + __ldg(&b_hh[col0+1]);
                    b0p = pack2(bi0, bi0); b1p = pack2(bi1, bi1);
                }
                #pragma unroll
                for (int p = 0; p < 4; ++p) { acc[0][p] = b0p; acc[1][p] = b1p; }
            }
            const float2* wp2 = (const float2*)&g_WgT[(size_t)k0g * NG_ + col0];
            const int p0 = bgrp * 4;
            #pragma unroll 8
            for (int kk = 0; kk < 64; ++kk) {
                float2 w = __ldg(wp2 + (size_t)kk * (NG_/2));
                u64 w20 = pack2(w.x, w.x);
                u64 w21 = pack2(w.y, w.y);
                ulonglong2 va = *(const ulonglong2*)&sm.g.vp[kk][p0];
                ulonglong2 vb = *(const ulonglong2*)&sm.g.vp[kk][p0 + 2];
                acc[0][0] = ffma2(va.x, w20, acc[0][0]);
                acc[0][1] = ffma2(va.y, w20, acc[0][1]);
                acc[0][2] = ffma2(vb.x, w20, acc[0][2]);
                acc[0][3] = ffma2(vb.y, w20, acc[0][3]);
                acc[1][0] = ffma2(va.x, w21, acc[1][0]);
                acc[1][1] = ffma2(va.y, w21, acc[1][1]);
                acc[1][2] = ffma2(vb.x, w21, acc[1][2]);
                acc[1][3] = ffma2(vb.y, w21, acc[1][3]);
            }
            #pragma unroll
            for (int p = 0; p < 4; ++p) {
                float2 c0 = unpack2(acc[0][p]);
                float2 c1 = unpack2(acc[1][p]);
                int b = bgrp * 8 + p * 2;
                *(float2*)&g_gates_part[ksl][b][col0]     = make_float2(c0.x, c1.x);
                *(float2*)&g_gates_part[ksl][b + 1][col0] = make_float2(c0.y, c1.y);
            }
            __syncthreads();
        }
        barwait(&g_bar[2*t + 0], NBLK);         // global: P1 -> P2

        // ================= P2: LSTM (quad-spread) + partial head GEMM =================
        {
            {
                const int cell = tid >> 2, q = tid & 3;     // 64 cells: 2 b x 32 j
                const int bi = cell >> 5, jj = cell & 31;
                const int b = b02 + bi, j = j0 + jj;
                float gs0 = 0.f, gs1 = 0.f, gs2 = 0.f, gs3 = 0.f;
                #pragma unroll
                for (int e = 0; e < 4; ++e) {
                    int s = q * 4 + e;
                    gs0 += __ldcg(&g_gates_part[s][b][j]);
                    gs1 += __ldcg(&g_gates_part[s][b][512 + j]);
                    gs2 += __ldcg(&g_gates_part[s][b][1024 + j]);
                    gs3 += __ldcg(&g_gates_part[s][b][1536 + j]);
                }
                gs0 += __shfl_xor_sync(0xffffffffu, gs0, 1);
                gs1 += __shfl_xor_sync(0xffffffffu, gs1, 1);
                gs2 += __shfl_xor_sync(0xffffffffu, gs2, 1);
                gs3 += __shfl_xor_sync(0xffffffffu, gs3, 1);
                gs0 += __shfl_xor_sync(0xffffffffu, gs0, 2);
                gs1 += __shfl_xor_sync(0xffffffffu, gs1, 2);
                gs2 += __shfl_xor_sync(0xffffffffu, gs2, 2);
                gs3 += __shfl_xor_sync(0xffffffffu, gs3, 2);
                if (q == 0) {
                    float cold = g_c[b * H_ + j];
                    float iv = sigm_f(gs0), fv = sigm_f(gs1);
                    float gv = tanh_f(gs2), ov = sigm_f(gs3);
                    float cn = fv * cold + iv * gv;
                    float hn = ov * tanh_f(cn);
                    g_c[b * H_ + j] = cn;
                    g_h[b * H_ + j] = hn;
                    g_hist_h[t][b][j] = hn;
                    sm.p2.h[bi][jj] = hn;
                }
            }
            __syncthreads();
            #pragma unroll
            for (int e = 0; e < 3; ++e) {
                int nn = tid + e * 256;
                if (nn < NHP_) {
                    float a0 = 0.f, a1 = 0.f;
                    #pragma unroll
                    for (int k = 0; k < 32; ++k) {
                        float w = __ldcg(&g_WhT[(size_t)(j0 + k) * NHP_ + nn]);
                        a0 += sm.p2.h[0][k] * w;
                        a1 += sm.p2.h[1][k] * w;
                    }
                    g_hp_part[ks2][b02 + 0][nn] = a0;
                    g_hp_part[ks2][b02 + 1][nn] = a1;
                }
            }
        }
        // hoist block-private mem-row loads above the barrier (coalesced)
        // warp owns rows {it*32 + wrp*4 + msub}; lane holds floats [hq*4..+4) and [32+hq*4..+4)
        ulonglong2 rows2[8][2];
        #pragma unroll
        for (int it = 0; it < 8; ++it) {
            const float* mp = &g_mem[ab][m0 + it*32 + wrp*4 + msub][0];
            rows2[it][0] = *(const ulonglong2*)(mp + hq * 4);
            rows2[it][1] = *(const ulonglong2*)(mp + 32 + hq * 4);
        }
        barwait(&g_barG[t][bid >> 4], 16);      // 16-group: P2 -> P3 (hp_part local)

        // ================= P3: keys + ws + scores + sk + chunk stats =================
        {
            #pragma unroll
            for (int e = 0; e < 2; ++e) {       // key build: 512 entries, 2 per thread
                int idx = e * 256 + tid;
                int key = idx >> 6, h = idx & 63;
                int n = key & 3;
                int p = (key < 4) ? h : 64 + h;
                float v = __ldg(&b_head[n * HPROW_ + p]);
                #pragma unroll
                for (int ps = 0; ps < 16; ++ps) v += __ldcg(&g_hp_part[ps][ab][n * 129 + p]);
                sm.a.key[key][h] = v * 0.125f;
            }
            if (tid < 4) {
                int nw = tid;
                float vw = __ldg(&b_head[nw * HPROW_ + 128]);
                #pragma unroll
                for (int ps = 0; ps < 16; ++ps) vw += __ldcg(&g_hp_part[ps][ab][nw * 129 + 128]);
                sm.a.ws[nw] = sigm_f(vw);
            }
            __syncthreads();
            #pragma unroll
            for (int it = 0; it < 8; ++it) {
                float pv[8];
                #pragma unroll
                for (int key = 0; key < 8; ++key) {
                    ulonglong2 klo = *(const ulonglong2*)&sm.a.key[key][hq * 4];
                    ulonglong2 khi = *(const ulonglong2*)&sm.a.key[key][32 + hq * 4];
                    u64 d2 = ffma2(rows2[it][0].x, klo.x, 0ull);
                    d2 = ffma2(rows2[it][0].y, klo.y, d2);
                    d2 = ffma2(rows2[it][1].x, khi.x, d2);
                    d2 = ffma2(rows2[it][1].y, khi.y, d2);
                    float2 pf = unpack2(d2);
                    pv[key] = pf.x + pf.y;
                }
                // multi-key butterfly: lane (hq) ends with total for key == hq
                float q4[4];
                #pragma unroll
                for (int k2 = 0; k2 < 4; ++k2) {
                    float send = (hq & 1) ? pv[2*k2] : pv[2*k2+1];
                    float recv = __shfl_xor_sync(0xffffffffu, send, 1);
                    float keepv = (hq & 1) ? pv[2*k2+1] : pv[2*k2];
                    q4[k2] = keepv + recv;
                }
                float r2v[2];
                #pragma unroll
                for (int k2 = 0; k2 < 2; ++k2) {
                    float send = (hq & 2) ? q4[2*k2] : q4[2*k2+1];
                    float recv = __shfl_xor_sync(0xffffffffu, send, 2);
                    float keepv = (hq & 2) ? q4[2*k2+1] : q4[2*k2];
                    r2v[k2] = keepv + recv;
                }
                {
                    float send = (hq & 4) ? r2v[0] : r2v[1];
                    float recv = __shfl_xor_sync(0xffffffffu, send, 4);
                    float keepv = (hq & 4) ? r2v[1] : r2v[0];
                    sm.a.sc[hq][it*32 + wrp*4 + msub] = keepv + recv;
                }
            }
            // sk build (needs ws + hp_part; independent of sc stats below)
            {
                int n = tid >> 6, h = tid & 63;
                float v = __ldg(&b_head[n * HPROW_ + 64 + h]);
                #pragma unroll
                for (int ps = 0; ps < 16; ++ps) v += __ldcg(&g_hp_part[ps][ab][n * 129 + 64 + h]);
                sm.a.sk[n][h] = v * sm.a.ws[n];
            }
            __syncthreads();
            if (wrp < 8) {      // chunk max per key (8 warps = 8 keys)
                float mx = -1e30f;
                for (int i = lane; i < 256; i += 32) mx = fmaxf(mx, sm.a.sc[wrp][i]);
                #pragma unroll
                for (int sh = 16; sh; sh >>= 1) mx = fmaxf(mx, __shfl_xor_sync(0xffffffffu, mx, sh));
                if (lane == 0) sm.a.gm[wrp] = mx;
            }
            __syncthreads();
            #pragma unroll
            for (int key = 0; key < 8; ++key)     // exp in place
                sm.a.sc[key][tid] = __expf(sm.a.sc[key][tid] - sm.a.gm[key]);
            __syncthreads();
            if (wrp < 8) {      // chunk sumexp
                float se = 0.f;
                for (int i = lane; i < 256; i += 32) se += sm.a.sc[wrp][i];
                #pragma unroll
                for (int sh = 16; sh; sh >>= 1) se += __shfl_xor_sync(0xffffffffu, se, sh);
                if (lane == 0) g_stats[ab][wrp][mq] = make_float2(sm.a.gm[wrp], se);
            }
        }
        barwait(&g_barG[t][16 + (bid >> 3)], 8); // 8-group: P3 -> P4 (stats local)

        // ================= P4: softmax apply on register rows, read acc, mem update ==========
        {
            if (tid < 8) {
                float gm = -1e30f;
                float2 st[8];
                #pragma unroll
                for (int c = 0; c < 8; ++c) {
                    st[c] = __ldcg(&g_stats[ab][tid][c]);
                    gm = fmaxf(gm, st[c].x);
                }
                float ssum = 0.f;
                #pragma unroll
                for (int c = 0; c < 8; ++c) ssum += st[c].y * __expf(st[c].x - gm);
                sm.a.inv[tid] = __expf(sm.a.gm[tid] - gm) / ssum;
            }
            __syncthreads();
            float scl[8];
            #pragma unroll
            for (int key = 0; key < 8; ++key) scl[key] = sm.a.inv[key];

            u64 racc2[4][4];
            #pragma unroll
            for (int n = 0; n < 4; ++n)
                #pragma unroll
                for (int q2 = 0; q2 < 4; ++q2) racc2[n][q2] = 0ull;

            #pragma unroll
            for (int it = 0; it < 8; ++it) {
                const int ml = it*32 + wrp*4 + msub;
                float wv[8];
                #pragma unroll
                for (int n = 0; n < 8; ++n) wv[n] = sm.a.sc[n][ml] * scl[n];
                ulonglong2 rlo = rows2[it][0], rhi = rows2[it][1];
                #pragma unroll
                for (int n = 0; n < 4; ++n) {
                    u64 rw2 = pack2(wv[n], wv[n]);
                    racc2[n][0] = ffma2(rw2, rlo.x, racc2[n][0]);
                    racc2[n][1] = ffma2(rw2, rlo.y, racc2[n][1]);
                    racc2[n][2] = ffma2(rw2, rhi.x, racc2[n][2]);
                    racc2[n][3] = ffma2(rw2, rhi.y, racc2[n][3]);
                }
                #pragma unroll
                for (int n = 0; n < 4; ++n) {
                    u64 ww2 = pack2(wv[4 + n], wv[4 + n]);
                    ulonglong2 slo = *(const ulonglong2*)&sm.a.sk[n][hq * 4];
                    ulonglong2 shi = *(const ulonglong2*)&sm.a.sk[n][32 + hq * 4];
                    rlo.x = ffma2(ww2, slo.x, rlo.x);
                    rlo.y = ffma2(ww2, slo.y, rlo.y);
                    rhi.x = ffma2(ww2, shi.x, rhi.x);
                    rhi.y = ffma2(ww2, shi.y, rhi.y);
                }
                float* mp = &g_mem[ab][m0 + ml][0];
                *(ulonglong2*)(mp + hq * 4) = rlo;
                *(ulonglong2*)(mp + 32 + hq * 4) = rhi;
            }
            // reduce read partials over msub (xor 8, 16)
            #pragma unroll
            for (int n = 0; n < 4; ++n)
                #pragma unroll
                for (int q2 = 0; q2 < 4; ++q2) {
                    racc2[n][q2] = fadd2(racc2[n][q2], __shfl_xor_sync(0xffffffffu, racc2[n][q2], 8));
                    racc2[n][q2] = fadd2(racc2[n][q2], __shfl_xor_sync(0xffffffffu, racc2[n][q2], 16));
                }
            if (lane < 8) {   // msub == 0, hq == lane
                #pragma unroll
                for (int n = 0; n < 4; ++n) {
                    float2 p0 = unpack2(racc2[n][0]);
                    float2 p1 = unpack2(racc2[n][1]);
                    float2 p2 = unpack2(racc2[n][2]);
                    float2 p3 = unpack2(racc2[n][3]);
                    *(float2*)&sm.a.racc[wrp][n][hq*4]          = p0;
                    *(float2*)&sm.a.racc[wrp][n][hq*4 + 2]      = p1;
                    *(float2*)&sm.a.racc[wrp][n][32 + hq*4]     = p2;
                    *(float2*)&sm.a.racc[wrp][n][32 + hq*4 + 2] = p3;
                }
            }
            __syncthreads();
            {
                int n = tid >> 6, h = tid & 63;
                float ssum = 0.f;
                #pragma unroll
                for (int wr = 0; wr < 8; ++wr) ssum += sm.a.racc[wr][n][h];
                g_read_part[t][mq][ab][n * 64 + h] = ssum;
            }
        }
        barwait(&g_bar[2*t + 1], NBLK);         // global: P4 -> next P1
    }
}

// ---------------- final output GEMM: outputs[b][t][o] ----------------
__global__ void k_out(const float* __restrict__ b_out, float* __restrict__ out) {
    const int m0 = blockIdx.x * 32, nc = blockIdx.y;
    const int tid = threadIdx.x;
    __shared__ float a_sh[32][64];
    const int n_l = tid & 63, mg = tid >> 6;
    const int n = nc * 64 + n_l;
    float acc[8];
    #pragma unroll
    for (int r = 0; r < 8; ++r) acc[r] = 0.f;
    for (int kt = 0; kt < 12; ++kt) {
        __syncthreads();
        #pragma unroll
        for (int e = 0; e < 8; ++e) {
            int lidx = e * 256 + tid;
            int mrow = lidx >> 6, kk = lidx & 63;
            int m = m0 + mrow;
            int ts = m >> 5, bb = m & 31;
            int gk = kt * 64 + kk;
            float v;
            if (gk < 512) v = g_hist_h[ts][bb][gk];
            else {
                int r = gk - 512;
                v = 0.f;
                #pragma unroll
                for (int mc = 0; mc < 8; ++mc) v += g_read_part[ts][mc][bb][r];
            }
            a_sh[mrow][kk] = v;
        }
        __syncthreads();
        #pragma unroll 4
        for (int kk = 0; kk < 64; ++kk) {
            float wv = g_WoT[(kt * 64 + kk) * O_ + n];
            #pragma unroll
            for (int r = 0; r < 8; ++r) acc[r] += a_sh[mg * 8 + r][kk] * wv;
        }
    }
    float bo = b_out[n];
    #pragma unroll
    for (int r = 0; r < 8; ++r) {
        int m = m0 + mg * 8 + r;
        int ts = m >> 5, bb = m & 31;
        out[(bb * T_ + ts) * O_ + n] = acc[r] + bo;
    }
}

// ---------------- final state copy: mem, h, c into d_out ----------------
__global__ void k_final(float* __restrict__ out) {
    const int OUT_N = B_ * T_ * O_;
    const int NMEM  = B_ * MS_ * HS_;
    const int total = NMEM + 2 * B_ * H_;
    for (int i = blockIdx.x * blockDim.x + threadIdx.x; i < total; i += gridDim.x * blockDim.x) {
        if (i < NMEM)                 out[OUT_N + i] = (&g_mem[0][0][0])[i];
        else if (i < NMEM + B_ * H_)  out[OUT_N + i] = g_h[i - NMEM];
        else                          out[OUT_N + i] = g_c[i - NMEM - B_ * H_];
    }
}

extern "C" void kernel_launch(void* const* d_in, const int* in_sizes, int n_in,
                              void* d_out, int out_size) {
    const float* x      = (const float*)d_in[0];
    const float* W_ih   = (const float*)d_in[1];
    const float* W_hh   = (const float*)d_in[2];
    const float* b_ih   = (const float*)d_in[3];
    const float* b_hh   = (const float*)d_in[4];
    const float* W_head = (const float*)d_in[5];
    const float* b_head = (const float*)d_in[6];
    const float* W_out  = (const float*)d_in[7];
    const float* b_out  = (const float*)d_in[8];
    float* out = (float*)d_out;

    k_prep<<<3024, 256>>>(W_ih, W_hh, W_head, W_out);
    k_nop<<<1, 32>>>();
    k_nop<<<1, 32>>>();
    k_steps<<<NBLK, NTHR>>>(x, b_ih, b_hh, b_head);
    k_out<<<dim3(32, 4), 256>>>(b_out, out);
    k_final<<<2048, 256>>>(out);
}

// round 15
// speedup vs baseline: 1.6261x; 1.0202x over previous
#include <cuda_runtime.h>
#include <math.h>

// Problem constants
#define B_  32
#define T_  32
#define I_  256
#define H_  512
#define NH_ 4
#define HS_ 64
#define MS_ 2048
#define O_  256
// derived
#define KG_ 1024
#define NG_ 2048        // 4*H, gate col index n = g*512 + j
#define NHP_ 516
#define HPROW_ 2115
#define NBLK 256
#define NTHR 256
#define NBARG (2*T_)    // global barriers (2 per step)

typedef unsigned long long u64;

__device__ __forceinline__ u64 ffma2(u64 a, u64 b, u64 c) {
    u64 d; asm("fma.rn.f32x2 %0, %1, %2, %3;" : "=l"(d) : "l"(a), "l"(b), "l"(c)); return d;
}
__device__ __forceinline__ u64 fadd2(u64 a, u64 b) {
    u64 d; asm("add.rn.f32x2 %0, %1, %2;" : "=l"(d) : "l"(a), "l"(b)); return d;
}
__device__ __forceinline__ u64 pack2(float lo, float hi) {
    u64 d; asm("mov.b64 %0, {%1, %2};" : "=l"(d) : "f"(lo), "f"(hi)); return d;
}
__device__ __forceinline__ float2 unpack2(u64 v) {
    float2 r; asm("mov.b64 {%0, %1}, %2;" : "=f"(r.x), "=f"(r.y) : "l"(v)); return r;
}

// ---------------- scratch (device globals; no allocation allowed) ----------------
__device__ float g_WgT[KG_*NG_];              // [k][n]  8MB
__device__ float g_WhT[H_*NHP_];              // [k][n*129+p]
__device__ float g_WoT[(H_+NH_*HS_)*O_];      // [k][o]
__device__ float g_h[B_*H_];
__device__ float g_c[B_*H_];
__device__ float g_gates_part[16][B_][NG_];   // k-split (16 slices of 64) partial gates
__device__ float g_hp_part[16][B_][NHP_];
__device__ float2 g_stats[B_][8][8];          // [b][key][mq] = {chunk max, chunk sumexp}
__device__ float g_read_part[T_][8][B_][NH_*HS_];
__device__ float g_hist_h[T_][B_][H_];
__device__ float g_mem[B_][MS_][HS_];         // 16.7MB
__device__ int   g_bar[NBARG];                // global barrier counters
__device__ int   g_barG[T_][48];              // per-step: [0..15]=16-groups, [16..47]=8-groups

// fast transcendentals (approx exp/div; errors ~1e-7, contractive in LSTM)
__device__ __forceinline__ float sigm_f(float v) {
    return __fdividef(1.f, 1.f + __expf(-v));
}
__device__ __forceinline__ float tanh_f(float v) {
    float e = __expf(-2.f * v);
    return __fdividef(1.f - e, 1.f + e);
}

// ---------------- barriers: release-add + acquire-poll, no L1 flush ----------------
__device__ __forceinline__ void barwait(int* p, int cnt) {
    __syncthreads();
    if (threadIdx.x == 0) {
        asm volatile("red.release.gpu.global.add.s32 [%0], 1;" :: "l"(p) : "memory");
        int v;
        do {
            asm volatile("ld.acquire.gpu.global.s32 %0, [%1];" : "=r"(v) : "l"(p) : "memory");
        } while (v < cnt);
    }
    __syncthreads();
}

// ---------------- fused prep: transposes + zeroing in ONE launch ----------------
__global__ void k_prep(const float* __restrict__ W_ih, const float* __restrict__ W_hh,
                       const float* __restrict__ W_head, const float* __restrict__ W_out) {
    const int b = blockIdx.x;
    const int tid = threadIdx.x;                // 256
    const int tx = tid & 31, ty = tid >> 5;     // (32, 8)
    __shared__ float tile[32][33];
    if (b < 2048) {                             // WgT[k][n]
        int bx = (b & 31) * 32, by = (b >> 5) * 32;
        #pragma unroll
        for (int i = 0; i < 32; i += 8) {
            int row = by + ty + i, k = bx + tx;
            tile[ty + i][tx] = (k < 512) ? W_ih[row*512 + k] : W_hh[row*512 + (k - 512)];
        }
        __syncthreads();
        #pragma unroll
        for (int i = 0; i < 32; i += 8) {
            int k = bx + ty + i, row = by + tx;
            g_WgT[(size_t)k * NG_ + row] = tile[tx][ty + i];
        }
    } else if (b < 2048 + 272) {                // WhT[k][r]
        int bb = b - 2048;
        int bx = (bb & 15) * 32, by = (bb >> 4) * 32;
        #pragma unroll
        for (int i = 0; i < 32; i += 8) {
            int r = by + ty + i, k = bx + tx;
            float v = 0.f;
            if (r < NHP_) {
                int n = r / 129, p = r % 129;
                v = W_head[(size_t)(n * HPROW_ + p) * 512 + k];
            }
            tile[ty + i][tx] = v;
        }
        __syncthreads();
        #pragma unroll
        for (int i = 0; i < 32; i += 8) {
            int k = bx + ty + i, r = by + tx;
            if (r < NHP_) g_WhT[(size_t)k * NHP_ + r] = tile[tx][ty + i];
        }
    } else if (b < 2048 + 272 + 192) {          // WoT[k][o]
        int bb = b - 2320;
        int bx = (bb % 24) * 32, by = (bb / 24) * 32;
        #pragma unroll
        for (int i = 0; i < 32; i += 8) {
            int o = by + ty + i, k = bx + tx;
            tile[ty + i][tx] = W_out[o * (H_ + NH_*HS_) + k];
        }
        __syncthreads();
        #pragma unroll
        for (int i = 0; i < 32; i += 8) {
            int k = bx + ty + i, o = by + tx;
            g_WoT[(size_t)k * O_ + o] = tile[tx][ty + i];
        }
    } else {
        int bb = b - 2512;                      // 0..511
        int gtid = bb * 256 + tid;
        float4 z4 = make_float4(0.f, 0.f, 0.f, 0.f);
        #pragma unroll
        for (int i = 0; i < 8; ++i)
            ((float4*)g_mem)[gtid + i * 131072] = z4;
        if (gtid < 4096)                  ((float4*)g_h)[gtid] = z4;
        else if (gtid < 8192)             ((float4*)g_c)[gtid - 4096] = z4;
        else if (gtid < 8192 + NBARG)     g_bar[gtid - 8192] = 0;
        else if (gtid < 8192 + NBARG + T_*48)
            (&g_barG[0][0])[gtid - 8192 - NBARG] = 0;
    }
}

__global__ void k_nop() {}

// ---------------- the persistent recurrence kernel (256 blocks x 256 threads, 2/SM) --------
struct SmGates { u64 vp[64][18]; };      // {v(2p), v(2p+1)} pairs
struct SmP2    { float h[2][32]; };
struct SmAttn  {
    float key[8][64];
    float sc[8][260];                    // raw scores -> exp(s - gm_chunk) in place
    float gm[8], inv[8], ws[4];
    float sk[4][64];
    float racc[8][4][64];
};
union __align__(16) SmU { SmGates g; SmP2 p2; SmAttn a; };

__global__ __launch_bounds__(NTHR, 2)
void k_steps(const float* __restrict__ x, const float* __restrict__ b_ih,
             const float* __restrict__ b_hh, const float* __restrict__ b_head) {
    __shared__ SmU sm;
    const int bid = blockIdx.x, tid = threadIdx.x;
    const int wrp = tid >> 5, lane = tid & 31;

    // P1 partition: (16 n-chunks of 128) x (16 k-slices of 64)
    const int nc = bid >> 4, ksl = bid & 15;
    const int n0 = nc * 128, k0g = ksl * 64;
    const int c_l = lane & 7, bgrp = lane >> 3;      // 8 col-subs x 4 batch-groups
    const int col0 = n0 + wrp * 16 + c_l * 2;        // warp = colgrp
    // P2 partition: (16 batch-pairs) x (16 j-slices of 32)
    const int bq2 = bid >> 4, ks2 = bid & 15;
    const int b02 = bq2 * 2, j0 = ks2 * 32;
    // P3/P4 partition: batch x 8 m-chunks of 256 rows
    const int ab = bid >> 3, mq = bid & 7;
    const int m0 = mq * 256;
    const int hq = lane & 7, msub = lane >> 3;

    for (int t = 0; t < T_; ++t) {
        // ================= P1: gates GEMM (16 k-slice partials) =================
        {
            // build v pair tile vp[k][p] = {v(2p), v(2p+1)} : 64k x 16 pairs
            #pragma unroll
            for (int e = 0; e < 4; ++e) {
                int idx = e * 256 + tid;
                int kk = idx & 63, p = idx >> 6;
                int gk = k0g + kk;
                int bb = p * 2;
                float v0, v1;
                if (gk < 256) {
                    v0 = __ldg(&x[(bb * T_ + t) * I_ + gk]);
                    v1 = __ldg(&x[((bb+1) * T_ + t) * I_ + gk]);
                } else if (gk < 512) {
                    if (t == 0) { v0 = 0.f; v1 = 0.f; }
                    else {
                        int r = gk - 256;
                        v0 = 0.f; v1 = 0.f;
                        #pragma unroll
                        for (int mc = 0; mc < 8; ++mc) {
                            v0 += __ldcg(&g_read_part[t-1][mc][bb][r]);
                            v1 += __ldcg(&g_read_part[t-1][mc][bb+1][r]);
                        }
                    }
                } else {
                    v0 = __ldcg(&g_h[bb * H_ + (gk - 512)]);
                    v1 = __ldcg(&g_h[(bb+1) * H_ + (gk - 512)]);
                }
                sm.g.vp[kk][p] = pack2(v0, v1);
            }
            __syncthreads();
            u64 acc[2][4];
            {
                u64 b0p = 0ull, b1p = 0ull;
                if (ksl == 0) {
                    float bi0 = __ldg(&b_ih[col0])   + __ldg(&b_hh[col0]);
                    float bi1 = __ldg(&b_ih[col0+1]) + __ldg(&b_hh[col0+1]);
                    b0p = pack2(bi0, bi0); b1p = pack2(bi1, bi1);
                }
                #pragma unroll
                for (int p = 0; p < 4; ++p) { acc[0][p] = b0p; acc[1][p] = b1p; }
            }
            const float2* wp2 = (const float2*)&g_WgT[(size_t)k0g * NG_ + col0];
            const int p0 = bgrp * 4;
            #pragma unroll 8
            for (int kk = 0; kk < 64; ++kk) {
                float2 w = __ldg(wp2 + (size_t)kk * (NG_/2));
                u64 w20 = pack2(w.x, w.x);
                u64 w21 = pack2(w.y, w.y);
                ulonglong2 va = *(const ulonglong2*)&sm.g.vp[kk][p0];
                ulonglong2 vb = *(const ulonglong2*)&sm.g.vp[kk][p0 + 2];
                acc[0][0] = ffma2(va.x, w20, acc[0][0]);
                acc[0][1] = ffma2(va.y, w20, acc[0][1]);
                acc[0][2] = ffma2(vb.x, w20, acc[0][2]);
                acc[0][3] = ffma2(vb.y, w20, acc[0][3]);
                acc[1][0] = ffma2(va.x, w21, acc[1][0]);
                acc[1][1] = ffma2(va.y, w21, acc[1][1]);
                acc[1][2] = ffma2(vb.x, w21, acc[1][2]);
                acc[1][3] = ffma2(vb.y, w21, acc[1][3]);
            }
            #pragma unroll
            for (int p = 0; p < 4; ++p) {
                float2 c0 = unpack2(acc[0][p]);
                float2 c1 = unpack2(acc[1][p]);
                int b = bgrp * 8 + p * 2;
                *(float2*)&g_gates_part[ksl][b][col0]     = make_float2(c0.x, c1.x);
                *(float2*)&g_gates_part[ksl][b + 1][col0] = make_float2(c0.y, c1.y);
            }
            __syncthreads();
        }
        barwait(&g_bar[2*t + 0], NBLK);         // global: P1 -> P2

        // ================= P2: LSTM (quad-spread) + partial head GEMM =================
        {
            {
                const int cell = tid >> 2, q = tid & 3;     // 64 cells: 2 b x 32 j
                const int bi = cell >> 5, jj = cell & 31;
                const int b = b02 + bi, j = j0 + jj;
                float gs0 = 0.f, gs1 = 0.f, gs2 = 0.f, gs3 = 0.f;
                #pragma unroll
                for (int e = 0; e < 4; ++e) {
                    int s = q * 4 + e;
                    gs0 += __ldcg(&g_gates_part[s][b][j]);
                    gs1 += __ldcg(&g_gates_part[s][b][512 + j]);
                    gs2 += __ldcg(&g_gates_part[s][b][1024 + j]);
                    gs3 += __ldcg(&g_gates_part[s][b][1536 + j]);
                }
                gs0 += __shfl_xor_sync(0xffffffffu, gs0, 1);
                gs1 += __shfl_xor_sync(0xffffffffu, gs1, 1);
                gs2 += __shfl_xor_sync(0xffffffffu, gs2, 1);
                gs3 += __shfl_xor_sync(0xffffffffu, gs3, 1);
                gs0 += __shfl_xor_sync(0xffffffffu, gs0, 2);
                gs1 += __shfl_xor_sync(0xffffffffu, gs1, 2);
                gs2 += __shfl_xor_sync(0xffffffffu, gs2, 2);
                gs3 += __shfl_xor_sync(0xffffffffu, gs3, 2);
                if (q == 0) {
                    float cold = g_c[b * H_ + j];
                    float iv = sigm_f(gs0), fv = sigm_f(gs1);
                    float gv = tanh_f(gs2), ov = sigm_f(gs3);
                    float cn = fv * cold + iv * gv;
                    float hn = ov * tanh_f(cn);
                    g_c[b * H_ + j] = cn;
                    g_h[b * H_ + j] = hn;
                    g_hist_h[t][b][j] = hn;
                    sm.p2.h[bi][jj] = hn;
                }
            }
            __syncthreads();
            #pragma unroll
            for (int e = 0; e < 3; ++e) {
                int nn = tid + e * 256;
                if (nn < NHP_) {
                    float a0 = 0.f, a1 = 0.f;
                    #pragma unroll
                    for (int k = 0; k < 32; ++k) {
                        float w = __ldcg(&g_WhT[(size_t)(j0 + k) * NHP_ + nn]);
                        a0 += sm.p2.h[0][k] * w;
                        a1 += sm.p2.h[1][k] * w;
                    }
                    g_hp_part[ks2][b02 + 0][nn] = a0;
                    g_hp_part[ks2][b02 + 1][nn] = a1;
                }
            }
        }
        // hoist block-private mem-row loads above the barrier (coalesced)
        ulonglong2 rows2[8][2];
        #pragma unroll
        for (int it = 0; it < 8; ++it) {
            const float* mp = &g_mem[ab][m0 + it*32 + wrp*4 + msub][0];
            rows2[it][0] = *(const ulonglong2*)(mp + hq * 4);
            rows2[it][1] = *(const ulonglong2*)(mp + 32 + hq * 4);
        }
        barwait(&g_barG[t][bid >> 4], 16);      // 16-group: P2 -> P3 (hp_part local)

        // ================= P3: keys + ws + scores + sk + chunk stats =================
        {
            #pragma unroll
            for (int e = 0; e < 2; ++e) {       // key build: 512 entries, 2 per thread
                int idx = e * 256 + tid;
                int key = idx >> 6, h = idx & 63;
                int n = key & 3;
                int p = (key < 4) ? h : 64 + h;
                float v = __ldg(&b_head[n * HPROW_ + p]);
                #pragma unroll
                for (int ps = 0; ps < 16; ++ps) v += __ldcg(&g_hp_part[ps][ab][n * 129 + p]);
                sm.a.key[key][h] = v * 0.125f;
            }
            if (tid < 4) {
                int nw = tid;
                float vw = __ldg(&b_head[nw * HPROW_ + 128]);
                #pragma unroll
                for (int ps = 0; ps < 16; ++ps) vw += __ldcg(&g_hp_part[ps][ab][nw * 129 + 128]);
                sm.a.ws[nw] = sigm_f(vw);
            }
            __syncthreads();
            // scores: 2 passes of 4 keys, keys register-hoisted out of the it-loop
            #pragma unroll
            for (int kp = 0; kp < 2; ++kp) {
                const int kb = kp * 4;
                ulonglong2 klo[4], khi[4];
                #pragma unroll
                for (int kq = 0; kq < 4; ++kq) {
                    klo[kq] = *(const ulonglong2*)&sm.a.key[kb + kq][hq * 4];
                    khi[kq] = *(const ulonglong2*)&sm.a.key[kb + kq][32 + hq * 4];
                }
                #pragma unroll
                for (int it = 0; it < 8; ++it) {
                    float pv[4];
                    #pragma unroll
                    for (int kq = 0; kq < 4; ++kq) {
                        u64 d2 = ffma2(rows2[it][0].x, klo[kq].x, 0ull);
                        d2 = ffma2(rows2[it][0].y, klo[kq].y, d2);
                        d2 = ffma2(rows2[it][1].x, khi[kq].x, d2);
                        d2 = ffma2(rows2[it][1].y, khi[kq].y, d2);
                        float2 pf = unpack2(d2);
                        pv[kq] = pf.x + pf.y;
                    }
                    // butterfly over hq: xor1/xor2 key-splits, xor4 plain add
                    float q2v[2];
                    #pragma unroll
                    for (int k2 = 0; k2 < 2; ++k2) {
                        float send = (hq & 1) ? pv[2*k2] : pv[2*k2+1];
                        float recv = __shfl_xor_sync(0xffffffffu, send, 1);
                        float keepv = (hq & 1) ? pv[2*k2+1] : pv[2*k2];
                        q2v[k2] = keepv + recv;
                    }
                    float r1;
                    {
                        float send = (hq & 2) ? q2v[0] : q2v[1];
                        float recv = __shfl_xor_sync(0xffffffffu, send, 2);
                        float keepv = (hq & 2) ? q2v[1] : q2v[0];
                        r1 = keepv + recv;
                    }
                    r1 += __shfl_xor_sync(0xffffffffu, r1, 4);
                    if (hq < 4) sm.a.sc[kb + hq][it*32 + wrp*4 + msub] = r1;
                }
            }
            // sk build (needs ws + hp_part; independent of sc stats below)
            {
                int n = tid >> 6, h = tid & 63;
                float v = __ldg(&b_head[n * HPROW_ + 64 + h]);
                #pragma unroll
                for (int ps = 0; ps < 16; ++ps) v += __ldcg(&g_hp_part[ps][ab][n * 129 + 64 + h]);
                sm.a.sk[n][h] = v * sm.a.ws[n];
            }
            __syncthreads();
            if (wrp < 8) {      // chunk max per key (8 warps = 8 keys)
                float mx = -1e30f;
                for (int i = lane; i < 256; i += 32) mx = fmaxf(mx, sm.a.sc[wrp][i]);
                #pragma unroll
                for (int sh = 16; sh; sh >>= 1) mx = fmaxf(mx, __shfl_xor_sync(0xffffffffu, mx, sh));
                if (lane == 0) sm.a.gm[wrp] = mx;
            }
            __syncthreads();
            #pragma unroll
            for (int key = 0; key < 8; ++key)     // exp in place
                sm.a.sc[key][tid] = __expf(sm.a.sc[key][tid] - sm.a.gm[key]);
            __syncthreads();
            if (wrp < 8) {      // chunk sumexp
                float se = 0.f;
                for (int i = lane; i < 256; i += 32) se += sm.a.sc[wrp][i];
                #pragma unroll
                for (int sh = 16; sh; sh >>= 1) se += __shfl_xor_sync(0xffffffffu, se, sh);
                if (lane == 0) g_stats[ab][wrp][mq] = make_float2(sm.a.gm[wrp], se);
            }
        }
        barwait(&g_barG[t][16 + (bid >> 3)], 8); // 8-group: P3 -> P4 (stats local)

        // ================= P4: softmax apply on register rows, read acc, mem update ==========
        {
            if (tid < 8) {
                float gm = -1e30f;
                float2 st[8];
                #pragma unroll
                for (int c = 0; c < 8; ++c) {
                    st[c] = __ldcg(&g_stats[ab][tid][c]);
                    gm = fmaxf(gm, st[c].x);
                }
                float ssum = 0.f;
                #pragma unroll
                for (int c = 0; c < 8; ++c) ssum += st[c].y * __expf(st[c].x - gm);
                sm.a.inv[tid] = __expf(sm.a.gm[tid] - gm) / ssum;
            }
            __syncthreads();
            float scl[8];
            #pragma unroll
            for (int key = 0; key < 8; ++key) scl[key] = sm.a.inv[key];

            u64 racc2[4][4];
            #pragma unroll
            for (int n = 0; n < 4; ++n)
                #pragma unroll
                for (int q2 = 0; q2 < 4; ++q2) racc2[n][q2] = 0ull;

            #pragma unroll
            for (int it = 0; it < 8; ++it) {
                const int ml = it*32 + wrp*4 + msub;
                float wv[8];
                #pragma unroll
                for (int n = 0; n < 8; ++n) wv[n] = sm.a.sc[n][ml] * scl[n];
                ulonglong2 rlo = rows2[it][0], rhi = rows2[it][1];
                #pragma unroll
                for (int n = 0; n < 4; ++n) {
                    u64 rw2 = pack2(wv[n], wv[n]);
                    racc2[n][0] = ffma2(rw2, rlo.x, racc2[n][0]);
                    racc2[n][1] = ffma2(rw2, rlo.y, racc2[n][1]);
                    racc2[n][2] = ffma2(rw2, rhi.x, racc2[n][2]);
                    racc2[n][3] = ffma2(rw2, rhi.y, racc2[n][3]);
                }
                #pragma unroll
                for (int n = 0; n < 4; ++n) {
                    u64 ww2 = pack2(wv[4 + n], wv[4 + n]);
                    ulonglong2 slo = *(const ulonglong2*)&sm.a.sk[n][hq * 4];
                    ulonglong2 shi = *(const ulonglong2*)&sm.a.sk[n][32 + hq * 4];
                    rlo.x = ffma2(ww2, slo.x, rlo.x);
                    rlo.y = ffma2(ww2, slo.y, rlo.y);
                    rhi.x = ffma2(ww2, shi.x, rhi.x);
                    rhi.y = ffma2(ww2, shi.y, rhi.y);
                }
                float* mp = &g_mem[ab][m0 + ml][0];
                *(ulonglong2*)(mp + hq * 4) = rlo;
                *(ulonglong2*)(mp + 32 + hq * 4) = rhi;
            }
            // reduce read partials over msub (xor 8, 16)
            #pragma unroll
            for (int n = 0; n < 4; ++n)
                #pragma unroll
                for (int q2 = 0; q2 < 4; ++q2) {
                    racc2[n][q2] = fadd2(racc2[n][q2], __shfl_xor_sync(0xffffffffu, racc2[n][q2], 8));
                    racc2[n][q2] = fadd2(racc2[n][q2], __shfl_xor_sync(0xffffffffu, racc2[n][q2], 16));
                }
            if (lane < 8) {   // msub == 0, hq == lane
                #pragma unroll
                for (int n = 0; n < 4; ++n) {
                    float2 p0 = unpack2(racc2[n][0]);
                    float2 p1 = unpack2(racc2[n][1]);
                    float2 p2 = unpack2(racc2[n][2]);
                    float2 p3 = unpack2(racc2[n][3]);
                    *(float2*)&sm.a.racc[wrp][n][hq*4]          = p0;
                    *(float2*)&sm.a.racc[wrp][n][hq*4 + 2]      = p1;
                    *(float2*)&sm.a.racc[wrp][n][32 + hq*4]     = p2;
                    *(float2*)&sm.a.racc[wrp][n][32 + hq*4 + 2] = p3;
                }
            }
            __syncthreads();
            {
                int n = tid >> 6, h = tid & 63;
                float ssum = 0.f;
                #pragma unroll
                for (int wr = 0; wr < 8; ++wr) ssum += sm.a.racc[wr][n][h];
                g_read_part[t][mq][ab][n * 64 + h] = ssum;
            }
        }
        barwait(&g_bar[2*t + 1], NBLK);         // global: P4 -> next P1
    }
}

// ---------------- final output GEMM: outputs[b][t][o] ----------------
__global__ void k_out(const float* __restrict__ b_out, float* __restrict__ out) {
    const int m0 = blockIdx.x * 32, nc = blockIdx.y;
    const int tid = threadIdx.x;
    __shared__ float a_sh[32][64];
    const int n_l = tid & 63, mg = tid >> 6;
    const int n = nc * 64 + n_l;
    float acc[8];
    #pragma unroll
    for (int r = 0; r < 8; ++r) acc[r] = 0.f;
    for (int kt = 0; kt < 12; ++kt) {
        __syncthreads();
        #pragma unroll
        for (int e = 0; e < 8; ++e) {
            int lidx = e * 256 + tid;
            int mrow = lidx >> 6, kk = lidx & 63;
            int m = m0 + mrow;
            int ts = m >> 5, bb = m & 31;
            int gk = kt * 64 + kk;
            float v;
            if (gk < 512) v = g_hist_h[ts][bb][gk];
            else {
                int r = gk - 512;
                v = 0.f;
                #pragma unroll
                for (int mc = 0; mc < 8; ++mc) v += g_read_part[ts][mc][bb][r];
            }
            a_sh[mrow][kk] = v;
        }
        __syncthreads();
        #pragma unroll 4
        for (int kk = 0; kk < 64; ++kk) {
            float wv = g_WoT[(kt * 64 + kk) * O_ + n];
            #pragma unroll
            for (int r = 0; r < 8; ++r) acc[r] += a_sh[mg * 8 + r][kk] * wv;
        }
    }
    float bo = b_out[n];
    #pragma unroll
    for (int r = 0; r < 8; ++r) {
        int m = m0 + mg * 8 + r;
        int ts = m >> 5, bb = m & 31;
        out[(bb * T_ + ts) * O_ + n] = acc[r] + bo;
    }
}

// ---------------- final state copy: mem, h, c into d_out ----------------
__global__ void k_final(float* __restrict__ out) {
    const int OUT_N = B_ * T_ * O_;
    const int NMEM  = B_ * MS_ * HS_;
    const int total = NMEM + 2 * B_ * H_;
    for (int i = blockIdx.x * blockDim.x + threadIdx.x; i < total; i += gridDim.x * blockDim.x) {
        if (i < NMEM)                 out[OUT_N + i] = (&g_mem[0][0][0])[i];
        else if (i < NMEM + B_ * H_)  out[OUT_N + i] = g_h[i - NMEM];
        else                          out[OUT_N + i] = g_c[i - NMEM - B_ * H_];
    }
}

extern "C" void kernel_launch(void* const* d_in, const int* in_sizes, int n_in,
                              void* d_out, int out_size) {
    const float* x      = (const float*)d_in[0];
    const float* W_ih   = (const float*)d_in[1];
    const float* W_hh   = (const float*)d_in[2];
    const float* b_ih   = (const float*)d_in[3];
    const float* b_hh   = (const float*)d_in[4];
    const float* W_head = (const float*)d_in[5];
    const float* b_head = (const float*)d_in[6];
    const float* W_out  = (const float*)d_in[7];
    const float* b_out  = (const float*)d_in[8];
    float* out = (float*)d_out;

    k_prep<<<3024, 256>>>(W_ih, W_hh, W_head, W_out);
    k_nop<<<1, 32>>>();
    k_nop<<<1, 32>>>();
    k_steps<<<NBLK, NTHR>>>(x, b_ih, b_hh, b_head);
    k_out<<<dim3(32, 4), 256>>>(b_out, out);
    k_final<<<2048, 256>>>(out);
}